// round 7
// baseline (speedup 1.0000x reference)
#include <cuda_runtime.h>
#include <cuda_fp16.h>
#include <math.h>
#include <stdint.h>

// ---------------------------------------------------------------------------
// Problem constants
// ---------------------------------------------------------------------------
#define PB 2
#define PS 2048
#define PD 2048
#define PH 16
#define PHD 128
#define PM (PB * PS)          // 4096 rows
#define K2 (2 * PD)           // 4096: fp16 2-term split-K (Wo GEMM)
#define KB8 4096              // int8 row bytes: [a1(2048) | a2(2048)]
#define ATT_SCALE 0.08838834764831845f

// ---------------------------------------------------------------------------
// Scratch (device globals; no allocation allowed)
// ---------------------------------------------------------------------------
__device__ float g_Q[(size_t)PM * PD];
__device__ float g_K[(size_t)PM * PD];
__device__ float g_cos[PS * (PHD / 2)];
__device__ float g_sin[PS * (PHD / 2)];
__device__ int8_t g_A8[(size_t)PM * KB8];            // x int8 2-term
__device__ int8_t g_B8q[(size_t)PD * KB8];
__device__ int8_t g_B8k[(size_t)PD * KB8];
__device__ int8_t g_B8v[(size_t)PD * KB8];
__device__ float g_sax[PM];
__device__ float g_sbq[PD];
__device__ float g_sbk[PD];
__device__ float g_sbv[PD];
__device__ __half g_Bo2[(size_t)PD * K2];            // Wo fp16 [hi|hi]
__device__ __half g_AxO[(size_t)PM * K2];            // attn out fp16 [hi|lo]
__device__ __half g_Q2h[(size_t)PB * PH * PS * 256]; // [qh|ql]*scale
__device__ __half g_K2h[(size_t)PB * PH * PS * 256]; // [kh|kh]
__device__ __half g_Vh[(size_t)PB * PH * PS * PHD];

// ---------------------------------------------------------------------------
// PTX helpers
// ---------------------------------------------------------------------------
__device__ __forceinline__ uint32_t smem_u32(const void* p) {
    uint32_t a;
    asm("{ .reg .u64 t; cvta.to.shared.u64 t, %1; cvt.u32.u64 %0, t; }"
        : "=r"(a) : "l"(p));
    return a;
}

#define CP_ASYNC16(smem, gptr) \
    asm volatile("cp.async.cg.shared.global [%0], [%1], 16;" \
                 :: "r"(smem), "l"(gptr) : "memory")
#define CP_COMMIT() asm volatile("cp.async.commit_group;" ::: "memory")
#define CP_WAIT1()  asm volatile("cp.async.wait_group 1;" ::: "memory")
#define CP_WAIT2()  asm volatile("cp.async.wait_group 2;" ::: "memory")
#define CP_WAIT0()  asm volatile("cp.async.wait_group 0;" ::: "memory")

#define LDSM_X4(r0, r1, r2, r3, addr) \
    asm volatile("ldmatrix.sync.aligned.m8n8.x4.shared.b16 {%0,%1,%2,%3}, [%4];" \
                 : "=r"(r0), "=r"(r1), "=r"(r2), "=r"(r3) : "r"(addr))
#define LDSM_X4T(r0, r1, r2, r3, addr) \
    asm volatile("ldmatrix.sync.aligned.m8n8.x4.trans.shared.b16 {%0,%1,%2,%3}, [%4];" \
                 : "=r"(r0), "=r"(r1), "=r"(r2), "=r"(r3) : "r"(addr))
#define LDSM_X2(r0, r1, addr) \
    asm volatile("ldmatrix.sync.aligned.m8n8.x2.shared.b16 {%0,%1}, [%2];" \
                 : "=r"(r0), "=r"(r1) : "r"(addr))

#define MMA_16816_F16(c0, c1, c2, c3, a0, a1, a2, a3, b0, b1) \
    asm volatile("mma.sync.aligned.m16n8k16.row.col.f32.f16.f16.f32 " \
                 "{%0,%1,%2,%3}, {%4,%5,%6,%7}, {%8,%9}, {%0,%1,%2,%3};" \
                 : "+f"(c0), "+f"(c1), "+f"(c2), "+f"(c3) \
                 : "r"(a0), "r"(a1), "r"(a2), "r"(a3), "r"(b0), "r"(b1))

#define MMA_16832_S8(c0, c1, c2, c3, a0, a1, a2, a3, b0, b1) \
    asm volatile("mma.sync.aligned.m16n8k32.row.col.s32.s8.s8.s32 " \
                 "{%0,%1,%2,%3}, {%4,%5,%6,%7}, {%8,%9}, {%0,%1,%2,%3};" \
                 : "+r"(c0), "+r"(c1), "+r"(c2), "+r"(c3) \
                 : "r"(a0), "r"(a1), "r"(a2), "r"(a3), "r"(b0), "r"(b1))

// swizzles
__device__ __forceinline__ uint32_t swz64(int r, int ch) {   // 64B rows, 4x16B chunks
    return (uint32_t)(r * 64 + (((ch) ^ ((r >> 1) & 3)) << 4));
}
__device__ __forceinline__ uint32_t swzV(int r, int ch) {    // 256B rows, 16x16B chunks
    return (uint32_t)(r * 256 + (((ch) ^ (r & 7)) << 4));
}

// ---------------------------------------------------------------------------
// Row-wise 2-term int8 quantization: X[row][0..2048) fp32 ->
//   Y[row][0..2048) = a1 = rn(x/s), Y[row][2048..4096) = a2 = rn((x/s-a1)*128)
//   S[row] = s = maxabs/127
// ---------------------------------------------------------------------------
__global__ __launch_bounds__(256)
void quant8(const float* __restrict__ X, int8_t* __restrict__ Y,
            float* __restrict__ S)
{
    const int row = blockIdx.x;
    const int tid = threadIdx.x;
    const float* src = X + (size_t)row * PD;
    float v[8];
    *(float4*)&v[0] = *(const float4*)(src + tid * 8);
    *(float4*)&v[4] = *(const float4*)(src + tid * 8 + 4);
    float mx = 0.0f;
#pragma unroll
    for (int i = 0; i < 8; ++i) mx = fmaxf(mx, fabsf(v[i]));
#pragma unroll
    for (int off = 16; off >= 1; off >>= 1)
        mx = fmaxf(mx, __shfl_xor_sync(0xffffffffu, mx, off));
    __shared__ float wmax[8];
    if ((tid & 31) == 0) wmax[tid >> 5] = mx;
    __syncthreads();
    float m2 = wmax[0];
#pragma unroll
    for (int i = 1; i < 8; ++i) m2 = fmaxf(m2, wmax[i]);
    m2 = fmaxf(m2, 1e-30f);
    const float inv = 127.0f / m2;
    signed char q1[8], q2[8];
#pragma unroll
    for (int i = 0; i < 8; ++i) {
        float t  = v[i] * inv;
        float r1 = rintf(t);
        q1[i] = (signed char)(int)r1;
        q2[i] = (signed char)(int)rintf((t - r1) * 128.0f);
    }
    *(uint2*)(Y + (size_t)row * KB8 + tid * 8)        = *(uint2*)q1;
    *(uint2*)(Y + (size_t)row * KB8 + 2048 + tid * 8) = *(uint2*)q2;
    if (tid == 0) S[row] = m2 / 127.0f;
}

// ---------------------------------------------------------------------------
// Split fp32 -> 2-segment fp16 (Wo weights): [hi|hi]
// ---------------------------------------------------------------------------
__global__ void split2(const float* __restrict__ X, __half* __restrict__ Y,
                       int npairs)
{
    int i = blockIdx.x * blockDim.x + threadIdx.x;
    if (i >= npairs) return;
    int r = i >> 10;
    int c = (i & 1023) << 1;
    float2 v = *(const float2*)(X + (size_t)r * PD + c);
    __half2 hh = __halves2half2(__float2half(v.x), __float2half(v.y));
    __half2* base = (__half2*)(Y + (size_t)r * K2 + c);
    base[0]    = hh;
    base[1024] = hh;
}

// ---------------------------------------------------------------------------
// int8 2-term GEMM: C[m][n] = Sa[m]*Sb[n]*(a1.b1 + (a1.b2 + a2.b1)/128)
// 128x128 tile, 96 k-tiles of 64 B, 3-stage cp.async, fold G1 to smem at
// the phase boundary. MODE 0: fp32 C; MODE 1: V head-gather fp16.
// ---------------------------------------------------------------------------
#define GI_STG 3
#define GI_STAGE 16384
#define GI_FOLD (GI_STG * GI_STAGE)     // 49152
#define GI_SMEM (GI_FOLD + 65536)       // 114688
#define GI_KT 96

__device__ __forceinline__ int gi_aoff(int t) {
    int i = t & 31, ph = t >> 5;
    return ((ph == 2) ? 2048 : 0) + i * 64;
}
__device__ __forceinline__ int gi_boff(int t) {
    int i = t & 31, ph = t >> 5;
    return ((ph == 1) ? 2048 : 0) + i * 64;
}

template<int MODE>
__global__ __launch_bounds__(256, 2)
void gemm_i8(const int8_t* __restrict__ A8, const int8_t* __restrict__ B8,
             const float* __restrict__ Sa, const float* __restrict__ Sb,
             float* __restrict__ C, __half* __restrict__ Vho)
{
    extern __shared__ __align__(1024) char smem[];
    const uint32_t sbase = smem_u32(smem);

    const int tid  = threadIdx.x;
    const int lane = tid & 31;
    const int wid  = tid >> 5;
    const int wm   = wid & 1;
    const int wn   = wid >> 1;
    const int bm   = blockIdx.y * 128;
    const int bn   = blockIdx.x * 128;

    const int8_t* Ag = A8 + (size_t)bm * KB8;
    const int8_t* Bg = B8 + (size_t)bn * KB8;

    uint32_t lsw[2];
    const int8_t* gA[2];
    const int8_t* gB[2];
#pragma unroll
    for (int p = 0; p < 2; ++p) {
        int idx = tid + p * 256;
        int r = idx >> 2, ch = idx & 3;
        lsw[p] = swz64(r, ch);
        gA[p] = Ag + (size_t)r * KB8 + ch * 16;
        gB[p] = Bg + (size_t)r * KB8 + ch * 16;
    }

    uint32_t a_row_off[4];
    int a_swz[4];
#pragma unroll
    for (int mi = 0; mi < 4; ++mi) {
        int r = wm * 64 + mi * 16 + (lane & 15);
        a_row_off[mi] = (uint32_t)(r * 64);
        a_swz[mi] = (r >> 1) & 3;
    }
    const int a_cpart = lane >> 4;
    uint32_t b_row_off[4];
    int b_swz[4];
#pragma unroll
    for (int nj = 0; nj < 4; ++nj) {
        int r = wn * 32 + nj * 8 + (lane & 7);
        b_row_off[nj] = (uint32_t)(r * 64);
        b_swz[nj] = (r >> 1) & 3;
    }
    const int b_cpart = (lane >> 3) & 1;

    int acc[4][4][4];
#pragma unroll
    for (int mi = 0; mi < 4; ++mi)
#pragma unroll
        for (int nj = 0; nj < 4; ++nj)
#pragma unroll
            for (int e = 0; e < 4; ++e) acc[mi][nj][e] = 0;

    // prologue: stages 0,1
#pragma unroll
    for (int s = 0; s < 2; ++s) {
        uint32_t sA = sbase + s * GI_STAGE;
        uint32_t sB = sA + 8192;
        int ao = gi_aoff(s), bo = gi_boff(s);
#pragma unroll
        for (int p = 0; p < 2; ++p) {
            CP_ASYNC16(sA + lsw[p], gA[p] + ao);
            CP_ASYNC16(sB + lsw[p], gB[p] + bo);
        }
        CP_COMMIT();
    }

    int st = 0, nst = 2;
    for (int kt = 0; kt < GI_KT; ++kt) {
        CP_WAIT1();
        __syncthreads();

        int nk = kt + 2;
        if (nk < GI_KT) {
            uint32_t sA = sbase + nst * GI_STAGE;
            uint32_t sB = sA + 8192;
            int ao = gi_aoff(nk), bo = gi_boff(nk);
#pragma unroll
            for (int p = 0; p < 2; ++p) {
                CP_ASYNC16(sA + lsw[p], gA[p] + ao);
                CP_ASYNC16(sB + lsw[p], gB[p] + bo);
            }
        }
        CP_COMMIT();

        uint32_t sA = sbase + st * GI_STAGE;
        uint32_t sB = sA + 8192;
#pragma unroll
        for (int h = 0; h < 2; ++h) {
            uint32_t a0[4], a1[4], a2[4], a3[4];
#pragma unroll
            for (int mi = 0; mi < 4; ++mi) {
                uint32_t addr = sA + a_row_off[mi]
                              + (uint32_t)(((2 * h + a_cpart) ^ a_swz[mi]) << 4);
                LDSM_X4(a0[mi], a1[mi], a2[mi], a3[mi], addr);
            }
            uint32_t b0[4], b1[4];
#pragma unroll
            for (int nj = 0; nj < 4; ++nj) {
                uint32_t addr = sB + b_row_off[nj]
                              + (uint32_t)(((2 * h + b_cpart) ^ b_swz[nj]) << 4);
                LDSM_X2(b0[nj], b1[nj], addr);
            }
#pragma unroll
            for (int mi = 0; mi < 4; ++mi)
#pragma unroll
                for (int nj = 0; nj < 4; ++nj)
                    MMA_16832_S8(acc[mi][nj][0], acc[mi][nj][1],
                                 acc[mi][nj][2], acc[mi][nj][3],
                                 a0[mi], a1[mi], a2[mi], a3[mi],
                                 b0[nj], b1[nj]);
        }
        __syncthreads();

        // phase-1 boundary: stash G1 in smem fold buffer, reset accumulators
        if (kt == 31) {
            int4* fb = (int4*)(smem + GI_FOLD) + tid * 16;
#pragma unroll
            for (int mi = 0; mi < 4; ++mi)
#pragma unroll
                for (int nj = 0; nj < 4; ++nj) {
                    fb[mi * 4 + nj] = make_int4(acc[mi][nj][0], acc[mi][nj][1],
                                                acc[mi][nj][2], acc[mi][nj][3]);
                    acc[mi][nj][0] = 0; acc[mi][nj][1] = 0;
                    acc[mi][nj][2] = 0; acc[mi][nj][3] = 0;
                }
        }

        st  = (st == 2)  ? 0 : st + 1;
        nst = (nst == 2) ? 0 : nst + 1;
    }

    // epilogue: dequant C = Sa*Sb*(G1 + G23/128)
    const int erow = (lane >> 2);
    const int ecol = (lane & 3) * 2;
    const int4* fb = (const int4*)(smem + GI_FOLD) + tid * 16;
    float sar[4][2], sbc[4][2];
#pragma unroll
    for (int mi = 0; mi < 4; ++mi) {
        int row = bm + wm * 64 + mi * 16 + erow;
        sar[mi][0] = Sa[row];
        sar[mi][1] = Sa[row + 8];
    }
#pragma unroll
    for (int nj = 0; nj < 4; ++nj) {
        int col = bn + wn * 32 + nj * 8 + ecol;
        sbc[nj][0] = Sb[col];
        sbc[nj][1] = Sb[col + 1];
    }
#pragma unroll
    for (int mi = 0; mi < 4; ++mi) {
#pragma unroll
        for (int nj = 0; nj < 4; ++nj) {
            int4 g1 = fb[mi * 4 + nj];
            const float w = 0.0078125f;   // 1/128
            float c0 = sar[mi][0] * sbc[nj][0] * ((float)g1.x + (float)acc[mi][nj][0] * w);
            float c1 = sar[mi][0] * sbc[nj][1] * ((float)g1.y + (float)acc[mi][nj][1] * w);
            float c2 = sar[mi][1] * sbc[nj][0] * ((float)g1.z + (float)acc[mi][nj][2] * w);
            float c3 = sar[mi][1] * sbc[nj][1] * ((float)g1.w + (float)acc[mi][nj][3] * w);
            int row = bm + wm * 64 + mi * 16 + erow;
            int col = bn + wn * 32 + nj * 8 + ecol;
            if (MODE == 0) {
                *(float2*)(C + (size_t)row * PD + col)       = make_float2(c0, c1);
                *(float2*)(C + (size_t)(row + 8) * PD + col) = make_float2(c2, c3);
            } else {
                int b = row >> 11, s = row & 2047;
                int h = col >> 7, hd = col & 127;
                size_t dst = ((size_t)(b * PH + h) * PS + s) * PHD + hd;
                *(__half2*)(Vho + dst)           = __float22half2_rn(make_float2(c0, c1));
                *(__half2*)(Vho + dst + 8 * PHD) = __float22half2_rn(make_float2(c2, c3));
            }
        }
    }
}

// ---------------------------------------------------------------------------
// fp16 2-term HMMA GEMM (round-6 body), Wo projection only. K = 4096.
// ---------------------------------------------------------------------------
#define HG_BK 32
#define HG_STG 4
#define HG_STAGE_BYTES 16384
#define HG_SMEM (HG_STG * HG_STAGE_BYTES)
#define HG_KT (K2 / HG_BK)     // 128

__global__ __launch_bounds__(256, 2)
void gemm_f16(const __half* __restrict__ A3, const __half* __restrict__ B3,
              float* __restrict__ C)
{
    extern __shared__ __align__(1024) char smem[];
    const uint32_t sbase = smem_u32(smem);

    const int tid  = threadIdx.x;
    const int lane = tid & 31;
    const int wid  = tid >> 5;
    const int wm   = wid & 1;
    const int wn   = wid >> 1;
    const int bm   = blockIdx.y * 128;
    const int bn   = blockIdx.x * 128;

    const __half* Ag = A3 + (size_t)bm * K2;
    const __half* Bg = B3 + (size_t)bn * K2;

    uint32_t lsw[2];
    const __half* gA[2];
    const __half* gB[2];
#pragma unroll
    for (int p = 0; p < 2; ++p) {
        int idx = tid + p * 256;
        int r = idx >> 2, ch = idx & 3;
        lsw[p] = swz64(r, ch);
        gA[p] = Ag + (size_t)r * K2 + ch * 8;
        gB[p] = Bg + (size_t)r * K2 + ch * 8;
    }

    uint32_t a_row_off[4];
    int a_swz[4];
#pragma unroll
    for (int mi = 0; mi < 4; ++mi) {
        int r = wm * 64 + mi * 16 + (lane & 15);
        a_row_off[mi] = (uint32_t)(r * 64);
        a_swz[mi] = (r >> 1) & 3;
    }
    const int a_cpart = lane >> 4;
    uint32_t b_row_off[4];
    int b_swz[4];
#pragma unroll
    for (int nj = 0; nj < 4; ++nj) {
        int r = wn * 32 + nj * 8 + (lane & 7);
        b_row_off[nj] = (uint32_t)(r * 64);
        b_swz[nj] = (r >> 1) & 3;
    }
    const int b_cpart = (lane >> 3) & 1;

    float acc[4][4][4];
#pragma unroll
    for (int mi = 0; mi < 4; ++mi)
#pragma unroll
        for (int nj = 0; nj < 4; ++nj)
#pragma unroll
            for (int e = 0; e < 4; ++e) acc[mi][nj][e] = 0.0f;

#pragma unroll
    for (int s = 0; s < HG_STG - 1; ++s) {
        uint32_t sA = sbase + s * HG_STAGE_BYTES;
        uint32_t sB = sA + 8192;
        int k0 = s * HG_BK;
#pragma unroll
        for (int p = 0; p < 2; ++p) {
            CP_ASYNC16(sA + lsw[p], gA[p] + k0);
            CP_ASYNC16(sB + lsw[p], gB[p] + k0);
        }
        CP_COMMIT();
    }

    for (int kt = 0; kt < HG_KT; ++kt) {
        CP_WAIT2();
        __syncthreads();

        int nk = kt + HG_STG - 1;
        if (nk < HG_KT) {
            uint32_t sA = sbase + (nk & 3) * HG_STAGE_BYTES;
            uint32_t sB = sA + 8192;
            int k0 = nk * HG_BK;
#pragma unroll
            for (int p = 0; p < 2; ++p) {
                CP_ASYNC16(sA + lsw[p], gA[p] + k0);
                CP_ASYNC16(sB + lsw[p], gB[p] + k0);
            }
        }
        CP_COMMIT();

        uint32_t sA = sbase + (kt & 3) * HG_STAGE_BYTES;
        uint32_t sB = sA + 8192;
#pragma unroll
        for (int h = 0; h < 2; ++h) {
            uint32_t a0[4], a1[4], a2[4], a3[4];
#pragma unroll
            for (int mi = 0; mi < 4; ++mi) {
                uint32_t addr = sA + a_row_off[mi]
                              + (uint32_t)(((2 * h + a_cpart) ^ a_swz[mi]) << 4);
                LDSM_X4(a0[mi], a1[mi], a2[mi], a3[mi], addr);
            }
            uint32_t b0[4], b1[4];
#pragma unroll
            for (int nj = 0; nj < 4; ++nj) {
                uint32_t addr = sB + b_row_off[nj]
                              + (uint32_t)(((2 * h + b_cpart) ^ b_swz[nj]) << 4);
                LDSM_X2(b0[nj], b1[nj], addr);
            }
#pragma unroll
            for (int mi = 0; mi < 4; ++mi)
#pragma unroll
                for (int nj = 0; nj < 4; ++nj)
                    MMA_16816_F16(acc[mi][nj][0], acc[mi][nj][1],
                                  acc[mi][nj][2], acc[mi][nj][3],
                                  a0[mi], a1[mi], a2[mi], a3[mi],
                                  b0[nj], b1[nj]);
        }
        __syncthreads();
    }

    const int erow = (lane >> 2);
    const int ecol = (lane & 3) * 2;
#pragma unroll
    for (int mi = 0; mi < 4; ++mi) {
#pragma unroll
        for (int nj = 0; nj < 4; ++nj) {
            int row = bm + wm * 64 + mi * 16 + erow;
            int col = bn + wn * 32 + nj * 8 + ecol;
            *(float2*)(C + (size_t)row * PD + col) =
                make_float2(acc[mi][nj][0], acc[mi][nj][1]);
            *(float2*)(C + (size_t)(row + 8) * PD + col) =
                make_float2(acc[mi][nj][2], acc[mi][nj][3]);
        }
    }
}

// ---------------------------------------------------------------------------
// RoPE tables (fp64 trig on fp32-rounded angle chain)
// ---------------------------------------------------------------------------
__global__ void rope_tables(float* __restrict__ ct, float* __restrict__ st)
{
    int idx = blockIdx.x * blockDim.x + threadIdx.x;
    if (idx >= PS * (PHD / 2)) return;
    int s = idx >> 6;
    int j = idx & 63;
    float invf = (float)pow(10000.0, -(double)j / 64.0);
    float ang  = (float)s * invf;
    double a   = (double)ang;
    double cs, sn;
    sincos(a, &sn, &cs);
    ct[idx] = (float)cs;
    st[idx] = (float)sn;
}

// ---------------------------------------------------------------------------
// RoPE + scale + fp16 split: Q -> [qh|ql]*scale, K -> [kh|kh]; [b,h,s,256].
// ---------------------------------------------------------------------------
__global__ __launch_bounds__(256)
void rope_split(const float* __restrict__ Q, const float* __restrict__ Kf,
                const float* __restrict__ ct, const float* __restrict__ st,
                __half* __restrict__ Q2, __half* __restrict__ K2g)
{
    const int row = blockIdx.x;
    const int b   = row >> 11;
    const int s   = row & (PS - 1);
    const int tid = threadIdx.x;
    __shared__ float buf[PD];

#pragma unroll
    for (int pass = 0; pass < 2; ++pass) {
        const float* src = (pass == 0 ? Q : Kf) + (size_t)row * PD;
        __half* dstbase = pass == 0 ? Q2 : K2g;
        for (int i = tid; i < PD; i += 256) buf[i] = src[i];
        __syncthreads();
        for (int i = tid; i < PD; i += 256) {
            int d = i & (PHD - 1);
            int h = i >> 7;
            int j = d & 63;
            float c  = ct[s * 64 + j];
            float sn = st[s * 64 + j];
            float x  = buf[i];
            float xr = (d < 64) ? -buf[i + 64] : buf[i - 64];
            float val = fmaf(x, c, xr * sn);
            if (pass == 0) val *= ATT_SCALE;
            __half hi = __float2half(val);
            __half* out = dstbase + ((size_t)(b * PH + h) * PS + s) * 256 + d;
            out[0] = hi;
            out[128] = (pass == 0) ? __float2half(val - __half2float(hi)) : hi;
        }
        __syncthreads();
    }
}

// ---------------------------------------------------------------------------
// Tensor-core causal flash attention (fp16): QK 2-term (K'=256),
// PV single term (p_hi x v_hi). Output -> fp16 [hi|lo] for Wo GEMM.
// ---------------------------------------------------------------------------
#define ATS_Q  0          // 8 panels x 8192 = 65536
#define ATS_K  65536      // 8 panels x 4096 = 32768
#define ATS_VH 98304      // 16384
#define ATS_P  114688     // 2 panels x 8192 = 16384
#define ATT_SMEM 131072

__global__ __launch_bounds__(256, 1)
void attn_tc(const __half* __restrict__ Q2,
             const __half* __restrict__ K2g,
             const __half* __restrict__ Vh,
             __half* __restrict__ AXO)
{
    extern __shared__ __align__(1024) char sm[];
    const uint32_t sb = smem_u32(sm);
    const int tid  = threadIdx.x;
    const int lane = tid & 31;
    const int w    = tid >> 5;
    const int qt   = 15 - (int)blockIdx.x;
    const int bh   = blockIdx.y;
    const int qb   = qt * 128;
    const int nkt  = 2 * qt + 2;

    const __half* q2 = Q2 + ((size_t)bh * PS + qb) * 256;
    const __half* k2 = K2g + (size_t)bh * PS * 256;
    const __half* vh = Vh + (size_t)bh * PS * PHD;

#pragma unroll
    for (int p = 0; p < 8; ++p)
#pragma unroll
        for (int ps = 0; ps < 2; ++ps) {
            int idx = tid + ps * 256;
            int r = idx >> 2, ch = idx & 3;
            CP_ASYNC16(sb + ATS_Q + p * 8192 + swz64(r, ch),
                       q2 + (size_t)r * 256 + p * 32 + ch * 8);
        }
    {
        int r = tid >> 2, ch = tid & 3;
#pragma unroll
        for (int p = 0; p < 8; ++p)
            CP_ASYNC16(sb + ATS_K + p * 4096 + swz64(r, ch),
                       k2 + (size_t)r * 256 + p * 32 + ch * 8);
#pragma unroll
        for (int ps = 0; ps < 4; ++ps) {
            int idx = tid + ps * 256;
            int rr = idx >> 4, cc = idx & 15;
            CP_ASYNC16(sb + ATS_VH + swzV(rr, cc), vh + (size_t)rr * PHD + cc * 8);
        }
    }
    CP_COMMIT();

    float m0 = -INFINITY, m1 = -INFINITY, l0 = 0.0f, l1 = 0.0f;
    float oa[16][4];
#pragma unroll
    for (int j = 0; j < 16; ++j)
#pragma unroll
        for (int e = 0; e < 4; ++e) oa[j][e] = 0.0f;

    const int arow  = w * 16 + (lane & 15);
    const int aswz  = (arow >> 1) & 3;
    const int acp   = lane >> 4;
    const int rr0   = w * 16 + (lane >> 2);
    const int prow0 = rr0;
    const int prow1 = rr0 + 8;
    const int pswz0 = (prow0 >> 1) & 3;
    const int pswz1 = (prow1 >> 1) & 3;
    const int vkrow_base = (lane & 7) + 8 * ((lane >> 3) & 1);

    for (int kt = 0; kt < nkt; ++kt) {
        CP_WAIT0();
        __syncthreads();

        float sa[8][4];
#pragma unroll
        for (int j = 0; j < 8; ++j)
#pragma unroll
            for (int e = 0; e < 4; ++e) sa[j][e] = 0.0f;

#pragma unroll
        for (int p = 0; p < 8; ++p) {
#pragma unroll
            for (int h = 0; h < 2; ++h) {
                uint32_t a0, a1, a2, a3;
                LDSM_X4(a0, a1, a2, a3,
                        sb + ATS_Q + p * 8192 + arow * 64
                           + (((2 * h + acp) ^ aswz) << 4));
#pragma unroll
                for (int jj = 0; jj < 4; ++jj) {
                    int brow = jj * 16 + (lane & 15);
                    uint32_t b0, b1, b2, b3;
                    LDSM_X4(b0, b1, b2, b3,
                            sb + ATS_K + p * 4096 + brow * 64
                               + (((2 * h + acp) ^ ((brow >> 1) & 3)) << 4));
                    MMA_16816_F16(sa[2 * jj][0], sa[2 * jj][1],
                                  sa[2 * jj][2], sa[2 * jj][3],
                                  a0, a1, a2, a3, b0, b2);
                    MMA_16816_F16(sa[2 * jj + 1][0], sa[2 * jj + 1][1],
                                  sa[2 * jj + 1][2], sa[2 * jj + 1][3],
                                  a0, a1, a2, a3, b1, b3);
                }
            }
        }
        __syncthreads();

        if (kt + 1 < nkt) {
            const __half* kp = k2 + (size_t)(kt + 1) * 64 * 256;
            int r = tid >> 2, ch = tid & 3;
#pragma unroll
            for (int p = 0; p < 8; ++p)
                CP_ASYNC16(sb + ATS_K + p * 4096 + swz64(r, ch),
                           kp + (size_t)r * 256 + p * 32 + ch * 8);
        }
        CP_COMMIT();

        const int kb = kt * 64;
        if (kt >= 2 * qt) {
            const int rg0 = qb + rr0;
            const int rg1 = rg0 + 8;
#pragma unroll
            for (int j = 0; j < 8; ++j) {
                int c0 = kb + j * 8 + 2 * (lane & 3);
                if (c0 > rg0)     sa[j][0] = -INFINITY;
                if (c0 + 1 > rg0) sa[j][1] = -INFINITY;
                if (c0 > rg1)     sa[j][2] = -INFINITY;
                if (c0 + 1 > rg1) sa[j][3] = -INFINITY;
            }
        }
        float rmax0 = -INFINITY, rmax1 = -INFINITY;
#pragma unroll
        for (int j = 0; j < 8; ++j) {
            rmax0 = fmaxf(rmax0, fmaxf(sa[j][0], sa[j][1]));
            rmax1 = fmaxf(rmax1, fmaxf(sa[j][2], sa[j][3]));
        }
        rmax0 = fmaxf(rmax0, __shfl_xor_sync(0xffffffffu, rmax0, 1));
        rmax0 = fmaxf(rmax0, __shfl_xor_sync(0xffffffffu, rmax0, 2));
        rmax1 = fmaxf(rmax1, __shfl_xor_sync(0xffffffffu, rmax1, 1));
        rmax1 = fmaxf(rmax1, __shfl_xor_sync(0xffffffffu, rmax1, 2));

        float mn0 = fmaxf(m0, rmax0);
        float mn1 = fmaxf(m1, rmax1);
        float corr0 = __expf(m0 - mn0);
        float corr1 = __expf(m1 - mn1);
        m0 = mn0; m1 = mn1;
#pragma unroll
        for (int j = 0; j < 16; ++j) {
            oa[j][0] *= corr0; oa[j][1] *= corr0;
            oa[j][2] *= corr1; oa[j][3] *= corr1;
        }
        float rs0 = 0.0f, rs1 = 0.0f;
#pragma unroll
        for (int j = 0; j < 8; ++j) {
            float p0 = __expf(sa[j][0] - mn0);
            float p1 = __expf(sa[j][1] - mn0);
            float p2 = __expf(sa[j][2] - mn1);
            float p3 = __expf(sa[j][3] - mn1);
            rs0 += p0 + p1;
            rs1 += p2 + p3;
            int key = j * 8 + 2 * (lane & 3);
            int panel = key >> 5, kin = key & 31;
            uint32_t inoff = (uint32_t)(((kin >> 3)) << 4) + ((kin & 7) << 1);
            __half2 h2a = __float22half2_rn(make_float2(p0, p1));
            __half2 h2b = __float22half2_rn(make_float2(p2, p3));
            uint32_t ba0 = (uint32_t)(ATS_P + panel * 8192) + prow0 * 64
                         + ((inoff & 0xF0u) ^ (pswz0 << 4)) + (inoff & 0xFu);
            uint32_t ba1 = (uint32_t)(ATS_P + panel * 8192) + prow1 * 64
                         + ((inoff & 0xF0u) ^ (pswz1 << 4)) + (inoff & 0xFu);
            *(__half2*)(sm + ba0) = h2a;
            *(__half2*)(sm + ba1) = h2b;
        }
        rs0 += __shfl_xor_sync(0xffffffffu, rs0, 1);
        rs0 += __shfl_xor_sync(0xffffffffu, rs0, 2);
        rs1 += __shfl_xor_sync(0xffffffffu, rs1, 1);
        rs1 += __shfl_xor_sync(0xffffffffu, rs1, 2);
        l0 = l0 * corr0 + rs0;
        l1 = l1 * corr1 + rs1;
        __syncwarp();

        // PV: O += p_hi x v_hi
#pragma unroll
        for (int s = 0; s < 4; ++s) {
            uint32_t a0, a1, a2, a3;
            LDSM_X4(a0, a1, a2, a3,
                    sb + ATS_P + (s >> 1) * 8192 + arow * 64
                       + (((2 * (s & 1) + acp) ^ aswz) << 4));
            int vk = s * 16 + vkrow_base;
#pragma unroll
            for (int g = 0; g < 8; ++g) {
                uint32_t b0, b1, b2, b3;
                LDSM_X4T(b0, b1, b2, b3,
                         sb + ATS_VH + vk * 256
                            + ((((2 * g + (lane >> 4)) ^ (vk & 7))) << 4));
                MMA_16816_F16(oa[2 * g][0], oa[2 * g][1],
                              oa[2 * g][2], oa[2 * g][3],
                              a0, a1, a2, a3, b0, b1);
                MMA_16816_F16(oa[2 * g + 1][0], oa[2 * g + 1][1],
                              oa[2 * g + 1][2], oa[2 * g + 1][3],
                              a0, a1, a2, a3, b2, b3);
            }
        }
        __syncthreads();

        if (kt + 1 < nkt) {
            const __half* va = vh + (size_t)(kt + 1) * 64 * PHD;
#pragma unroll
            for (int ps = 0; ps < 4; ++ps) {
                int idx = tid + ps * 256;
                int rr = idx >> 4, cc = idx & 15;
                CP_ASYNC16(sb + ATS_VH + swzV(rr, cc), va + (size_t)rr * PHD + cc * 8);
            }
        }
        CP_COMMIT();
    }

    const float inv0 = 1.0f / l0;
    const float inv1 = 1.0f / l1;
    const int b = bh >> 4, h = bh & 15;
    const size_t row0 = (size_t)b * PS + qb + rr0;
    const size_t row1 = row0 + 8;
#pragma unroll
    for (int j = 0; j < 16; ++j) {
        int col = h * PHD + j * 8 + 2 * (lane & 3);
        float2 p0 = make_float2(oa[j][0] * inv0, oa[j][1] * inv0);
        float2 p1 = make_float2(oa[j][2] * inv1, oa[j][3] * inv1);
        __half2 h20 = __float22half2_rn(p0);
        __half2 h21 = __float22half2_rn(p1);
        __half2 l20 = __float22half2_rn(make_float2(
            p0.x - __half2float(__low2half(h20)),
            p0.y - __half2float(__high2half(h20))));
        __half2 l21 = __float22half2_rn(make_float2(
            p1.x - __half2float(__low2half(h21)),
            p1.y - __half2float(__high2half(h21))));
        __half* d0 = AXO + row0 * K2 + col;
        __half* d1 = AXO + row1 * K2 + col;
        *(__half2*)(d0)        = h20;
        *(__half2*)(d0 + 2048) = l20;
        *(__half2*)(d1)        = h21;
        *(__half2*)(d1 + 2048) = l21;
    }
}

// ---------------------------------------------------------------------------
// kernel_launch
// ---------------------------------------------------------------------------
extern "C" void kernel_launch(void* const* d_in, const int* in_sizes, int n_in,
                              void* d_out, int out_size)
{
    const float* x  = (const float*)d_in[0];
    const float* Wq = (const float*)d_in[1];
    const float* Wk = (const float*)d_in[2];
    const float* Wv = (const float*)d_in[3];
    const float* Wo = (const float*)d_in[4];
    float* out = (float*)d_out;

    float *Qp, *Kp, *cp, *sp, *saxp, *sbqp, *sbkp, *sbvp;
    int8_t *A8p, *B8qp, *B8kp, *B8vp;
    __half *Bo2p, *AxOp, *Q2p, *K2p, *Vhp;
    cudaGetSymbolAddress((void**)&Qp,   g_Q);
    cudaGetSymbolAddress((void**)&Kp,   g_K);
    cudaGetSymbolAddress((void**)&cp,   g_cos);
    cudaGetSymbolAddress((void**)&sp,   g_sin);
    cudaGetSymbolAddress((void**)&A8p,  g_A8);
    cudaGetSymbolAddress((void**)&B8qp, g_B8q);
    cudaGetSymbolAddress((void**)&B8kp, g_B8k);
    cudaGetSymbolAddress((void**)&B8vp, g_B8v);
    cudaGetSymbolAddress((void**)&saxp, g_sax);
    cudaGetSymbolAddress((void**)&sbqp, g_sbq);
    cudaGetSymbolAddress((void**)&sbkp, g_sbk);
    cudaGetSymbolAddress((void**)&sbvp, g_sbv);
    cudaGetSymbolAddress((void**)&Bo2p, g_Bo2);
    cudaGetSymbolAddress((void**)&AxOp, g_AxO);
    cudaGetSymbolAddress((void**)&Q2p,  g_Q2h);
    cudaGetSymbolAddress((void**)&K2p,  g_K2h);
    cudaGetSymbolAddress((void**)&Vhp,  g_Vh);

    cudaFuncSetAttribute((const void*)gemm_i8<0>,
                         cudaFuncAttributeMaxDynamicSharedMemorySize, GI_SMEM);
    cudaFuncSetAttribute((const void*)gemm_i8<1>,
                         cudaFuncAttributeMaxDynamicSharedMemorySize, GI_SMEM);
    cudaFuncSetAttribute((const void*)gemm_f16,
                         cudaFuncAttributeMaxDynamicSharedMemorySize, HG_SMEM);
    cudaFuncSetAttribute((const void*)attn_tc,
                         cudaFuncAttributeMaxDynamicSharedMemorySize, ATT_SMEM);

    const int wpairs = PD * PD / 2;

    // int8 quantization (x + QKV weights) and fp16 split (Wo)
    quant8<<<PM, 256>>>(x,  A8p,  saxp);
    quant8<<<PD, 256>>>(Wq, B8qp, sbqp);
    quant8<<<PD, 256>>>(Wk, B8kp, sbkp);
    quant8<<<PD, 256>>>(Wv, B8vp, sbvp);
    split2<<<(wpairs + 255) / 256, 256>>>(Wo, Bo2p, wpairs);

    dim3 ggrid(PD / 128, PM / 128);   // (16, 32)

    // QKV projections: int8 2-term tensor-core GEMMs
    gemm_i8<0><<<ggrid, 256, GI_SMEM>>>(A8p, B8qp, saxp, sbqp, Qp, nullptr);
    gemm_i8<0><<<ggrid, 256, GI_SMEM>>>(A8p, B8kp, saxp, sbkp, Kp, nullptr);
    gemm_i8<1><<<ggrid, 256, GI_SMEM>>>(A8p, B8vp, saxp, sbvp, nullptr, Vhp);

    rope_tables<<<(PS * 64 + 255) / 256, 256>>>(cp, sp);
    rope_split<<<PM, 256>>>(Qp, Kp, cp, sp, Q2p, K2p);

    attn_tc<<<dim3(PS / 128, PB * PH), 256, ATT_SMEM>>>(Q2p, K2p, Vhp, AxOp);

    // Wo projection: fp16 2-term
    gemm_f16<<<ggrid, 256, HG_SMEM>>>(AxOp, Bo2p, out);
}

// round 8
// speedup vs baseline: 1.0132x; 1.0132x over previous
#include <cuda_runtime.h>
#include <cuda_fp16.h>
#include <math.h>
#include <stdint.h>

// ---------------------------------------------------------------------------
// Problem constants
// ---------------------------------------------------------------------------
#define PB 2
#define PS 2048
#define PD 2048
#define PH 16
#define PHD 128
#define PM (PB * PS)          // 4096 rows
#define K2 (2 * PD)           // 4096: fp16 2-term split-K (Wo GEMM)
#define KB8 4096              // int8 row bytes: [a1(2048) | a2(2048)]
#define ATT_SCALE 0.08838834764831845f

// ---------------------------------------------------------------------------
// Scratch (device globals; no allocation allowed)
// ---------------------------------------------------------------------------
__device__ float g_Q[(size_t)PM * PD];
__device__ float g_K[(size_t)PM * PD];
__device__ float g_cos[PS * (PHD / 2)];
__device__ float g_sin[PS * (PHD / 2)];
__device__ int8_t g_A8[(size_t)PM * KB8];            // x int8 2-term
__device__ int8_t g_B8q[(size_t)PD * KB8];
__device__ int8_t g_B8k[(size_t)PD * KB8];
__device__ int8_t g_B8v[(size_t)PD * KB8];
__device__ float g_sax[PM];
__device__ float g_sbq[PD];
__device__ float g_sbk[PD];
__device__ float g_sbv[PD];
__device__ __half g_Bo2[(size_t)PD * K2];            // Wo fp16 [hi|hi]
__device__ __half g_AxO[(size_t)PM * K2];            // attn out fp16 [hi|lo]
__device__ __half g_Q2h[(size_t)PB * PH * PS * 256]; // [qh|ql]*scale
__device__ __half g_K2h[(size_t)PB * PH * PS * 256]; // [kh|kh]
__device__ __half g_Vh[(size_t)PB * PH * PS * PHD];

// ---------------------------------------------------------------------------
// PTX helpers
// ---------------------------------------------------------------------------
__device__ __forceinline__ uint32_t smem_u32(const void* p) {
    uint32_t a;
    asm("{ .reg .u64 t; cvta.to.shared.u64 t, %1; cvt.u32.u64 %0, t; }"
        : "=r"(a) : "l"(p));
    return a;
}

#define CP_ASYNC16(smem, gptr) \
    asm volatile("cp.async.cg.shared.global [%0], [%1], 16;" \
                 :: "r"(smem), "l"(gptr) : "memory")
#define CP_COMMIT() asm volatile("cp.async.commit_group;" ::: "memory")
#define CP_WAIT2()  asm volatile("cp.async.wait_group 2;" ::: "memory")
#define CP_WAIT0()  asm volatile("cp.async.wait_group 0;" ::: "memory")

#define LDSM_X4(r0, r1, r2, r3, addr) \
    asm volatile("ldmatrix.sync.aligned.m8n8.x4.shared.b16 {%0,%1,%2,%3}, [%4];" \
                 : "=r"(r0), "=r"(r1), "=r"(r2), "=r"(r3) : "r"(addr))
#define LDSM_X4T(r0, r1, r2, r3, addr) \
    asm volatile("ldmatrix.sync.aligned.m8n8.x4.trans.shared.b16 {%0,%1,%2,%3}, [%4];" \
                 : "=r"(r0), "=r"(r1), "=r"(r2), "=r"(r3) : "r"(addr))
#define LDSM_X2(r0, r1, addr) \
    asm volatile("ldmatrix.sync.aligned.m8n8.x2.shared.b16 {%0,%1}, [%2];" \
                 : "=r"(r0), "=r"(r1) : "r"(addr))

#define MMA_16816_F16(c0, c1, c2, c3, a0, a1, a2, a3, b0, b1) \
    asm volatile("mma.sync.aligned.m16n8k16.row.col.f32.f16.f16.f32 " \
                 "{%0,%1,%2,%3}, {%4,%5,%6,%7}, {%8,%9}, {%0,%1,%2,%3};" \
                 : "+f"(c0), "+f"(c1), "+f"(c2), "+f"(c3) \
                 : "r"(a0), "r"(a1), "r"(a2), "r"(a3), "r"(b0), "r"(b1))

#define MMA_16832_S8(c0, c1, c2, c3, a0, a1, a2, a3, b0, b1) \
    asm volatile("mma.sync.aligned.m16n8k32.row.col.s32.s8.s8.s32 " \
                 "{%0,%1,%2,%3}, {%4,%5,%6,%7}, {%8,%9}, {%0,%1,%2,%3};" \
                 : "+r"(c0), "+r"(c1), "+r"(c2), "+r"(c3) \
                 : "r"(a0), "r"(a1), "r"(a2), "r"(a3), "r"(b0), "r"(b1))

// swizzles
__device__ __forceinline__ uint32_t swz64(int r, int ch) {   // 64B rows, 4x16B chunks
    return (uint32_t)(r * 64 + (((ch) ^ ((r >> 1) & 3)) << 4));
}
__device__ __forceinline__ uint32_t swzV(int r, int ch) {    // 256B rows, 16x16B chunks
    return (uint32_t)(r * 256 + (((ch) ^ (r & 7)) << 4));
}

// ---------------------------------------------------------------------------
// Row-wise 2-term int8 quantization: X[row][0..2048) fp32 ->
//   Y[row][0..2048) = a1 = rn(x/s), Y[row][2048..4096) = a2 = rn((x/s-a1)*128)
//   S[row] = s = maxabs/127
// ---------------------------------------------------------------------------
__global__ __launch_bounds__(256)
void quant8(const float* __restrict__ X, int8_t* __restrict__ Y,
            float* __restrict__ S)
{
    const int row = blockIdx.x;
    const int tid = threadIdx.x;
    const float* src = X + (size_t)row * PD;
    float v[8];
    *(float4*)&v[0] = *(const float4*)(src + tid * 8);
    *(float4*)&v[4] = *(const float4*)(src + tid * 8 + 4);
    float mx = 0.0f;
#pragma unroll
    for (int i = 0; i < 8; ++i) mx = fmaxf(mx, fabsf(v[i]));
#pragma unroll
    for (int off = 16; off >= 1; off >>= 1)
        mx = fmaxf(mx, __shfl_xor_sync(0xffffffffu, mx, off));
    __shared__ float wmax[8];
    if ((tid & 31) == 0) wmax[tid >> 5] = mx;
    __syncthreads();
    float m2 = wmax[0];
#pragma unroll
    for (int i = 1; i < 8; ++i) m2 = fmaxf(m2, wmax[i]);
    m2 = fmaxf(m2, 1e-30f);
    const float inv = 127.0f / m2;
    signed char q1[8], q2[8];
#pragma unroll
    for (int i = 0; i < 8; ++i) {
        float t  = v[i] * inv;
        float r1 = rintf(t);
        q1[i] = (signed char)(int)r1;
        q2[i] = (signed char)(int)rintf((t - r1) * 128.0f);
    }
    *(uint2*)(Y + (size_t)row * KB8 + tid * 8)        = *(uint2*)q1;
    *(uint2*)(Y + (size_t)row * KB8 + 2048 + tid * 8) = *(uint2*)q2;
    if (tid == 0) S[row] = m2 / 127.0f;
}

// ---------------------------------------------------------------------------
// Split fp32 -> 2-segment fp16 (Wo weights): [hi|hi]
// ---------------------------------------------------------------------------
__global__ void split2(const float* __restrict__ X, __half* __restrict__ Y,
                       int npairs)
{
    int i = blockIdx.x * blockDim.x + threadIdx.x;
    if (i >= npairs) return;
    int r = i >> 10;
    int c = (i & 1023) << 1;
    float2 v = *(const float2*)(X + (size_t)r * PD + c);
    __half2 hh = __halves2half2(__float2half(v.x), __float2half(v.y));
    __half2* base = (__half2*)(Y + (size_t)r * K2 + c);
    base[0]    = hh;
    base[1024] = hh;
}

// ---------------------------------------------------------------------------
// int8 2-term GEMM: C = Sa*Sb/128 * (128*(a1.b1) + a1.b2 + a2.b1), exact s32.
// 128x128 tile, 96 k-tiles of 64 B, 4-stage cp.async (64KB smem, occ 2).
// Phase boundary folds by acc *= 128 (no extra smem).
// MODE 0: fp32 C; MODE 1: V head-gather fp16.
// ---------------------------------------------------------------------------
#define GI_STG 4
#define GI_STAGE 16384
#define GI_SMEM (GI_STG * GI_STAGE)    // 65536
#define GI_KT 96

__device__ __forceinline__ int gi_aoff(int t) {
    int i = t & 31, ph = t >> 5;
    return ((ph == 2) ? 2048 : 0) + i * 64;
}
__device__ __forceinline__ int gi_boff(int t) {
    int i = t & 31, ph = t >> 5;
    return ((ph == 1) ? 2048 : 0) + i * 64;
}

template<int MODE>
__global__ __launch_bounds__(256, 2)
void gemm_i8(const int8_t* __restrict__ A8, const int8_t* __restrict__ B8,
             const float* __restrict__ Sa, const float* __restrict__ Sb,
             float* __restrict__ C, __half* __restrict__ Vho)
{
    extern __shared__ __align__(1024) char smem[];
    const uint32_t sbase = smem_u32(smem);

    const int tid  = threadIdx.x;
    const int lane = tid & 31;
    const int wid  = tid >> 5;
    const int wm   = wid & 1;
    const int wn   = wid >> 1;
    const int bm   = blockIdx.y * 128;
    const int bn   = blockIdx.x * 128;

    const int8_t* Ag = A8 + (size_t)bm * KB8;
    const int8_t* Bg = B8 + (size_t)bn * KB8;

    uint32_t lsw[2];
    const int8_t* gA[2];
    const int8_t* gB[2];
#pragma unroll
    for (int p = 0; p < 2; ++p) {
        int idx = tid + p * 256;
        int r = idx >> 2, ch = idx & 3;
        lsw[p] = swz64(r, ch);
        gA[p] = Ag + (size_t)r * KB8 + ch * 16;
        gB[p] = Bg + (size_t)r * KB8 + ch * 16;
    }

    uint32_t a_row_off[4];
    int a_swz[4];
#pragma unroll
    for (int mi = 0; mi < 4; ++mi) {
        int r = wm * 64 + mi * 16 + (lane & 15);
        a_row_off[mi] = (uint32_t)(r * 64);
        a_swz[mi] = (r >> 1) & 3;
    }
    const int a_cpart = lane >> 4;
    uint32_t b_row_off[4];
    int b_swz[4];
#pragma unroll
    for (int nj = 0; nj < 4; ++nj) {
        int r = wn * 32 + nj * 8 + (lane & 7);
        b_row_off[nj] = (uint32_t)(r * 64);
        b_swz[nj] = (r >> 1) & 3;
    }
    const int b_cpart = (lane >> 3) & 1;

    int acc[4][4][4];
#pragma unroll
    for (int mi = 0; mi < 4; ++mi)
#pragma unroll
        for (int nj = 0; nj < 4; ++nj)
#pragma unroll
            for (int e = 0; e < 4; ++e) acc[mi][nj][e] = 0;

    // prologue: stages 0..2
#pragma unroll
    for (int s = 0; s < GI_STG - 1; ++s) {
        uint32_t sA = sbase + s * GI_STAGE;
        uint32_t sB = sA + 8192;
        int ao = gi_aoff(s), bo = gi_boff(s);
#pragma unroll
        for (int p = 0; p < 2; ++p) {
            CP_ASYNC16(sA + lsw[p], gA[p] + ao);
            CP_ASYNC16(sB + lsw[p], gB[p] + bo);
        }
        CP_COMMIT();
    }

    for (int kt = 0; kt < GI_KT; ++kt) {
        CP_WAIT2();
        __syncthreads();

        int nk = kt + GI_STG - 1;
        if (nk < GI_KT) {
            uint32_t sA = sbase + (nk & 3) * GI_STAGE;
            uint32_t sB = sA + 8192;
            int ao = gi_aoff(nk), bo = gi_boff(nk);
#pragma unroll
            for (int p = 0; p < 2; ++p) {
                CP_ASYNC16(sA + lsw[p], gA[p] + ao);
                CP_ASYNC16(sB + lsw[p], gB[p] + bo);
            }
        }
        CP_COMMIT();

        uint32_t sA = sbase + (kt & 3) * GI_STAGE;
        uint32_t sB = sA + 8192;
#pragma unroll
        for (int h = 0; h < 2; ++h) {
            uint32_t a0[4], a1[4], a2[4], a3[4];
#pragma unroll
            for (int mi = 0; mi < 4; ++mi) {
                uint32_t addr = sA + a_row_off[mi]
                              + (uint32_t)(((2 * h + a_cpart) ^ a_swz[mi]) << 4);
                LDSM_X4(a0[mi], a1[mi], a2[mi], a3[mi], addr);
            }
            uint32_t b0[4], b1[4];
#pragma unroll
            for (int nj = 0; nj < 4; ++nj) {
                uint32_t addr = sB + b_row_off[nj]
                              + (uint32_t)(((2 * h + b_cpart) ^ b_swz[nj]) << 4);
                LDSM_X2(b0[nj], b1[nj], addr);
            }
#pragma unroll
            for (int mi = 0; mi < 4; ++mi)
#pragma unroll
                for (int nj = 0; nj < 4; ++nj)
                    MMA_16832_S8(acc[mi][nj][0], acc[mi][nj][1],
                                 acc[mi][nj][2], acc[mi][nj][3],
                                 a0[mi], a1[mi], a2[mi], a3[mi],
                                 b0[nj], b1[nj]);
        }

        // phase-1 boundary: fold G1 by scaling accumulators (exact, in-register)
        if (kt == 31) {
#pragma unroll
            for (int mi = 0; mi < 4; ++mi)
#pragma unroll
                for (int nj = 0; nj < 4; ++nj) {
                    acc[mi][nj][0] <<= 7; acc[mi][nj][1] <<= 7;
                    acc[mi][nj][2] <<= 7; acc[mi][nj][3] <<= 7;
                }
        }
        __syncthreads();
    }

    // epilogue: dequant C = Sa*Sb/128 * acc
    const int erow = (lane >> 2);
    const int ecol = (lane & 3) * 2;
    float sar[4][2], sbc[4][2];
#pragma unroll
    for (int mi = 0; mi < 4; ++mi) {
        int row = bm + wm * 64 + mi * 16 + erow;
        sar[mi][0] = Sa[row] * 0.0078125f;
        sar[mi][1] = Sa[row + 8] * 0.0078125f;
    }
#pragma unroll
    for (int nj = 0; nj < 4; ++nj) {
        int col = bn + wn * 32 + nj * 8 + ecol;
        sbc[nj][0] = Sb[col];
        sbc[nj][1] = Sb[col + 1];
    }
#pragma unroll
    for (int mi = 0; mi < 4; ++mi) {
#pragma unroll
        for (int nj = 0; nj < 4; ++nj) {
            float c0 = sar[mi][0] * sbc[nj][0] * (float)acc[mi][nj][0];
            float c1 = sar[mi][0] * sbc[nj][1] * (float)acc[mi][nj][1];
            float c2 = sar[mi][1] * sbc[nj][0] * (float)acc[mi][nj][2];
            float c3 = sar[mi][1] * sbc[nj][1] * (float)acc[mi][nj][3];
            int row = bm + wm * 64 + mi * 16 + erow;
            int col = bn + wn * 32 + nj * 8 + ecol;
            if (MODE == 0) {
                *(float2*)(C + (size_t)row * PD + col)       = make_float2(c0, c1);
                *(float2*)(C + (size_t)(row + 8) * PD + col) = make_float2(c2, c3);
            } else {
                int b = row >> 11, s = row & 2047;
                int h = col >> 7, hd = col & 127;
                size_t dst = ((size_t)(b * PH + h) * PS + s) * PHD + hd;
                *(__half2*)(Vho + dst)           = __float22half2_rn(make_float2(c0, c1));
                *(__half2*)(Vho + dst + 8 * PHD) = __float22half2_rn(make_float2(c2, c3));
            }
        }
    }
}

// ---------------------------------------------------------------------------
// fp16 2-term HMMA GEMM (proven round-6 body), Wo projection. K = 4096.
// ---------------------------------------------------------------------------
#define HG_BK 32
#define HG_STG 4
#define HG_STAGE_BYTES 16384
#define HG_SMEM (HG_STG * HG_STAGE_BYTES)
#define HG_KT (K2 / HG_BK)     // 128

__global__ __launch_bounds__(256, 2)
void gemm_f16(const __half* __restrict__ A3, const __half* __restrict__ B3,
              float* __restrict__ C)
{
    extern __shared__ __align__(1024) char smem[];
    const uint32_t sbase = smem_u32(smem);

    const int tid  = threadIdx.x;
    const int lane = tid & 31;
    const int wid  = tid >> 5;
    const int wm   = wid & 1;
    const int wn   = wid >> 1;
    const int bm   = blockIdx.y * 128;
    const int bn   = blockIdx.x * 128;

    const __half* Ag = A3 + (size_t)bm * K2;
    const __half* Bg = B3 + (size_t)bn * K2;

    uint32_t lsw[2];
    const __half* gA[2];
    const __half* gB[2];
#pragma unroll
    for (int p = 0; p < 2; ++p) {
        int idx = tid + p * 256;
        int r = idx >> 2, ch = idx & 3;
        lsw[p] = swz64(r, ch);
        gA[p] = Ag + (size_t)r * K2 + ch * 8;
        gB[p] = Bg + (size_t)r * K2 + ch * 8;
    }

    uint32_t a_row_off[4];
    int a_swz[4];
#pragma unroll
    for (int mi = 0; mi < 4; ++mi) {
        int r = wm * 64 + mi * 16 + (lane & 15);
        a_row_off[mi] = (uint32_t)(r * 64);
        a_swz[mi] = (r >> 1) & 3;
    }
    const int a_cpart = lane >> 4;
    uint32_t b_row_off[4];
    int b_swz[4];
#pragma unroll
    for (int nj = 0; nj < 4; ++nj) {
        int r = wn * 32 + nj * 8 + (lane & 7);
        b_row_off[nj] = (uint32_t)(r * 64);
        b_swz[nj] = (r >> 1) & 3;
    }
    const int b_cpart = (lane >> 3) & 1;

    float acc[4][4][4];
#pragma unroll
    for (int mi = 0; mi < 4; ++mi)
#pragma unroll
        for (int nj = 0; nj < 4; ++nj)
#pragma unroll
            for (int e = 0; e < 4; ++e) acc[mi][nj][e] = 0.0f;

#pragma unroll
    for (int s = 0; s < HG_STG - 1; ++s) {
        uint32_t sA = sbase + s * HG_STAGE_BYTES;
        uint32_t sB = sA + 8192;
        int k0 = s * HG_BK;
#pragma unroll
        for (int p = 0; p < 2; ++p) {
            CP_ASYNC16(sA + lsw[p], gA[p] + k0);
            CP_ASYNC16(sB + lsw[p], gB[p] + k0);
        }
        CP_COMMIT();
    }

    for (int kt = 0; kt < HG_KT; ++kt) {
        CP_WAIT2();
        __syncthreads();

        int nk = kt + HG_STG - 1;
        if (nk < HG_KT) {
            uint32_t sA = sbase + (nk & 3) * HG_STAGE_BYTES;
            uint32_t sB = sA + 8192;
            int k0 = nk * HG_BK;
#pragma unroll
            for (int p = 0; p < 2; ++p) {
                CP_ASYNC16(sA + lsw[p], gA[p] + k0);
                CP_ASYNC16(sB + lsw[p], gB[p] + k0);
            }
        }
        CP_COMMIT();

        uint32_t sA = sbase + (kt & 3) * HG_STAGE_BYTES;
        uint32_t sB = sA + 8192;
#pragma unroll
        for (int h = 0; h < 2; ++h) {
            uint32_t a0[4], a1[4], a2[4], a3[4];
#pragma unroll
            for (int mi = 0; mi < 4; ++mi) {
                uint32_t addr = sA + a_row_off[mi]
                              + (uint32_t)(((2 * h + a_cpart) ^ a_swz[mi]) << 4);
                LDSM_X4(a0[mi], a1[mi], a2[mi], a3[mi], addr);
            }
            uint32_t b0[4], b1[4];
#pragma unroll
            for (int nj = 0; nj < 4; ++nj) {
                uint32_t addr = sB + b_row_off[nj]
                              + (uint32_t)(((2 * h + b_cpart) ^ b_swz[nj]) << 4);
                LDSM_X2(b0[nj], b1[nj], addr);
            }
#pragma unroll
            for (int mi = 0; mi < 4; ++mi)
#pragma unroll
                for (int nj = 0; nj < 4; ++nj)
                    MMA_16816_F16(acc[mi][nj][0], acc[mi][nj][1],
                                  acc[mi][nj][2], acc[mi][nj][3],
                                  a0[mi], a1[mi], a2[mi], a3[mi],
                                  b0[nj], b1[nj]);
        }
        __syncthreads();
    }

    const int erow = (lane >> 2);
    const int ecol = (lane & 3) * 2;
#pragma unroll
    for (int mi = 0; mi < 4; ++mi) {
#pragma unroll
        for (int nj = 0; nj < 4; ++nj) {
            int row = bm + wm * 64 + mi * 16 + erow;
            int col = bn + wn * 32 + nj * 8 + ecol;
            *(float2*)(C + (size_t)row * PD + col) =
                make_float2(acc[mi][nj][0], acc[mi][nj][1]);
            *(float2*)(C + (size_t)(row + 8) * PD + col) =
                make_float2(acc[mi][nj][2], acc[mi][nj][3]);
        }
    }
}

// ---------------------------------------------------------------------------
// RoPE tables (fp64 trig on fp32-rounded angle chain)
// ---------------------------------------------------------------------------
__global__ void rope_tables(float* __restrict__ ct, float* __restrict__ st)
{
    int idx = blockIdx.x * blockDim.x + threadIdx.x;
    if (idx >= PS * (PHD / 2)) return;
    int s = idx >> 6;
    int j = idx & 63;
    float invf = (float)pow(10000.0, -(double)j / 64.0);
    float ang  = (float)s * invf;
    double a   = (double)ang;
    double cs, sn;
    sincos(a, &sn, &cs);
    ct[idx] = (float)cs;
    st[idx] = (float)sn;
}

// ---------------------------------------------------------------------------
// RoPE + scale + fp16 split: Q -> [qh|ql]*scale, K -> [kh|kh]; [b,h,s,256].
// ---------------------------------------------------------------------------
__global__ __launch_bounds__(256)
void rope_split(const float* __restrict__ Q, const float* __restrict__ Kf,
                const float* __restrict__ ct, const float* __restrict__ st,
                __half* __restrict__ Q2, __half* __restrict__ K2g)
{
    const int row = blockIdx.x;
    const int b   = row >> 11;
    const int s   = row & (PS - 1);
    const int tid = threadIdx.x;
    __shared__ float buf[PD];

#pragma unroll
    for (int pass = 0; pass < 2; ++pass) {
        const float* src = (pass == 0 ? Q : Kf) + (size_t)row * PD;
        __half* dstbase = pass == 0 ? Q2 : K2g;
        for (int i = tid; i < PD; i += 256) buf[i] = src[i];
        __syncthreads();
        for (int i = tid; i < PD; i += 256) {
            int d = i & (PHD - 1);
            int h = i >> 7;
            int j = d & 63;
            float c  = ct[s * 64 + j];
            float sn = st[s * 64 + j];
            float x  = buf[i];
            float xr = (d < 64) ? -buf[i + 64] : buf[i - 64];
            float val = fmaf(x, c, xr * sn);
            if (pass == 0) val *= ATT_SCALE;
            __half hi = __float2half(val);
            __half* out = dstbase + ((size_t)(b * PH + h) * PS + s) * 256 + d;
            out[0] = hi;
            out[128] = (pass == 0) ? __float2half(val - __half2float(hi)) : hi;
        }
        __syncthreads();
    }
}

// ---------------------------------------------------------------------------
// Tensor-core causal flash attention (fp16): QK 2-term (K'=256),
// PV single term (p_hi x v_hi). Output -> fp16 [hi|lo] for Wo GEMM.
// ---------------------------------------------------------------------------
#define ATS_Q  0          // 8 panels x 8192 = 65536
#define ATS_K  65536      // 8 panels x 4096 = 32768
#define ATS_VH 98304      // 16384
#define ATS_P  114688     // 2 panels x 8192 = 16384
#define ATT_SMEM 131072

__global__ __launch_bounds__(256, 1)
void attn_tc(const __half* __restrict__ Q2,
             const __half* __restrict__ K2g,
             const __half* __restrict__ Vh,
             __half* __restrict__ AXO)
{
    extern __shared__ __align__(1024) char sm[];
    const uint32_t sb = smem_u32(sm);
    const int tid  = threadIdx.x;
    const int lane = tid & 31;
    const int w    = tid >> 5;
    const int qt   = 15 - (int)blockIdx.x;
    const int bh   = blockIdx.y;
    const int qb   = qt * 128;
    const int nkt  = 2 * qt + 2;

    const __half* q2 = Q2 + ((size_t)bh * PS + qb) * 256;
    const __half* k2 = K2g + (size_t)bh * PS * 256;
    const __half* vh = Vh + (size_t)bh * PS * PHD;

#pragma unroll
    for (int p = 0; p < 8; ++p)
#pragma unroll
        for (int ps = 0; ps < 2; ++ps) {
            int idx = tid + ps * 256;
            int r = idx >> 2, ch = idx & 3;
            CP_ASYNC16(sb + ATS_Q + p * 8192 + swz64(r, ch),
                       q2 + (size_t)r * 256 + p * 32 + ch * 8);
        }
    {
        int r = tid >> 2, ch = tid & 3;
#pragma unroll
        for (int p = 0; p < 8; ++p)
            CP_ASYNC16(sb + ATS_K + p * 4096 + swz64(r, ch),
                       k2 + (size_t)r * 256 + p * 32 + ch * 8);
#pragma unroll
        for (int ps = 0; ps < 4; ++ps) {
            int idx = tid + ps * 256;
            int rr = idx >> 4, cc = idx & 15;
            CP_ASYNC16(sb + ATS_VH + swzV(rr, cc), vh + (size_t)rr * PHD + cc * 8);
        }
    }
    CP_COMMIT();

    float m0 = -INFINITY, m1 = -INFINITY, l0 = 0.0f, l1 = 0.0f;
    float oa[16][4];
#pragma unroll
    for (int j = 0; j < 16; ++j)
#pragma unroll
        for (int e = 0; e < 4; ++e) oa[j][e] = 0.0f;

    const int arow  = w * 16 + (lane & 15);
    const int aswz  = (arow >> 1) & 3;
    const int acp   = lane >> 4;
    const int rr0   = w * 16 + (lane >> 2);
    const int prow0 = rr0;
    const int prow1 = rr0 + 8;
    const int pswz0 = (prow0 >> 1) & 3;
    const int pswz1 = (prow1 >> 1) & 3;
    const int vkrow_base = (lane & 7) + 8 * ((lane >> 3) & 1);

    for (int kt = 0; kt < nkt; ++kt) {
        CP_WAIT0();
        __syncthreads();

        float sa[8][4];
#pragma unroll
        for (int j = 0; j < 8; ++j)
#pragma unroll
            for (int e = 0; e < 4; ++e) sa[j][e] = 0.0f;

#pragma unroll
        for (int p = 0; p < 8; ++p) {
#pragma unroll
            for (int h = 0; h < 2; ++h) {
                uint32_t a0, a1, a2, a3;
                LDSM_X4(a0, a1, a2, a3,
                        sb + ATS_Q + p * 8192 + arow * 64
                           + (((2 * h + acp) ^ aswz) << 4));
#pragma unroll
                for (int jj = 0; jj < 4; ++jj) {
                    int brow = jj * 16 + (lane & 15);
                    uint32_t b0, b1, b2, b3;
                    LDSM_X4(b0, b1, b2, b3,
                            sb + ATS_K + p * 4096 + brow * 64
                               + (((2 * h + acp) ^ ((brow >> 1) & 3)) << 4));
                    MMA_16816_F16(sa[2 * jj][0], sa[2 * jj][1],
                                  sa[2 * jj][2], sa[2 * jj][3],
                                  a0, a1, a2, a3, b0, b2);
                    MMA_16816_F16(sa[2 * jj + 1][0], sa[2 * jj + 1][1],
                                  sa[2 * jj + 1][2], sa[2 * jj + 1][3],
                                  a0, a1, a2, a3, b1, b3);
                }
            }
        }
        __syncthreads();

        if (kt + 1 < nkt) {
            const __half* kp = k2 + (size_t)(kt + 1) * 64 * 256;
            int r = tid >> 2, ch = tid & 3;
#pragma unroll
            for (int p = 0; p < 8; ++p)
                CP_ASYNC16(sb + ATS_K + p * 4096 + swz64(r, ch),
                           kp + (size_t)r * 256 + p * 32 + ch * 8);
        }
        CP_COMMIT();

        const int kb = kt * 64;
        if (kt >= 2 * qt) {
            const int rg0 = qb + rr0;
            const int rg1 = rg0 + 8;
#pragma unroll
            for (int j = 0; j < 8; ++j) {
                int c0 = kb + j * 8 + 2 * (lane & 3);
                if (c0 > rg0)     sa[j][0] = -INFINITY;
                if (c0 + 1 > rg0) sa[j][1] = -INFINITY;
                if (c0 > rg1)     sa[j][2] = -INFINITY;
                if (c0 + 1 > rg1) sa[j][3] = -INFINITY;
            }
        }
        float rmax0 = -INFINITY, rmax1 = -INFINITY;
#pragma unroll
        for (int j = 0; j < 8; ++j) {
            rmax0 = fmaxf(rmax0, fmaxf(sa[j][0], sa[j][1]));
            rmax1 = fmaxf(rmax1, fmaxf(sa[j][2], sa[j][3]));
        }
        rmax0 = fmaxf(rmax0, __shfl_xor_sync(0xffffffffu, rmax0, 1));
        rmax0 = fmaxf(rmax0, __shfl_xor_sync(0xffffffffu, rmax0, 2));
        rmax1 = fmaxf(rmax1, __shfl_xor_sync(0xffffffffu, rmax1, 1));
        rmax1 = fmaxf(rmax1, __shfl_xor_sync(0xffffffffu, rmax1, 2));

        float mn0 = fmaxf(m0, rmax0);
        float mn1 = fmaxf(m1, rmax1);
        float corr0 = __expf(m0 - mn0);
        float corr1 = __expf(m1 - mn1);
        m0 = mn0; m1 = mn1;
#pragma unroll
        for (int j = 0; j < 16; ++j) {
            oa[j][0] *= corr0; oa[j][1] *= corr0;
            oa[j][2] *= corr1; oa[j][3] *= corr1;
        }
        float rs0 = 0.0f, rs1 = 0.0f;
#pragma unroll
        for (int j = 0; j < 8; ++j) {
            float p0 = __expf(sa[j][0] - mn0);
            float p1 = __expf(sa[j][1] - mn0);
            float p2 = __expf(sa[j][2] - mn1);
            float p3 = __expf(sa[j][3] - mn1);
            rs0 += p0 + p1;
            rs1 += p2 + p3;
            int key = j * 8 + 2 * (lane & 3);
            int panel = key >> 5, kin = key & 31;
            uint32_t inoff = (uint32_t)(((kin >> 3)) << 4) + ((kin & 7) << 1);
            __half2 h2a = __float22half2_rn(make_float2(p0, p1));
            __half2 h2b = __float22half2_rn(make_float2(p2, p3));
            uint32_t ba0 = (uint32_t)(ATS_P + panel * 8192) + prow0 * 64
                         + ((inoff & 0xF0u) ^ (pswz0 << 4)) + (inoff & 0xFu);
            uint32_t ba1 = (uint32_t)(ATS_P + panel * 8192) + prow1 * 64
                         + ((inoff & 0xF0u) ^ (pswz1 << 4)) + (inoff & 0xFu);
            *(__half2*)(sm + ba0) = h2a;
            *(__half2*)(sm + ba1) = h2b;
        }
        rs0 += __shfl_xor_sync(0xffffffffu, rs0, 1);
        rs0 += __shfl_xor_sync(0xffffffffu, rs0, 2);
        rs1 += __shfl_xor_sync(0xffffffffu, rs1, 1);
        rs1 += __shfl_xor_sync(0xffffffffu, rs1, 2);
        l0 = l0 * corr0 + rs0;
        l1 = l1 * corr1 + rs1;
        __syncwarp();

        // PV: O += p_hi x v_hi
#pragma unroll
        for (int s = 0; s < 4; ++s) {
            uint32_t a0, a1, a2, a3;
            LDSM_X4(a0, a1, a2, a3,
                    sb + ATS_P + (s >> 1) * 8192 + arow * 64
                       + (((2 * (s & 1) + acp) ^ aswz) << 4));
            int vk = s * 16 + vkrow_base;
#pragma unroll
            for (int g = 0; g < 8; ++g) {
                uint32_t b0, b1, b2, b3;
                LDSM_X4T(b0, b1, b2, b3,
                         sb + ATS_VH + vk * 256
                            + ((((2 * g + (lane >> 4)) ^ (vk & 7))) << 4));
                MMA_16816_F16(oa[2 * g][0], oa[2 * g][1],
                              oa[2 * g][2], oa[2 * g][3],
                              a0, a1, a2, a3, b0, b1);
                MMA_16816_F16(oa[2 * g + 1][0], oa[2 * g + 1][1],
                              oa[2 * g + 1][2], oa[2 * g + 1][3],
                              a0, a1, a2, a3, b2, b3);
            }
        }
        __syncthreads();

        if (kt + 1 < nkt) {
            const __half* va = vh + (size_t)(kt + 1) * 64 * PHD;
#pragma unroll
            for (int ps = 0; ps < 4; ++ps) {
                int idx = tid + ps * 256;
                int rr = idx >> 4, cc = idx & 15;
                CP_ASYNC16(sb + ATS_VH + swzV(rr, cc), va + (size_t)rr * PHD + cc * 8);
            }
        }
        CP_COMMIT();
    }

    const float inv0 = 1.0f / l0;
    const float inv1 = 1.0f / l1;
    const int b = bh >> 4, h = bh & 15;
    const size_t row0 = (size_t)b * PS + qb + rr0;
    const size_t row1 = row0 + 8;
#pragma unroll
    for (int j = 0; j < 16; ++j) {
        int col = h * PHD + j * 8 + 2 * (lane & 3);
        float2 p0 = make_float2(oa[j][0] * inv0, oa[j][1] * inv0);
        float2 p1 = make_float2(oa[j][2] * inv1, oa[j][3] * inv1);
        __half2 h20 = __float22half2_rn(p0);
        __half2 h21 = __float22half2_rn(p1);
        __half2 l20 = __float22half2_rn(make_float2(
            p0.x - __half2float(__low2half(h20)),
            p0.y - __half2float(__high2half(h20))));
        __half2 l21 = __float22half2_rn(make_float2(
            p1.x - __half2float(__low2half(h21)),
            p1.y - __half2float(__high2half(h21))));
        __half* d0 = AXO + row0 * K2 + col;
        __half* d1 = AXO + row1 * K2 + col;
        *(__half2*)(d0)        = h20;
        *(__half2*)(d0 + 2048) = l20;
        *(__half2*)(d1)        = h21;
        *(__half2*)(d1 + 2048) = l21;
    }
}

// ---------------------------------------------------------------------------
// kernel_launch
// ---------------------------------------------------------------------------
extern "C" void kernel_launch(void* const* d_in, const int* in_sizes, int n_in,
                              void* d_out, int out_size)
{
    const float* x  = (const float*)d_in[0];
    const float* Wq = (const float*)d_in[1];
    const float* Wk = (const float*)d_in[2];
    const float* Wv = (const float*)d_in[3];
    const float* Wo = (const float*)d_in[4];
    float* out = (float*)d_out;

    float *Qp, *Kp, *cp, *sp, *saxp, *sbqp, *sbkp, *sbvp;
    int8_t *A8p, *B8qp, *B8kp, *B8vp;
    __half *Bo2p, *AxOp, *Q2p, *K2p, *Vhp;
    cudaGetSymbolAddress((void**)&Qp,   g_Q);
    cudaGetSymbolAddress((void**)&Kp,   g_K);
    cudaGetSymbolAddress((void**)&cp,   g_cos);
    cudaGetSymbolAddress((void**)&sp,   g_sin);
    cudaGetSymbolAddress((void**)&A8p,  g_A8);
    cudaGetSymbolAddress((void**)&B8qp, g_B8q);
    cudaGetSymbolAddress((void**)&B8kp, g_B8k);
    cudaGetSymbolAddress((void**)&B8vp, g_B8v);
    cudaGetSymbolAddress((void**)&saxp, g_sax);
    cudaGetSymbolAddress((void**)&sbqp, g_sbq);
    cudaGetSymbolAddress((void**)&sbkp, g_sbk);
    cudaGetSymbolAddress((void**)&sbvp, g_sbv);
    cudaGetSymbolAddress((void**)&Bo2p, g_Bo2);
    cudaGetSymbolAddress((void**)&AxOp, g_AxO);
    cudaGetSymbolAddress((void**)&Q2p,  g_Q2h);
    cudaGetSymbolAddress((void**)&K2p,  g_K2h);
    cudaGetSymbolAddress((void**)&Vhp,  g_Vh);

    cudaFuncSetAttribute((const void*)gemm_i8<0>,
                         cudaFuncAttributeMaxDynamicSharedMemorySize, GI_SMEM);
    cudaFuncSetAttribute((const void*)gemm_i8<1>,
                         cudaFuncAttributeMaxDynamicSharedMemorySize, GI_SMEM);
    cudaFuncSetAttribute((const void*)gemm_f16,
                         cudaFuncAttributeMaxDynamicSharedMemorySize, HG_SMEM);
    cudaFuncSetAttribute((const void*)attn_tc,
                         cudaFuncAttributeMaxDynamicSharedMemorySize, ATT_SMEM);

    const int wpairs = PD * PD / 2;

    quant8<<<PM, 256>>>(x,  A8p,  saxp);
    quant8<<<PD, 256>>>(Wq, B8qp, sbqp);
    quant8<<<PD, 256>>>(Wk, B8kp, sbkp);
    quant8<<<PD, 256>>>(Wv, B8vp, sbvp);
    split2<<<(wpairs + 255) / 256, 256>>>(Wo, Bo2p, wpairs);

    dim3 ggrid(PD / 128, PM / 128);   // (16, 32)

    gemm_i8<0><<<ggrid, 256, GI_SMEM>>>(A8p, B8qp, saxp, sbqp, Qp, nullptr);
    gemm_i8<0><<<ggrid, 256, GI_SMEM>>>(A8p, B8kp, saxp, sbkp, Kp, nullptr);
    gemm_i8<1><<<ggrid, 256, GI_SMEM>>>(A8p, B8vp, saxp, sbvp, nullptr, Vhp);

    rope_tables<<<(PS * 64 + 255) / 256, 256>>>(cp, sp);
    rope_split<<<PM, 256>>>(Qp, Kp, cp, sp, Q2p, K2p);

    attn_tc<<<dim3(PS / 128, PB * PH), 256, ATT_SMEM>>>(Q2p, K2p, Vhp, AxOp);

    gemm_f16<<<ggrid, 256, HG_SMEM>>>(AxOp, Bo2p, out);
}

// round 9
// speedup vs baseline: 2.5999x; 2.5661x over previous
#include <cuda_runtime.h>
#include <cuda_fp16.h>
#include <math.h>
#include <stdint.h>

// ---------------------------------------------------------------------------
// Problem constants
// ---------------------------------------------------------------------------
#define PB 2
#define PS 2048
#define PD 2048
#define PH 16
#define PHD 128
#define PM (PB * PS)          // 4096 rows
#define K2 (2 * PD)           // 4096: fp16 2-term split-K
#define NQKV (3 * PD)         // 6144: fused QKV output columns
#define ATT_SCALE 0.08838834764831845f

// ---------------------------------------------------------------------------
// Scratch (device globals; no allocation allowed)
// ---------------------------------------------------------------------------
__device__ float g_Q[(size_t)PM * PD];
__device__ float g_K[(size_t)PM * PD];
__device__ __half g_Ax2[(size_t)PM * K2];                // x, fp16 [hi|lo]
__device__ __half g_Bqkv[(size_t)NQKV * K2];             // [Wq;Wk;Wv] fp16 [hi|hi]
__device__ __half g_Bo2[(size_t)PD * K2];                // Wo fp16 [hi|hi]
__device__ __half g_AxO[(size_t)PM * K2];                // attn out fp16 [hi|lo]
__device__ __half g_Q2h[(size_t)PB * PH * PS * 256];     // [qh|ql]*scale
__device__ __half g_K2h[(size_t)PB * PH * PS * 256];     // [kh|kh]
__device__ __half g_Vh[(size_t)PB * PH * PS * PHD];

// ---------------------------------------------------------------------------
// PTX helpers (sm_80-compatible: cp.async + ldmatrix + mma.sync)
// ---------------------------------------------------------------------------
__device__ __forceinline__ uint32_t smem_u32(const void* p) {
    uint32_t a;
    asm("{ .reg .u64 t; cvta.to.shared.u64 t, %1; cvt.u32.u64 %0, t; }"
        : "=r"(a) : "l"(p));
    return a;
}

#define CP_ASYNC16(smem, gptr) \
    asm volatile("cp.async.cg.shared.global [%0], [%1], 16;" \
                 :: "r"(smem), "l"(gptr) : "memory")
#define CP_COMMIT() asm volatile("cp.async.commit_group;" ::: "memory")
#define CP_WAIT2()  asm volatile("cp.async.wait_group 2;" ::: "memory")
#define CP_WAIT0()  asm volatile("cp.async.wait_group 0;" ::: "memory")

#define LDSM_X4(r0, r1, r2, r3, addr) \
    asm volatile("ldmatrix.sync.aligned.m8n8.x4.shared.b16 {%0,%1,%2,%3}, [%4];" \
                 : "=r"(r0), "=r"(r1), "=r"(r2), "=r"(r3) : "r"(addr))
#define LDSM_X4T(r0, r1, r2, r3, addr) \
    asm volatile("ldmatrix.sync.aligned.m8n8.x4.trans.shared.b16 {%0,%1,%2,%3}, [%4];" \
                 : "=r"(r0), "=r"(r1), "=r"(r2), "=r"(r3) : "r"(addr))
#define LDSM_X2(r0, r1, addr) \
    asm volatile("ldmatrix.sync.aligned.m8n8.x2.shared.b16 {%0,%1}, [%2];" \
                 : "=r"(r0), "=r"(r1) : "r"(addr))

#define MMA_16816_F16(c0, c1, c2, c3, a0, a1, a2, a3, b0, b1) \
    asm volatile("mma.sync.aligned.m16n8k16.row.col.f32.f16.f16.f32 " \
                 "{%0,%1,%2,%3}, {%4,%5,%6,%7}, {%8,%9}, {%0,%1,%2,%3};" \
                 : "+f"(c0), "+f"(c1), "+f"(c2), "+f"(c3) \
                 : "r"(a0), "r"(a1), "r"(a2), "r"(a3), "r"(b0), "r"(b1))

// swizzles
__device__ __forceinline__ uint32_t swz64(int r, int ch) {   // 64B rows, 4x16B chunks
    return (uint32_t)(r * 64 + (((ch) ^ ((r >> 1) & 3)) << 4));
}
__device__ __forceinline__ uint32_t swzV(int r, int ch) {    // 256B rows, 16x16B chunks
    return (uint32_t)(r * 256 + (((ch) ^ (r & 7)) << 4));
}

// ---------------------------------------------------------------------------
// Split fp32 -> 2-segment fp16: order=0 (act): [hi|lo], order=1 (wgt): [hi|hi]
// ---------------------------------------------------------------------------
__global__ void split2(const float* __restrict__ X, __half* __restrict__ Y,
                       int order, int npairs)
{
    int i = blockIdx.x * blockDim.x + threadIdx.x;
    if (i >= npairs) return;
    int r = i >> 10;
    int c = (i & 1023) << 1;
    float2 v = *(const float2*)(X + (size_t)r * PD + c);
    __half h0 = __float2half(v.x);
    __half h1 = __float2half(v.y);
    __half2 hh = __halves2half2(h0, h1);
    __half2 seg1;
    if (order) {
        seg1 = hh;
    } else {
        __half l0 = __float2half(v.x - __half2float(h0));
        __half l1 = __float2half(v.y - __half2float(h1));
        seg1 = __halves2half2(l0, l1);
    }
    __half2* base = (__half2*)(Y + (size_t)r * K2 + c);
    base[0]    = hh;
    base[1024] = seg1;
}

// ---------------------------------------------------------------------------
// fp16 2-term HMMA GEMM, K=4096 (proven round-6 body).
//  MODE 0: Wo projection — plain fp32 C stores (N=2048 stride).
//  MODE 1: fused QKV — N=6144; per-CTA region: Q fp32 / K fp32 / V fp16 gather.
// ---------------------------------------------------------------------------
#define HG_BK 32
#define HG_STG 4
#define HG_STAGE_BYTES 16384
#define HG_SMEM (HG_STG * HG_STAGE_BYTES)
#define HG_KT (K2 / HG_BK)     // 128

template<int MODE>
__global__ __launch_bounds__(256, 2)
void gemm_f16(const __half* __restrict__ A3, const __half* __restrict__ B3,
              float* __restrict__ Cq, float* __restrict__ Ck,
              __half* __restrict__ Vho)
{
    extern __shared__ __align__(1024) char smem[];
    const uint32_t sbase = smem_u32(smem);

    const int tid  = threadIdx.x;
    const int lane = tid & 31;
    const int wid  = tid >> 5;
    const int wm   = wid & 1;
    const int wn   = wid >> 1;
    const int bm   = blockIdx.y * 128;
    const int bn   = blockIdx.x * 128;

    const __half* Ag = A3 + (size_t)bm * K2;
    const __half* Bg = B3 + (size_t)bn * K2;

    uint32_t lsw[2];
    const __half* gA[2];
    const __half* gB[2];
#pragma unroll
    for (int p = 0; p < 2; ++p) {
        int idx = tid + p * 256;
        int r = idx >> 2, ch = idx & 3;
        lsw[p] = swz64(r, ch);
        gA[p] = Ag + (size_t)r * K2 + ch * 8;
        gB[p] = Bg + (size_t)r * K2 + ch * 8;
    }

    uint32_t a_row_off[4];
    int a_swz[4];
#pragma unroll
    for (int mi = 0; mi < 4; ++mi) {
        int r = wm * 64 + mi * 16 + (lane & 15);
        a_row_off[mi] = (uint32_t)(r * 64);
        a_swz[mi] = (r >> 1) & 3;
    }
    const int a_cpart = lane >> 4;
    uint32_t b_row_off[4];
    int b_swz[4];
#pragma unroll
    for (int nj = 0; nj < 4; ++nj) {
        int r = wn * 32 + nj * 8 + (lane & 7);
        b_row_off[nj] = (uint32_t)(r * 64);
        b_swz[nj] = (r >> 1) & 3;
    }
    const int b_cpart = (lane >> 3) & 1;

    float acc[4][4][4];
#pragma unroll
    for (int mi = 0; mi < 4; ++mi)
#pragma unroll
        for (int nj = 0; nj < 4; ++nj)
#pragma unroll
            for (int e = 0; e < 4; ++e) acc[mi][nj][e] = 0.0f;

#pragma unroll
    for (int s = 0; s < HG_STG - 1; ++s) {
        uint32_t sA = sbase + s * HG_STAGE_BYTES;
        uint32_t sB = sA + 8192;
        int k0 = s * HG_BK;
#pragma unroll
        for (int p = 0; p < 2; ++p) {
            CP_ASYNC16(sA + lsw[p], gA[p] + k0);
            CP_ASYNC16(sB + lsw[p], gB[p] + k0);
        }
        CP_COMMIT();
    }

    for (int kt = 0; kt < HG_KT; ++kt) {
        CP_WAIT2();
        __syncthreads();

        int nk = kt + HG_STG - 1;
        if (nk < HG_KT) {
            uint32_t sA = sbase + (nk & 3) * HG_STAGE_BYTES;
            uint32_t sB = sA + 8192;
            int k0 = nk * HG_BK;
#pragma unroll
            for (int p = 0; p < 2; ++p) {
                CP_ASYNC16(sA + lsw[p], gA[p] + k0);
                CP_ASYNC16(sB + lsw[p], gB[p] + k0);
            }
        }
        CP_COMMIT();

        uint32_t sA = sbase + (kt & 3) * HG_STAGE_BYTES;
        uint32_t sB = sA + 8192;
#pragma unroll
        for (int h = 0; h < 2; ++h) {
            uint32_t a0[4], a1[4], a2[4], a3[4];
#pragma unroll
            for (int mi = 0; mi < 4; ++mi) {
                uint32_t addr = sA + a_row_off[mi]
                              + (uint32_t)(((2 * h + a_cpart) ^ a_swz[mi]) << 4);
                LDSM_X4(a0[mi], a1[mi], a2[mi], a3[mi], addr);
            }
            uint32_t b0[4], b1[4];
#pragma unroll
            for (int nj = 0; nj < 4; ++nj) {
                uint32_t addr = sB + b_row_off[nj]
                              + (uint32_t)(((2 * h + b_cpart) ^ b_swz[nj]) << 4);
                LDSM_X2(b0[nj], b1[nj], addr);
            }
#pragma unroll
            for (int mi = 0; mi < 4; ++mi)
#pragma unroll
                for (int nj = 0; nj < 4; ++nj)
                    MMA_16816_F16(acc[mi][nj][0], acc[mi][nj][1],
                                  acc[mi][nj][2], acc[mi][nj][3],
                                  a0[mi], a1[mi], a2[mi], a3[mi],
                                  b0[nj], b1[nj]);
        }
        __syncthreads();
    }

    const int erow = (lane >> 2);
    const int ecol = (lane & 3) * 2;
    // region: 0 -> Q (fp32), 1 -> K (fp32), 2 -> V (fp16 head-gather).
    const int region  = (MODE == 1) ? (bn >> 11) : 0;
    const int colbase = bn - region * 2048;
#pragma unroll
    for (int mi = 0; mi < 4; ++mi) {
#pragma unroll
        for (int nj = 0; nj < 4; ++nj) {
            int row = bm + wm * 64 + mi * 16 + erow;
            int col = colbase + wn * 32 + nj * 8 + ecol;
            if (MODE == 0 || region == 0) {
                *(float2*)(Cq + (size_t)row * PD + col) =
                    make_float2(acc[mi][nj][0], acc[mi][nj][1]);
                *(float2*)(Cq + (size_t)(row + 8) * PD + col) =
                    make_float2(acc[mi][nj][2], acc[mi][nj][3]);
            } else if (region == 1) {
                *(float2*)(Ck + (size_t)row * PD + col) =
                    make_float2(acc[mi][nj][0], acc[mi][nj][1]);
                *(float2*)(Ck + (size_t)(row + 8) * PD + col) =
                    make_float2(acc[mi][nj][2], acc[mi][nj][3]);
            } else {
                int b = row >> 11, s = row & 2047;
                int h = col >> 7, hd = col & 127;
                size_t dst = ((size_t)(b * PH + h) * PS + s) * PHD + hd;
                *(__half2*)(Vho + dst) = __float22half2_rn(
                    make_float2(acc[mi][nj][0], acc[mi][nj][1]));
                *(__half2*)(Vho + dst + 8 * PHD) = __float22half2_rn(
                    make_float2(acc[mi][nj][2], acc[mi][nj][3]));
            }
        }
    }
}

// ---------------------------------------------------------------------------
// RoPE + scale + fp16 split (tables computed in-block, fp64 trig on the
// fp32-rounded angle chain): Q -> [qh|ql]*scale, K -> [kh|kh]; [b,h,s,256].
// ---------------------------------------------------------------------------
__global__ __launch_bounds__(256)
void rope_split(const float* __restrict__ Q, const float* __restrict__ Kf,
                __half* __restrict__ Q2, __half* __restrict__ K2g)
{
    const int row = blockIdx.x;           // b*S + s
    const int b   = row >> 11;
    const int s   = row & (PS - 1);
    const int tid = threadIdx.x;
    __shared__ float buf[PD];
    __shared__ float cbuf[64], sbuf[64];

    if (tid < 64) {
        float invf = (float)pow(10000.0, -(double)tid / 64.0);
        float ang  = (float)s * invf;
        double cs, sn;
        sincos((double)ang, &sn, &cs);
        cbuf[tid] = (float)cs;
        sbuf[tid] = (float)sn;
    }

#pragma unroll
    for (int pass = 0; pass < 2; ++pass) {
        const float* src = (pass == 0 ? Q : Kf) + (size_t)row * PD;
        __half* dstbase = pass == 0 ? Q2 : K2g;
        for (int i = tid; i < PD; i += 256) buf[i] = src[i];
        __syncthreads();
        for (int i = tid; i < PD; i += 256) {
            int d = i & (PHD - 1);
            int h = i >> 7;
            int j = d & 63;
            float c  = cbuf[j];
            float sn = sbuf[j];
            float x  = buf[i];
            float xr = (d < 64) ? -buf[i + 64] : buf[i - 64];
            float val = fmaf(x, c, xr * sn);
            if (pass == 0) val *= ATT_SCALE;
            __half hi = __float2half(val);
            __half* out = dstbase + ((size_t)(b * PH + h) * PS + s) * 256 + d;
            out[0] = hi;
            out[128] = (pass == 0) ? __float2half(val - __half2float(hi)) : hi;
        }
        __syncthreads();
    }
}

// ---------------------------------------------------------------------------
// Tensor-core causal flash attention (fp16): QK 2-term (K'=256),
// PV single term (p_hi x v_hi). Output -> fp16 [hi|lo] for Wo GEMM.
// (Validated round-7/8 body.)
// ---------------------------------------------------------------------------
#define ATS_Q  0          // 8 panels x 8192 = 65536
#define ATS_K  65536      // 8 panels x 4096 = 32768
#define ATS_VH 98304      // 16384
#define ATS_P  114688     // 2 panels x 8192 = 16384
#define ATT_SMEM 131072

__global__ __launch_bounds__(256, 1)
void attn_tc(const __half* __restrict__ Q2,
             const __half* __restrict__ K2g,
             const __half* __restrict__ Vh,
             __half* __restrict__ AXO)
{
    extern __shared__ __align__(1024) char sm[];
    const uint32_t sb = smem_u32(sm);
    const int tid  = threadIdx.x;
    const int lane = tid & 31;
    const int w    = tid >> 5;
    const int qt   = 15 - (int)blockIdx.x;
    const int bh   = blockIdx.y;
    const int qb   = qt * 128;
    const int nkt  = 2 * qt + 2;

    const __half* q2 = Q2 + ((size_t)bh * PS + qb) * 256;
    const __half* k2 = K2g + (size_t)bh * PS * 256;
    const __half* vh = Vh + (size_t)bh * PS * PHD;

#pragma unroll
    for (int p = 0; p < 8; ++p)
#pragma unroll
        for (int ps = 0; ps < 2; ++ps) {
            int idx = tid + ps * 256;
            int r = idx >> 2, ch = idx & 3;
            CP_ASYNC16(sb + ATS_Q + p * 8192 + swz64(r, ch),
                       q2 + (size_t)r * 256 + p * 32 + ch * 8);
        }
    {
        int r = tid >> 2, ch = tid & 3;
#pragma unroll
        for (int p = 0; p < 8; ++p)
            CP_ASYNC16(sb + ATS_K + p * 4096 + swz64(r, ch),
                       k2 + (size_t)r * 256 + p * 32 + ch * 8);
#pragma unroll
        for (int ps = 0; ps < 4; ++ps) {
            int idx = tid + ps * 256;
            int rr = idx >> 4, cc = idx & 15;
            CP_ASYNC16(sb + ATS_VH + swzV(rr, cc), vh + (size_t)rr * PHD + cc * 8);
        }
    }
    CP_COMMIT();

    float m0 = -INFINITY, m1 = -INFINITY, l0 = 0.0f, l1 = 0.0f;
    float oa[16][4];
#pragma unroll
    for (int j = 0; j < 16; ++j)
#pragma unroll
        for (int e = 0; e < 4; ++e) oa[j][e] = 0.0f;

    const int arow  = w * 16 + (lane & 15);
    const int aswz  = (arow >> 1) & 3;
    const int acp   = lane >> 4;
    const int rr0   = w * 16 + (lane >> 2);
    const int prow0 = rr0;
    const int prow1 = rr0 + 8;
    const int pswz0 = (prow0 >> 1) & 3;
    const int pswz1 = (prow1 >> 1) & 3;
    const int vkrow_base = (lane & 7) + 8 * ((lane >> 3) & 1);

    for (int kt = 0; kt < nkt; ++kt) {
        CP_WAIT0();
        __syncthreads();

        float sa[8][4];
#pragma unroll
        for (int j = 0; j < 8; ++j)
#pragma unroll
            for (int e = 0; e < 4; ++e) sa[j][e] = 0.0f;

#pragma unroll
        for (int p = 0; p < 8; ++p) {
#pragma unroll
            for (int h = 0; h < 2; ++h) {
                uint32_t a0, a1, a2, a3;
                LDSM_X4(a0, a1, a2, a3,
                        sb + ATS_Q + p * 8192 + arow * 64
                           + (((2 * h + acp) ^ aswz) << 4));
#pragma unroll
                for (int jj = 0; jj < 4; ++jj) {
                    int brow = jj * 16 + (lane & 15);
                    uint32_t b0, b1, b2, b3;
                    LDSM_X4(b0, b1, b2, b3,
                            sb + ATS_K + p * 4096 + brow * 64
                               + (((2 * h + acp) ^ ((brow >> 1) & 3)) << 4));
                    MMA_16816_F16(sa[2 * jj][0], sa[2 * jj][1],
                                  sa[2 * jj][2], sa[2 * jj][3],
                                  a0, a1, a2, a3, b0, b2);
                    MMA_16816_F16(sa[2 * jj + 1][0], sa[2 * jj + 1][1],
                                  sa[2 * jj + 1][2], sa[2 * jj + 1][3],
                                  a0, a1, a2, a3, b1, b3);
                }
            }
        }
        __syncthreads();

        if (kt + 1 < nkt) {
            const __half* kp = k2 + (size_t)(kt + 1) * 64 * 256;
            int r = tid >> 2, ch = tid & 3;
#pragma unroll
            for (int p = 0; p < 8; ++p)
                CP_ASYNC16(sb + ATS_K + p * 4096 + swz64(r, ch),
                           kp + (size_t)r * 256 + p * 32 + ch * 8);
        }
        CP_COMMIT();

        const int kb = kt * 64;
        if (kt >= 2 * qt) {
            const int rg0 = qb + rr0;
            const int rg1 = rg0 + 8;
#pragma unroll
            for (int j = 0; j < 8; ++j) {
                int c0 = kb + j * 8 + 2 * (lane & 3);
                if (c0 > rg0)     sa[j][0] = -INFINITY;
                if (c0 + 1 > rg0) sa[j][1] = -INFINITY;
                if (c0 > rg1)     sa[j][2] = -INFINITY;
                if (c0 + 1 > rg1) sa[j][3] = -INFINITY;
            }
        }
        float rmax0 = -INFINITY, rmax1 = -INFINITY;
#pragma unroll
        for (int j = 0; j < 8; ++j) {
            rmax0 = fmaxf(rmax0, fmaxf(sa[j][0], sa[j][1]));
            rmax1 = fmaxf(rmax1, fmaxf(sa[j][2], sa[j][3]));
        }
        rmax0 = fmaxf(rmax0, __shfl_xor_sync(0xffffffffu, rmax0, 1));
        rmax0 = fmaxf(rmax0, __shfl_xor_sync(0xffffffffu, rmax0, 2));
        rmax1 = fmaxf(rmax1, __shfl_xor_sync(0xffffffffu, rmax1, 1));
        rmax1 = fmaxf(rmax1, __shfl_xor_sync(0xffffffffu, rmax1, 2));

        float mn0 = fmaxf(m0, rmax0);
        float mn1 = fmaxf(m1, rmax1);
        float corr0 = __expf(m0 - mn0);
        float corr1 = __expf(m1 - mn1);
        m0 = mn0; m1 = mn1;
#pragma unroll
        for (int j = 0; j < 16; ++j) {
            oa[j][0] *= corr0; oa[j][1] *= corr0;
            oa[j][2] *= corr1; oa[j][3] *= corr1;
        }
        float rs0 = 0.0f, rs1 = 0.0f;
#pragma unroll
        for (int j = 0; j < 8; ++j) {
            float p0 = __expf(sa[j][0] - mn0);
            float p1 = __expf(sa[j][1] - mn0);
            float p2 = __expf(sa[j][2] - mn1);
            float p3 = __expf(sa[j][3] - mn1);
            rs0 += p0 + p1;
            rs1 += p2 + p3;
            int key = j * 8 + 2 * (lane & 3);
            int panel = key >> 5, kin = key & 31;
            uint32_t inoff = (uint32_t)(((kin >> 3)) << 4) + ((kin & 7) << 1);
            __half2 h2a = __float22half2_rn(make_float2(p0, p1));
            __half2 h2b = __float22half2_rn(make_float2(p2, p3));
            uint32_t ba0 = (uint32_t)(ATS_P + panel * 8192) + prow0 * 64
                         + ((inoff & 0xF0u) ^ (pswz0 << 4)) + (inoff & 0xFu);
            uint32_t ba1 = (uint32_t)(ATS_P + panel * 8192) + prow1 * 64
                         + ((inoff & 0xF0u) ^ (pswz1 << 4)) + (inoff & 0xFu);
            *(__half2*)(sm + ba0) = h2a;
            *(__half2*)(sm + ba1) = h2b;
        }
        rs0 += __shfl_xor_sync(0xffffffffu, rs0, 1);
        rs0 += __shfl_xor_sync(0xffffffffu, rs0, 2);
        rs1 += __shfl_xor_sync(0xffffffffu, rs1, 1);
        rs1 += __shfl_xor_sync(0xffffffffu, rs1, 2);
        l0 = l0 * corr0 + rs0;
        l1 = l1 * corr1 + rs1;
        __syncwarp();

        // PV: O += p_hi x v_hi
#pragma unroll
        for (int s = 0; s < 4; ++s) {
            uint32_t a0, a1, a2, a3;
            LDSM_X4(a0, a1, a2, a3,
                    sb + ATS_P + (s >> 1) * 8192 + arow * 64
                       + (((2 * (s & 1) + acp) ^ aswz) << 4));
            int vk = s * 16 + vkrow_base;
#pragma unroll
            for (int g = 0; g < 8; ++g) {
                uint32_t b0, b1, b2, b3;
                LDSM_X4T(b0, b1, b2, b3,
                         sb + ATS_VH + vk * 256
                            + ((((2 * g + (lane >> 4)) ^ (vk & 7))) << 4));
                MMA_16816_F16(oa[2 * g][0], oa[2 * g][1],
                              oa[2 * g][2], oa[2 * g][3],
                              a0, a1, a2, a3, b0, b1);
                MMA_16816_F16(oa[2 * g + 1][0], oa[2 * g + 1][1],
                              oa[2 * g + 1][2], oa[2 * g + 1][3],
                              a0, a1, a2, a3, b2, b3);
            }
        }
        __syncthreads();

        if (kt + 1 < nkt) {
            const __half* va = vh + (size_t)(kt + 1) * 64 * PHD;
#pragma unroll
            for (int ps = 0; ps < 4; ++ps) {
                int idx = tid + ps * 256;
                int rr = idx >> 4, cc = idx & 15;
                CP_ASYNC16(sb + ATS_VH + swzV(rr, cc), va + (size_t)rr * PHD + cc * 8);
            }
        }
        CP_COMMIT();
    }

    const float inv0 = 1.0f / l0;
    const float inv1 = 1.0f / l1;
    const int b = bh >> 4, h = bh & 15;
    const size_t row0 = (size_t)b * PS + qb + rr0;
    const size_t row1 = row0 + 8;
#pragma unroll
    for (int j = 0; j < 16; ++j) {
        int col = h * PHD + j * 8 + 2 * (lane & 3);
        float2 p0 = make_float2(oa[j][0] * inv0, oa[j][1] * inv0);
        float2 p1 = make_float2(oa[j][2] * inv1, oa[j][3] * inv1);
        __half2 h20 = __float22half2_rn(p0);
        __half2 h21 = __float22half2_rn(p1);
        __half2 l20 = __float22half2_rn(make_float2(
            p0.x - __half2float(__low2half(h20)),
            p0.y - __half2float(__high2half(h20))));
        __half2 l21 = __float22half2_rn(make_float2(
            p1.x - __half2float(__low2half(h21)),
            p1.y - __half2float(__high2half(h21))));
        __half* d0 = AXO + row0 * K2 + col;
        __half* d1 = AXO + row1 * K2 + col;
        *(__half2*)(d0)        = h20;
        *(__half2*)(d0 + 2048) = l20;
        *(__half2*)(d1)        = h21;
        *(__half2*)(d1 + 2048) = l21;
    }
}

// ---------------------------------------------------------------------------
// kernel_launch
// ---------------------------------------------------------------------------
extern "C" void kernel_launch(void* const* d_in, const int* in_sizes, int n_in,
                              void* d_out, int out_size)
{
    const float* x  = (const float*)d_in[0];
    const float* Wq = (const float*)d_in[1];
    const float* Wk = (const float*)d_in[2];
    const float* Wv = (const float*)d_in[3];
    const float* Wo = (const float*)d_in[4];
    float* out = (float*)d_out;

    float *Qp, *Kp;
    __half *Ax2p, *Bqkvp, *Bo2p, *AxOp, *Q2p, *K2p, *Vhp;
    cudaGetSymbolAddress((void**)&Qp,    g_Q);
    cudaGetSymbolAddress((void**)&Kp,    g_K);
    cudaGetSymbolAddress((void**)&Ax2p,  g_Ax2);
    cudaGetSymbolAddress((void**)&Bqkvp, g_Bqkv);
    cudaGetSymbolAddress((void**)&Bo2p,  g_Bo2);
    cudaGetSymbolAddress((void**)&AxOp,  g_AxO);
    cudaGetSymbolAddress((void**)&Q2p,   g_Q2h);
    cudaGetSymbolAddress((void**)&K2p,   g_K2h);
    cudaGetSymbolAddress((void**)&Vhp,   g_Vh);

    cudaFuncSetAttribute((const void*)gemm_f16<0>,
                         cudaFuncAttributeMaxDynamicSharedMemorySize, HG_SMEM);
    cudaFuncSetAttribute((const void*)gemm_f16<1>,
                         cudaFuncAttributeMaxDynamicSharedMemorySize, HG_SMEM);
    cudaFuncSetAttribute((const void*)attn_tc,
                         cudaFuncAttributeMaxDynamicSharedMemorySize, ATT_SMEM);

    const int wpairs = PD * PD / 2;
    const int xpairs = PM * PD / 2;

    // weight splits into concatenated QKV buffer + Wo; activation split
    split2<<<(wpairs + 255) / 256, 256>>>(Wq, Bqkvp,                      1, wpairs);
    split2<<<(wpairs + 255) / 256, 256>>>(Wk, Bqkvp + (size_t)2048 * K2,  1, wpairs);
    split2<<<(wpairs + 255) / 256, 256>>>(Wv, Bqkvp + (size_t)4096 * K2,  1, wpairs);
    split2<<<(wpairs + 255) / 256, 256>>>(Wo, Bo2p,                       1, wpairs);
    split2<<<(xpairs + 255) / 256, 256>>>(x,  Ax2p,                       0, xpairs);

    // fused QKV projection (N = 6144)
    gemm_f16<1><<<dim3(NQKV / 128, PM / 128), 256, HG_SMEM>>>(
        Ax2p, Bqkvp, Qp, Kp, Vhp);

    // RoPE + split (tables computed in-block)
    rope_split<<<PM, 256>>>(Qp, Kp, Q2p, K2p);

    // attention
    attn_tc<<<dim3(PS / 128, PB * PH), 256, ATT_SMEM>>>(Q2p, K2p, Vhp, AxOp);

    // Wo projection
    gemm_f16<0><<<dim3(PD / 128, PM / 128), 256, HG_SMEM>>>(
        AxOp, Bo2p, out, nullptr, nullptr);
}

// round 10
// speedup vs baseline: 2.7040x; 1.0400x over previous
#include <cuda_runtime.h>
#include <cuda_fp16.h>
#include <math.h>
#include <stdint.h>

// ---------------------------------------------------------------------------
// Problem constants
// ---------------------------------------------------------------------------
#define PB 2
#define PS 2048
#define PD 2048
#define PH 16
#define PHD 128
#define PM (PB * PS)          // 4096 rows
#define K2 (2 * PD)           // 4096: fp16 2-term split-K
#define NQKV (3 * PD)         // 6144: fused QKV output columns
#define ATT_SCALE 0.08838834764831845f

// ---------------------------------------------------------------------------
// Scratch (device globals; no allocation allowed)
// ---------------------------------------------------------------------------
__device__ __half g_Ax2[(size_t)PM * K2];                // x, fp16 [hi|lo]
__device__ __half g_Bqkv[(size_t)NQKV * K2];             // [Wq;Wk;Wv] fp16 [hi|hi]
__device__ __half g_Bo2[(size_t)PD * K2];                // Wo fp16 [hi|hi]
__device__ __half g_AxO[(size_t)PM * K2];                // attn out fp16 [hi|lo]
__device__ __half g_Q2h[(size_t)PB * PH * PS * 256];     // [qh|ql]*scale
__device__ __half g_K2h[(size_t)PB * PH * PS * 256];     // [kh|kh]
__device__ __half g_Vh[(size_t)PB * PH * PS * PHD];
__device__ float2 g_tab[PS * 64];                        // {cos, sin}

// ---------------------------------------------------------------------------
// PTX helpers (sm_80-compatible: cp.async + ldmatrix + mma.sync)
// ---------------------------------------------------------------------------
__device__ __forceinline__ uint32_t smem_u32(const void* p) {
    uint32_t a;
    asm("{ .reg .u64 t; cvta.to.shared.u64 t, %1; cvt.u32.u64 %0, t; }"
        : "=r"(a) : "l"(p));
    return a;
}

#define CP_ASYNC16(smem, gptr) \
    asm volatile("cp.async.cg.shared.global [%0], [%1], 16;" \
                 :: "r"(smem), "l"(gptr) : "memory")
#define CP_COMMIT() asm volatile("cp.async.commit_group;" ::: "memory")
#define CP_WAIT2()  asm volatile("cp.async.wait_group 2;" ::: "memory")
#define CP_WAIT0()  asm volatile("cp.async.wait_group 0;" ::: "memory")

#define LDSM_X4(r0, r1, r2, r3, addr) \
    asm volatile("ldmatrix.sync.aligned.m8n8.x4.shared.b16 {%0,%1,%2,%3}, [%4];" \
                 : "=r"(r0), "=r"(r1), "=r"(r2), "=r"(r3) : "r"(addr))
#define LDSM_X4T(r0, r1, r2, r3, addr) \
    asm volatile("ldmatrix.sync.aligned.m8n8.x4.trans.shared.b16 {%0,%1,%2,%3}, [%4];" \
                 : "=r"(r0), "=r"(r1), "=r"(r2), "=r"(r3) : "r"(addr))
#define LDSM_X2(r0, r1, addr) \
    asm volatile("ldmatrix.sync.aligned.m8n8.x2.shared.b16 {%0,%1}, [%2];" \
                 : "=r"(r0), "=r"(r1) : "r"(addr))

#define MMA_16816_F16(c0, c1, c2, c3, a0, a1, a2, a3, b0, b1) \
    asm volatile("mma.sync.aligned.m16n8k16.row.col.f32.f16.f16.f32 " \
                 "{%0,%1,%2,%3}, {%4,%5,%6,%7}, {%8,%9}, {%0,%1,%2,%3};" \
                 : "+f"(c0), "+f"(c1), "+f"(c2), "+f"(c3) \
                 : "r"(a0), "r"(a1), "r"(a2), "r"(a3), "r"(b0), "r"(b1))

// swizzles
__device__ __forceinline__ uint32_t swz64(int r, int ch) {   // 64B rows, 4x16B chunks
    return (uint32_t)(r * 64 + (((ch) ^ ((r >> 1) & 3)) << 4));
}
__device__ __forceinline__ uint32_t swzV(int r, int ch) {    // 256B rows, 16x16B chunks
    return (uint32_t)(r * 256 + (((ch) ^ (r & 7)) << 4));
}

// ---------------------------------------------------------------------------
// RoPE tables: invf = exp(-j/64 * ln(10000)) (fp64, == pow within ulps);
// angle = fp32(s) * fp32(invf) -- fp32-rounded chain matching the reference.
// ---------------------------------------------------------------------------
__global__ __launch_bounds__(256)
void rope_tables(float2* __restrict__ tab)
{
    int idx = blockIdx.x * blockDim.x + threadIdx.x;   // 131072
    int s = idx >> 6;
    int j = idx & 63;
    double invf_d = exp(-(double)j * (9.210340371976184 / 64.0));
    float ang = (float)s * (float)invf_d;
    double cs, sn;
    sincos((double)ang, &sn, &cs);
    tab[idx] = make_float2((float)cs, (float)sn);
}

// ---------------------------------------------------------------------------
// Merged splits: fp32 -> 2-segment fp16.
//   blocks [0, 16384): x -> Ax [hi|lo]
//   blocks [16384+8192*seg, ...): Wq/Wk/Wv -> Bqkv segs, Wo -> Bo  [hi|hi]
// ---------------------------------------------------------------------------
__global__ __launch_bounds__(256)
void split_all(const float* __restrict__ x,
               const float* __restrict__ Wq, const float* __restrict__ Wk,
               const float* __restrict__ Wv, const float* __restrict__ Wo,
               __half* __restrict__ Ax, __half* __restrict__ Bqkv,
               __half* __restrict__ Bo)
{
    int bid = blockIdx.x;
    const float* src;
    __half* dst;
    int order, base;
    if (bid < 16384) {
        src = x; dst = Ax; order = 0; base = 0;
    } else {
        int seg = (bid - 16384) >> 13;
        base = 16384 + seg * 8192;
        order = 1;
        if (seg == 0)      { src = Wq; dst = Bqkv; }
        else if (seg == 1) { src = Wk; dst = Bqkv + (size_t)2048 * K2; }
        else if (seg == 2) { src = Wv; dst = Bqkv + (size_t)4096 * K2; }
        else               { src = Wo; dst = Bo; }
    }
    int i = (bid - base) * 256 + threadIdx.x;   // pair index
    int r = i >> 10;
    int c = (i & 1023) << 1;
    float2 v = *(const float2*)(src + (size_t)r * PD + c);
    __half h0 = __float2half(v.x);
    __half h1 = __float2half(v.y);
    __half2 hh = __halves2half2(h0, h1);
    __half2 seg1;
    if (order) {
        seg1 = hh;
    } else {
        seg1 = __halves2half2(__float2half(v.x - __half2float(h0)),
                              __float2half(v.y - __half2float(h1)));
    }
    __half2* bp = (__half2*)(dst + (size_t)r * K2 + c);
    bp[0]    = hh;
    bp[1024] = seg1;
}

// ---------------------------------------------------------------------------
// fp16 2-term HMMA GEMM, K=4096.
//  MODE 0: Wo projection — plain fp32 C stores.
//  MODE 1: fused QKV (N=6144):
//    region 0/1 (Q/K): smem-stage fp32 tile, apply RoPE (+scale for Q),
//                      emit fp16 [hi|lo] / [hi|hi] directly to Q2/K2.
//    region 2 (V): fp16 head-gather.
// ---------------------------------------------------------------------------
#define HG_BK 32
#define HG_STG 4
#define HG_STAGE_BYTES 16384
#define HG_SMEM0 (HG_STG * HG_STAGE_BYTES)      // 65536 (MODE 0)
#define HG_PITCH 136
#define HG_SMEM1 (128 * HG_PITCH * 4)           // 69632 (MODE 1, >= 65536)
#define HG_KT (K2 / HG_BK)                      // 128

template<int MODE>
__global__ __launch_bounds__(256, 2)
void gemm_f16(const __half* __restrict__ A3, const __half* __restrict__ B3,
              float* __restrict__ C,
              __half* __restrict__ Q2o, __half* __restrict__ K2o,
              __half* __restrict__ Vho, const float2* __restrict__ tab)
{
    extern __shared__ __align__(1024) char smem[];
    const uint32_t sbase = smem_u32(smem);

    const int tid  = threadIdx.x;
    const int lane = tid & 31;
    const int wid  = tid >> 5;
    const int wm   = wid & 1;
    const int wn   = wid >> 1;
    const int bm   = blockIdx.y * 128;
    const int bn   = blockIdx.x * 128;

    const __half* Ag = A3 + (size_t)bm * K2;
    const __half* Bg = B3 + (size_t)bn * K2;

    uint32_t lsw[2];
    const __half* gA[2];
    const __half* gB[2];
#pragma unroll
    for (int p = 0; p < 2; ++p) {
        int idx = tid + p * 256;
        int r = idx >> 2, ch = idx & 3;
        lsw[p] = swz64(r, ch);
        gA[p] = Ag + (size_t)r * K2 + ch * 8;
        gB[p] = Bg + (size_t)r * K2 + ch * 8;
    }

    uint32_t a_row_off[4];
    int a_swz[4];
#pragma unroll
    for (int mi = 0; mi < 4; ++mi) {
        int r = wm * 64 + mi * 16 + (lane & 15);
        a_row_off[mi] = (uint32_t)(r * 64);
        a_swz[mi] = (r >> 1) & 3;
    }
    const int a_cpart = lane >> 4;
    uint32_t b_row_off[4];
    int b_swz[4];
#pragma unroll
    for (int nj = 0; nj < 4; ++nj) {
        int r = wn * 32 + nj * 8 + (lane & 7);
        b_row_off[nj] = (uint32_t)(r * 64);
        b_swz[nj] = (r >> 1) & 3;
    }
    const int b_cpart = (lane >> 3) & 1;

    float acc[4][4][4];
#pragma unroll
    for (int mi = 0; mi < 4; ++mi)
#pragma unroll
        for (int nj = 0; nj < 4; ++nj)
#pragma unroll
            for (int e = 0; e < 4; ++e) acc[mi][nj][e] = 0.0f;

#pragma unroll
    for (int s = 0; s < HG_STG - 1; ++s) {
        uint32_t sA = sbase + s * HG_STAGE_BYTES;
        uint32_t sB = sA + 8192;
        int k0 = s * HG_BK;
#pragma unroll
        for (int p = 0; p < 2; ++p) {
            CP_ASYNC16(sA + lsw[p], gA[p] + k0);
            CP_ASYNC16(sB + lsw[p], gB[p] + k0);
        }
        CP_COMMIT();
    }

    for (int kt = 0; kt < HG_KT; ++kt) {
        CP_WAIT2();
        __syncthreads();

        int nk = kt + HG_STG - 1;
        if (nk < HG_KT) {
            uint32_t sA = sbase + (nk & 3) * HG_STAGE_BYTES;
            uint32_t sB = sA + 8192;
            int k0 = nk * HG_BK;
#pragma unroll
            for (int p = 0; p < 2; ++p) {
                CP_ASYNC16(sA + lsw[p], gA[p] + k0);
                CP_ASYNC16(sB + lsw[p], gB[p] + k0);
            }
        }
        CP_COMMIT();

        uint32_t sA = sbase + (kt & 3) * HG_STAGE_BYTES;
        uint32_t sB = sA + 8192;
#pragma unroll
        for (int h = 0; h < 2; ++h) {
            uint32_t a0[4], a1[4], a2[4], a3[4];
#pragma unroll
            for (int mi = 0; mi < 4; ++mi) {
                uint32_t addr = sA + a_row_off[mi]
                              + (uint32_t)(((2 * h + a_cpart) ^ a_swz[mi]) << 4);
                LDSM_X4(a0[mi], a1[mi], a2[mi], a3[mi], addr);
            }
            uint32_t b0[4], b1[4];
#pragma unroll
            for (int nj = 0; nj < 4; ++nj) {
                uint32_t addr = sB + b_row_off[nj]
                              + (uint32_t)(((2 * h + b_cpart) ^ b_swz[nj]) << 4);
                LDSM_X2(b0[nj], b1[nj], addr);
            }
#pragma unroll
            for (int mi = 0; mi < 4; ++mi)
#pragma unroll
                for (int nj = 0; nj < 4; ++nj)
                    MMA_16816_F16(acc[mi][nj][0], acc[mi][nj][1],
                                  acc[mi][nj][2], acc[mi][nj][3],
                                  a0[mi], a1[mi], a2[mi], a3[mi],
                                  b0[nj], b1[nj]);
        }
        __syncthreads();
    }

    const int erow = (lane >> 2);
    const int ecol = (lane & 3) * 2;
    const int region  = (MODE == 1) ? (bn >> 11) : 0;
    const int colbase = bn - region * 2048;

    if (MODE == 0) {
#pragma unroll
        for (int mi = 0; mi < 4; ++mi)
#pragma unroll
            for (int nj = 0; nj < 4; ++nj) {
                int row = bm + wm * 64 + mi * 16 + erow;
                int col = colbase + wn * 32 + nj * 8 + ecol;
                *(float2*)(C + (size_t)row * PD + col) =
                    make_float2(acc[mi][nj][0], acc[mi][nj][1]);
                *(float2*)(C + (size_t)(row + 8) * PD + col) =
                    make_float2(acc[mi][nj][2], acc[mi][nj][3]);
            }
    } else if (region == 2) {
        // V: fp16 head-gather
#pragma unroll
        for (int mi = 0; mi < 4; ++mi)
#pragma unroll
            for (int nj = 0; nj < 4; ++nj) {
                int row = bm + wm * 64 + mi * 16 + erow;
                int col = colbase + wn * 32 + nj * 8 + ecol;
                int b = row >> 11, s = row & 2047;
                int h = col >> 7, hd = col & 127;
                size_t dst = ((size_t)(b * PH + h) * PS + s) * PHD + hd;
                *(__half2*)(Vho + dst) = __float22half2_rn(
                    make_float2(acc[mi][nj][0], acc[mi][nj][1]));
                *(__half2*)(Vho + dst + 8 * PHD) = __float22half2_rn(
                    make_float2(acc[mi][nj][2], acc[mi][nj][3]));
            }
    } else {
        // Q/K: smem stage + RoPE + fp16 split
        float* tile = (float*)smem;
#pragma unroll
        for (int mi = 0; mi < 4; ++mi)
#pragma unroll
            for (int nj = 0; nj < 4; ++nj) {
                int r = wm * 64 + mi * 16 + erow;
                int c = wn * 32 + nj * 8 + ecol;
                *(float2*)(tile + r * HG_PITCH + c) =
                    make_float2(acc[mi][nj][0], acc[mi][nj][1]);
                *(float2*)(tile + (r + 8) * HG_PITCH + c) =
                    make_float2(acc[mi][nj][2], acc[mi][nj][3]);
            }
        __syncthreads();

        const int hh = colbase >> 7;        // head (tile == one full head)
        const int b  = bm >> 11;
        const int s0 = bm & 2047;
        __half* dst = (region == 0 ? Q2o : K2o)
                    + (size_t)(b * PH + hh) * PS * 256;
        const int rg = tid >> 6;            // 4 groups x 32 rows
        const int ii = tid & 63;            // d index (and j index)
#pragma unroll 4
        for (int rr = 0; rr < 32; ++rr) {
            int r = rg * 32 + rr;
            float x0 = tile[r * HG_PITCH + ii];
            float x1 = tile[r * HG_PITCH + 64 + ii];
            int s = s0 + r;
            float2 cs = tab[s * 64 + ii];
            float o0 = x0 * cs.x - x1 * cs.y;
            float o1 = x1 * cs.x + x0 * cs.y;
            __half* o = dst + (size_t)s * 256;
            if (region == 0) {
                o0 *= ATT_SCALE;
                o1 *= ATT_SCALE;
                __half h0 = __float2half(o0), h1 = __float2half(o1);
                o[ii]       = h0;
                o[64 + ii]  = h1;
                o[128 + ii] = __float2half(o0 - __half2float(h0));
                o[192 + ii] = __float2half(o1 - __half2float(h1));
            } else {
                __half h0 = __float2half(o0), h1 = __float2half(o1);
                o[ii]       = h0;
                o[64 + ii]  = h1;
                o[128 + ii] = h0;
                o[192 + ii] = h1;
            }
        }
    }
}

// ---------------------------------------------------------------------------
// Tensor-core causal flash attention (fp16): QK 2-term (K'=256),
// PV single term (p_hi x v_hi). Output -> fp16 [hi|lo] for Wo GEMM.
// (Validated round-7/8/9 body.)
// ---------------------------------------------------------------------------
#define ATS_Q  0
#define ATS_K  65536
#define ATS_VH 98304
#define ATS_P  114688
#define ATT_SMEM 131072

__global__ __launch_bounds__(256, 1)
void attn_tc(const __half* __restrict__ Q2,
             const __half* __restrict__ K2g,
             const __half* __restrict__ Vh,
             __half* __restrict__ AXO)
{
    extern __shared__ __align__(1024) char sm[];
    const uint32_t sb = smem_u32(sm);
    const int tid  = threadIdx.x;
    const int lane = tid & 31;
    const int w    = tid >> 5;
    const int qt   = 15 - (int)blockIdx.x;
    const int bh   = blockIdx.y;
    const int qb   = qt * 128;
    const int nkt  = 2 * qt + 2;

    const __half* q2 = Q2 + ((size_t)bh * PS + qb) * 256;
    const __half* k2 = K2g + (size_t)bh * PS * 256;
    const __half* vh = Vh + (size_t)bh * PS * PHD;

#pragma unroll
    for (int p = 0; p < 8; ++p)
#pragma unroll
        for (int ps = 0; ps < 2; ++ps) {
            int idx = tid + ps * 256;
            int r = idx >> 2, ch = idx & 3;
            CP_ASYNC16(sb + ATS_Q + p * 8192 + swz64(r, ch),
                       q2 + (size_t)r * 256 + p * 32 + ch * 8);
        }
    {
        int r = tid >> 2, ch = tid & 3;
#pragma unroll
        for (int p = 0; p < 8; ++p)
            CP_ASYNC16(sb + ATS_K + p * 4096 + swz64(r, ch),
                       k2 + (size_t)r * 256 + p * 32 + ch * 8);
#pragma unroll
        for (int ps = 0; ps < 4; ++ps) {
            int idx = tid + ps * 256;
            int rr = idx >> 4, cc = idx & 15;
            CP_ASYNC16(sb + ATS_VH + swzV(rr, cc), vh + (size_t)rr * PHD + cc * 8);
        }
    }
    CP_COMMIT();

    float m0 = -INFINITY, m1 = -INFINITY, l0 = 0.0f, l1 = 0.0f;
    float oa[16][4];
#pragma unroll
    for (int j = 0; j < 16; ++j)
#pragma unroll
        for (int e = 0; e < 4; ++e) oa[j][e] = 0.0f;

    const int arow  = w * 16 + (lane & 15);
    const int aswz  = (arow >> 1) & 3;
    const int acp   = lane >> 4;
    const int rr0   = w * 16 + (lane >> 2);
    const int prow0 = rr0;
    const int prow1 = rr0 + 8;
    const int pswz0 = (prow0 >> 1) & 3;
    const int pswz1 = (prow1 >> 1) & 3;
    const int vkrow_base = (lane & 7) + 8 * ((lane >> 3) & 1);

    for (int kt = 0; kt < nkt; ++kt) {
        CP_WAIT0();
        __syncthreads();

        float sa[8][4];
#pragma unroll
        for (int j = 0; j < 8; ++j)
#pragma unroll
            for (int e = 0; e < 4; ++e) sa[j][e] = 0.0f;

#pragma unroll
        for (int p = 0; p < 8; ++p) {
#pragma unroll
            for (int h = 0; h < 2; ++h) {
                uint32_t a0, a1, a2, a3;
                LDSM_X4(a0, a1, a2, a3,
                        sb + ATS_Q + p * 8192 + arow * 64
                           + (((2 * h + acp) ^ aswz) << 4));
#pragma unroll
                for (int jj = 0; jj < 4; ++jj) {
                    int brow = jj * 16 + (lane & 15);
                    uint32_t b0, b1, b2, b3;
                    LDSM_X4(b0, b1, b2, b3,
                            sb + ATS_K + p * 4096 + brow * 64
                               + (((2 * h + acp) ^ ((brow >> 1) & 3)) << 4));
                    MMA_16816_F16(sa[2 * jj][0], sa[2 * jj][1],
                                  sa[2 * jj][2], sa[2 * jj][3],
                                  a0, a1, a2, a3, b0, b2);
                    MMA_16816_F16(sa[2 * jj + 1][0], sa[2 * jj + 1][1],
                                  sa[2 * jj + 1][2], sa[2 * jj + 1][3],
                                  a0, a1, a2, a3, b1, b3);
                }
            }
        }
        __syncthreads();

        if (kt + 1 < nkt) {
            const __half* kp = k2 + (size_t)(kt + 1) * 64 * 256;
            int r = tid >> 2, ch = tid & 3;
#pragma unroll
            for (int p = 0; p < 8; ++p)
                CP_ASYNC16(sb + ATS_K + p * 4096 + swz64(r, ch),
                           kp + (size_t)r * 256 + p * 32 + ch * 8);
        }
        CP_COMMIT();

        const int kb = kt * 64;
        if (kt >= 2 * qt) {
            const int rg0 = qb + rr0;
            const int rg1 = rg0 + 8;
#pragma unroll
            for (int j = 0; j < 8; ++j) {
                int c0 = kb + j * 8 + 2 * (lane & 3);
                if (c0 > rg0)     sa[j][0] = -INFINITY;
                if (c0 + 1 > rg0) sa[j][1] = -INFINITY;
                if (c0 > rg1)     sa[j][2] = -INFINITY;
                if (c0 + 1 > rg1) sa[j][3] = -INFINITY;
            }
        }
        float rmax0 = -INFINITY, rmax1 = -INFINITY;
#pragma unroll
        for (int j = 0; j < 8; ++j) {
            rmax0 = fmaxf(rmax0, fmaxf(sa[j][0], sa[j][1]));
            rmax1 = fmaxf(rmax1, fmaxf(sa[j][2], sa[j][3]));
        }
        rmax0 = fmaxf(rmax0, __shfl_xor_sync(0xffffffffu, rmax0, 1));
        rmax0 = fmaxf(rmax0, __shfl_xor_sync(0xffffffffu, rmax0, 2));
        rmax1 = fmaxf(rmax1, __shfl_xor_sync(0xffffffffu, rmax1, 1));
        rmax1 = fmaxf(rmax1, __shfl_xor_sync(0xffffffffu, rmax1, 2));

        float mn0 = fmaxf(m0, rmax0);
        float mn1 = fmaxf(m1, rmax1);
        float corr0 = __expf(m0 - mn0);
        float corr1 = __expf(m1 - mn1);
        m0 = mn0; m1 = mn1;
#pragma unroll
        for (int j = 0; j < 16; ++j) {
            oa[j][0] *= corr0; oa[j][1] *= corr0;
            oa[j][2] *= corr1; oa[j][3] *= corr1;
        }
        float rs0 = 0.0f, rs1 = 0.0f;
#pragma unroll
        for (int j = 0; j < 8; ++j) {
            float p0 = __expf(sa[j][0] - mn0);
            float p1 = __expf(sa[j][1] - mn0);
            float p2 = __expf(sa[j][2] - mn1);
            float p3 = __expf(sa[j][3] - mn1);
            rs0 += p0 + p1;
            rs1 += p2 + p3;
            int key = j * 8 + 2 * (lane & 3);
            int panel = key >> 5, kin = key & 31;
            uint32_t inoff = (uint32_t)(((kin >> 3)) << 4) + ((kin & 7) << 1);
            __half2 h2a = __float22half2_rn(make_float2(p0, p1));
            __half2 h2b = __float22half2_rn(make_float2(p2, p3));
            uint32_t ba0 = (uint32_t)(ATS_P + panel * 8192) + prow0 * 64
                         + ((inoff & 0xF0u) ^ (pswz0 << 4)) + (inoff & 0xFu);
            uint32_t ba1 = (uint32_t)(ATS_P + panel * 8192) + prow1 * 64
                         + ((inoff & 0xF0u) ^ (pswz1 << 4)) + (inoff & 0xFu);
            *(__half2*)(sm + ba0) = h2a;
            *(__half2*)(sm + ba1) = h2b;
        }
        rs0 += __shfl_xor_sync(0xffffffffu, rs0, 1);
        rs0 += __shfl_xor_sync(0xffffffffu, rs0, 2);
        rs1 += __shfl_xor_sync(0xffffffffu, rs1, 1);
        rs1 += __shfl_xor_sync(0xffffffffu, rs1, 2);
        l0 = l0 * corr0 + rs0;
        l1 = l1 * corr1 + rs1;
        __syncwarp();

        // PV: O += p_hi x v_hi
#pragma unroll
        for (int s = 0; s < 4; ++s) {
            uint32_t a0, a1, a2, a3;
            LDSM_X4(a0, a1, a2, a3,
                    sb + ATS_P + (s >> 1) * 8192 + arow * 64
                       + (((2 * (s & 1) + acp) ^ aswz) << 4));
            int vk = s * 16 + vkrow_base;
#pragma unroll
            for (int g = 0; g < 8; ++g) {
                uint32_t b0, b1, b2, b3;
                LDSM_X4T(b0, b1, b2, b3,
                         sb + ATS_VH + vk * 256
                            + ((((2 * g + (lane >> 4)) ^ (vk & 7))) << 4));
                MMA_16816_F16(oa[2 * g][0], oa[2 * g][1],
                              oa[2 * g][2], oa[2 * g][3],
                              a0, a1, a2, a3, b0, b1);
                MMA_16816_F16(oa[2 * g + 1][0], oa[2 * g + 1][1],
                              oa[2 * g + 1][2], oa[2 * g + 1][3],
                              a0, a1, a2, a3, b2, b3);
            }
        }
        __syncthreads();

        if (kt + 1 < nkt) {
            const __half* va = vh + (size_t)(kt + 1) * 64 * PHD;
#pragma unroll
            for (int ps = 0; ps < 4; ++ps) {
                int idx = tid + ps * 256;
                int rr = idx >> 4, cc = idx & 15;
                CP_ASYNC16(sb + ATS_VH + swzV(rr, cc), va + (size_t)rr * PHD + cc * 8);
            }
        }
        CP_COMMIT();
    }

    const float inv0 = 1.0f / l0;
    const float inv1 = 1.0f / l1;
    const int b = bh >> 4, h = bh & 15;
    const size_t row0 = (size_t)b * PS + qb + rr0;
    const size_t row1 = row0 + 8;
#pragma unroll
    for (int j = 0; j < 16; ++j) {
        int col = h * PHD + j * 8 + 2 * (lane & 3);
        float2 p0 = make_float2(oa[j][0] * inv0, oa[j][1] * inv0);
        float2 p1 = make_float2(oa[j][2] * inv1, oa[j][3] * inv1);
        __half2 h20 = __float22half2_rn(p0);
        __half2 h21 = __float22half2_rn(p1);
        __half2 l20 = __float22half2_rn(make_float2(
            p0.x - __half2float(__low2half(h20)),
            p0.y - __half2float(__high2half(h20))));
        __half2 l21 = __float22half2_rn(make_float2(
            p1.x - __half2float(__low2half(h21)),
            p1.y - __half2float(__high2half(h21))));
        __half* d0 = AXO + row0 * K2 + col;
        __half* d1 = AXO + row1 * K2 + col;
        *(__half2*)(d0)        = h20;
        *(__half2*)(d0 + 2048) = l20;
        *(__half2*)(d1)        = h21;
        *(__half2*)(d1 + 2048) = l21;
    }
}

// ---------------------------------------------------------------------------
// kernel_launch
// ---------------------------------------------------------------------------
extern "C" void kernel_launch(void* const* d_in, const int* in_sizes, int n_in,
                              void* d_out, int out_size)
{
    const float* x  = (const float*)d_in[0];
    const float* Wq = (const float*)d_in[1];
    const float* Wk = (const float*)d_in[2];
    const float* Wv = (const float*)d_in[3];
    const float* Wo = (const float*)d_in[4];
    float* out = (float*)d_out;

    __half *Ax2p, *Bqkvp, *Bo2p, *AxOp, *Q2p, *K2p, *Vhp;
    float2* tabp;
    cudaGetSymbolAddress((void**)&Ax2p,  g_Ax2);
    cudaGetSymbolAddress((void**)&Bqkvp, g_Bqkv);
    cudaGetSymbolAddress((void**)&Bo2p,  g_Bo2);
    cudaGetSymbolAddress((void**)&AxOp,  g_AxO);
    cudaGetSymbolAddress((void**)&Q2p,   g_Q2h);
    cudaGetSymbolAddress((void**)&K2p,   g_K2h);
    cudaGetSymbolAddress((void**)&Vhp,   g_Vh);
    cudaGetSymbolAddress((void**)&tabp,  g_tab);

    cudaFuncSetAttribute((const void*)gemm_f16<0>,
                         cudaFuncAttributeMaxDynamicSharedMemorySize, HG_SMEM0);
    cudaFuncSetAttribute((const void*)gemm_f16<1>,
                         cudaFuncAttributeMaxDynamicSharedMemorySize, HG_SMEM1);
    cudaFuncSetAttribute((const void*)attn_tc,
                         cudaFuncAttributeMaxDynamicSharedMemorySize, ATT_SMEM);

    // RoPE tables + all splits
    rope_tables<<<512, 256>>>(tabp);
    split_all<<<16384 + 4 * 8192, 256>>>(x, Wq, Wk, Wv, Wo, Ax2p, Bqkvp, Bo2p);

    // fused QKV projection (N = 6144) with RoPE/split epilogue
    gemm_f16<1><<<dim3(NQKV / 128, PM / 128), 256, HG_SMEM1>>>(
        Ax2p, Bqkvp, nullptr, Q2p, K2p, Vhp, tabp);

    // attention
    attn_tc<<<dim3(PS / 128, PB * PH), 256, ATT_SMEM>>>(Q2p, K2p, Vhp, AxOp);

    // Wo projection
    gemm_f16<0><<<dim3(PD / 128, PM / 128), 256, HG_SMEM0>>>(
        AxOp, Bo2p, out, nullptr, nullptr, nullptr, nullptr);
}

// round 11
// speedup vs baseline: 2.7670x; 1.0233x over previous
#include <cuda_runtime.h>
#include <cuda_fp16.h>
#include <math.h>
#include <stdint.h>

// ---------------------------------------------------------------------------
// Problem constants
// ---------------------------------------------------------------------------
#define PB 2
#define PS 2048
#define PD 2048
#define PH 16
#define PHD 128
#define PM (PB * PS)          // 4096 rows
#define K2 (2 * PD)           // 4096: fp16 2-term split-K
#define NQKV (3 * PD)         // 6144: fused QKV output columns
#define ATT_SCALE 0.08838834764831845f

// ---------------------------------------------------------------------------
// Scratch (device globals; no allocation allowed)
// ---------------------------------------------------------------------------
__device__ __half g_Ax2[(size_t)PM * K2];                // x, fp16 [hi|lo]
__device__ __half g_Bqkv[(size_t)NQKV * K2];             // [Wq;Wk;Wv] fp16 [hi|hi]
__device__ __half g_Bo2[(size_t)PD * K2];                // Wo fp16 [hi|hi]
__device__ __half g_AxO[(size_t)PM * K2];                // attn out fp16 [hi|lo]
__device__ __half g_Q2h[(size_t)PB * PH * PS * 256];     // [qh|ql]*scale
__device__ __half g_K2h[(size_t)PB * PH * PS * 256];     // [kh|kh]
__device__ __half g_Vh[(size_t)PB * PH * PS * PHD];
__device__ float2 g_tab[PS * 64];                        // {cos, sin}

// ---------------------------------------------------------------------------
// PTX helpers (sm_80-compatible: cp.async + ldmatrix + mma.sync)
// ---------------------------------------------------------------------------
__device__ __forceinline__ uint32_t smem_u32(const void* p) {
    uint32_t a;
    asm("{ .reg .u64 t; cvta.to.shared.u64 t, %1; cvt.u32.u64 %0, t; }"
        : "=r"(a) : "l"(p));
    return a;
}

#define CP_ASYNC16(smem, gptr) \
    asm volatile("cp.async.cg.shared.global [%0], [%1], 16;" \
                 :: "r"(smem), "l"(gptr) : "memory")
#define CP_COMMIT() asm volatile("cp.async.commit_group;" ::: "memory")
#define CP_WAIT2()  asm volatile("cp.async.wait_group 2;" ::: "memory")
#define CP_WAIT0()  asm volatile("cp.async.wait_group 0;" ::: "memory")

#define LDSM_X4(r0, r1, r2, r3, addr) \
    asm volatile("ldmatrix.sync.aligned.m8n8.x4.shared.b16 {%0,%1,%2,%3}, [%4];" \
                 : "=r"(r0), "=r"(r1), "=r"(r2), "=r"(r3) : "r"(addr))
#define LDSM_X4T(r0, r1, r2, r3, addr) \
    asm volatile("ldmatrix.sync.aligned.m8n8.x4.trans.shared.b16 {%0,%1,%2,%3}, [%4];" \
                 : "=r"(r0), "=r"(r1), "=r"(r2), "=r"(r3) : "r"(addr))
#define LDSM_X2(r0, r1, addr) \
    asm volatile("ldmatrix.sync.aligned.m8n8.x2.shared.b16 {%0,%1}, [%2];" \
                 : "=r"(r0), "=r"(r1) : "r"(addr))

#define MMA_16816_F16(c0, c1, c2, c3, a0, a1, a2, a3, b0, b1) \
    asm volatile("mma.sync.aligned.m16n8k16.row.col.f32.f16.f16.f32 " \
                 "{%0,%1,%2,%3}, {%4,%5,%6,%7}, {%8,%9}, {%0,%1,%2,%3};" \
                 : "+f"(c0), "+f"(c1), "+f"(c2), "+f"(c3) \
                 : "r"(a0), "r"(a1), "r"(a2), "r"(a3), "r"(b0), "r"(b1))

// swizzles
__device__ __forceinline__ uint32_t swz64(int r, int ch) {   // 64B rows, 4x16B chunks
    return (uint32_t)(r * 64 + (((ch) ^ ((r >> 1) & 3)) << 4));
}
__device__ __forceinline__ uint32_t swzV(int r, int ch) {    // 256B rows, 16x16B chunks
    return (uint32_t)(r * 256 + (((ch) ^ (r & 7)) << 4));
}

// ---------------------------------------------------------------------------
// RoPE tables: invf = exp(-j/64 * ln(10000)) (fp64); angle fp32-rounded chain.
// ---------------------------------------------------------------------------
__global__ __launch_bounds__(256)
void rope_tables(float2* __restrict__ tab)
{
    int idx = blockIdx.x * blockDim.x + threadIdx.x;   // 131072
    int s = idx >> 6;
    int j = idx & 63;
    double invf_d = exp(-(double)j * (9.210340371976184 / 64.0));
    float ang = (float)s * (float)invf_d;
    double cs, sn;
    sincos((double)ang, &sn, &cs);
    tab[idx] = make_float2((float)cs, (float)sn);
}

// ---------------------------------------------------------------------------
// Merged splits: fp32 -> 2-segment fp16.
// ---------------------------------------------------------------------------
__global__ __launch_bounds__(256)
void split_all(const float* __restrict__ x,
               const float* __restrict__ Wq, const float* __restrict__ Wk,
               const float* __restrict__ Wv, const float* __restrict__ Wo,
               __half* __restrict__ Ax, __half* __restrict__ Bqkv,
               __half* __restrict__ Bo)
{
    int bid = blockIdx.x;
    const float* src;
    __half* dst;
    int order, base;
    if (bid < 16384) {
        src = x; dst = Ax; order = 0; base = 0;
    } else {
        int seg = (bid - 16384) >> 13;
        base = 16384 + seg * 8192;
        order = 1;
        if (seg == 0)      { src = Wq; dst = Bqkv; }
        else if (seg == 1) { src = Wk; dst = Bqkv + (size_t)2048 * K2; }
        else if (seg == 2) { src = Wv; dst = Bqkv + (size_t)4096 * K2; }
        else               { src = Wo; dst = Bo; }
    }
    int i = (bid - base) * 256 + threadIdx.x;
    int r = i >> 10;
    int c = (i & 1023) << 1;
    float2 v = *(const float2*)(src + (size_t)r * PD + c);
    __half h0 = __float2half(v.x);
    __half h1 = __float2half(v.y);
    __half2 hh = __halves2half2(h0, h1);
    __half2 seg1;
    if (order) {
        seg1 = hh;
    } else {
        seg1 = __halves2half2(__float2half(v.x - __half2float(h0)),
                              __float2half(v.y - __half2float(h1)));
    }
    __half2* bp = (__half2*)(dst + (size_t)r * K2 + c);
    bp[0]    = hh;
    bp[1024] = seg1;
}

// ---------------------------------------------------------------------------
// fp16 2-term HMMA GEMM, K=4096 (proven round-10 body).
// ---------------------------------------------------------------------------
#define HG_BK 32
#define HG_STG 4
#define HG_STAGE_BYTES 16384
#define HG_SMEM0 (HG_STG * HG_STAGE_BYTES)      // 65536 (MODE 0)
#define HG_PITCH 136
#define HG_SMEM1 (128 * HG_PITCH * 4)           // 69632 (MODE 1)
#define HG_KT (K2 / HG_BK)                      // 128

template<int MODE>
__global__ __launch_bounds__(256, 2)
void gemm_f16(const __half* __restrict__ A3, const __half* __restrict__ B3,
              float* __restrict__ C,
              __half* __restrict__ Q2o, __half* __restrict__ K2o,
              __half* __restrict__ Vho, const float2* __restrict__ tab)
{
    extern __shared__ __align__(1024) char smem[];
    const uint32_t sbase = smem_u32(smem);

    const int tid  = threadIdx.x;
    const int lane = tid & 31;
    const int wid  = tid >> 5;
    const int wm   = wid & 1;
    const int wn   = wid >> 1;
    const int bm   = blockIdx.y * 128;
    const int bn   = blockIdx.x * 128;

    const __half* Ag = A3 + (size_t)bm * K2;
    const __half* Bg = B3 + (size_t)bn * K2;

    uint32_t lsw[2];
    const __half* gA[2];
    const __half* gB[2];
#pragma unroll
    for (int p = 0; p < 2; ++p) {
        int idx = tid + p * 256;
        int r = idx >> 2, ch = idx & 3;
        lsw[p] = swz64(r, ch);
        gA[p] = Ag + (size_t)r * K2 + ch * 8;
        gB[p] = Bg + (size_t)r * K2 + ch * 8;
    }

    uint32_t a_row_off[4];
    int a_swz[4];
#pragma unroll
    for (int mi = 0; mi < 4; ++mi) {
        int r = wm * 64 + mi * 16 + (lane & 15);
        a_row_off[mi] = (uint32_t)(r * 64);
        a_swz[mi] = (r >> 1) & 3;
    }
    const int a_cpart = lane >> 4;
    uint32_t b_row_off[4];
    int b_swz[4];
#pragma unroll
    for (int nj = 0; nj < 4; ++nj) {
        int r = wn * 32 + nj * 8 + (lane & 7);
        b_row_off[nj] = (uint32_t)(r * 64);
        b_swz[nj] = (r >> 1) & 3;
    }
    const int b_cpart = (lane >> 3) & 1;

    float acc[4][4][4];
#pragma unroll
    for (int mi = 0; mi < 4; ++mi)
#pragma unroll
        for (int nj = 0; nj < 4; ++nj)
#pragma unroll
            for (int e = 0; e < 4; ++e) acc[mi][nj][e] = 0.0f;

#pragma unroll
    for (int s = 0; s < HG_STG - 1; ++s) {
        uint32_t sA = sbase + s * HG_STAGE_BYTES;
        uint32_t sB = sA + 8192;
        int k0 = s * HG_BK;
#pragma unroll
        for (int p = 0; p < 2; ++p) {
            CP_ASYNC16(sA + lsw[p], gA[p] + k0);
            CP_ASYNC16(sB + lsw[p], gB[p] + k0);
        }
        CP_COMMIT();
    }

    for (int kt = 0; kt < HG_KT; ++kt) {
        CP_WAIT2();
        __syncthreads();

        int nk = kt + HG_STG - 1;
        if (nk < HG_KT) {
            uint32_t sA = sbase + (nk & 3) * HG_STAGE_BYTES;
            uint32_t sB = sA + 8192;
            int k0 = nk * HG_BK;
#pragma unroll
            for (int p = 0; p < 2; ++p) {
                CP_ASYNC16(sA + lsw[p], gA[p] + k0);
                CP_ASYNC16(sB + lsw[p], gB[p] + k0);
            }
        }
        CP_COMMIT();

        uint32_t sA = sbase + (kt & 3) * HG_STAGE_BYTES;
        uint32_t sB = sA + 8192;
#pragma unroll
        for (int h = 0; h < 2; ++h) {
            uint32_t a0[4], a1[4], a2[4], a3[4];
#pragma unroll
            for (int mi = 0; mi < 4; ++mi) {
                uint32_t addr = sA + a_row_off[mi]
                              + (uint32_t)(((2 * h + a_cpart) ^ a_swz[mi]) << 4);
                LDSM_X4(a0[mi], a1[mi], a2[mi], a3[mi], addr);
            }
            uint32_t b0[4], b1[4];
#pragma unroll
            for (int nj = 0; nj < 4; ++nj) {
                uint32_t addr = sB + b_row_off[nj]
                              + (uint32_t)(((2 * h + b_cpart) ^ b_swz[nj]) << 4);
                LDSM_X2(b0[nj], b1[nj], addr);
            }
#pragma unroll
            for (int mi = 0; mi < 4; ++mi)
#pragma unroll
                for (int nj = 0; nj < 4; ++nj)
                    MMA_16816_F16(acc[mi][nj][0], acc[mi][nj][1],
                                  acc[mi][nj][2], acc[mi][nj][3],
                                  a0[mi], a1[mi], a2[mi], a3[mi],
                                  b0[nj], b1[nj]);
        }
        __syncthreads();
    }

    const int erow = (lane >> 2);
    const int ecol = (lane & 3) * 2;
    const int region  = (MODE == 1) ? (bn >> 11) : 0;
    const int colbase = bn - region * 2048;

    if (MODE == 0) {
#pragma unroll
        for (int mi = 0; mi < 4; ++mi)
#pragma unroll
            for (int nj = 0; nj < 4; ++nj) {
                int row = bm + wm * 64 + mi * 16 + erow;
                int col = colbase + wn * 32 + nj * 8 + ecol;
                *(float2*)(C + (size_t)row * PD + col) =
                    make_float2(acc[mi][nj][0], acc[mi][nj][1]);
                *(float2*)(C + (size_t)(row + 8) * PD + col) =
                    make_float2(acc[mi][nj][2], acc[mi][nj][3]);
            }
    } else if (region == 2) {
#pragma unroll
        for (int mi = 0; mi < 4; ++mi)
#pragma unroll
            for (int nj = 0; nj < 4; ++nj) {
                int row = bm + wm * 64 + mi * 16 + erow;
                int col = colbase + wn * 32 + nj * 8 + ecol;
                int b = row >> 11, s = row & 2047;
                int h = col >> 7, hd = col & 127;
                size_t dst = ((size_t)(b * PH + h) * PS + s) * PHD + hd;
                *(__half2*)(Vho + dst) = __float22half2_rn(
                    make_float2(acc[mi][nj][0], acc[mi][nj][1]));
                *(__half2*)(Vho + dst + 8 * PHD) = __float22half2_rn(
                    make_float2(acc[mi][nj][2], acc[mi][nj][3]));
            }
    } else {
        float* tile = (float*)smem;
#pragma unroll
        for (int mi = 0; mi < 4; ++mi)
#pragma unroll
            for (int nj = 0; nj < 4; ++nj) {
                int r = wm * 64 + mi * 16 + erow;
                int c = wn * 32 + nj * 8 + ecol;
                *(float2*)(tile + r * HG_PITCH + c) =
                    make_float2(acc[mi][nj][0], acc[mi][nj][1]);
                *(float2*)(tile + (r + 8) * HG_PITCH + c) =
                    make_float2(acc[mi][nj][2], acc[mi][nj][3]);
            }
        __syncthreads();

        const int hh = colbase >> 7;
        const int b  = bm >> 11;
        const int s0 = bm & 2047;
        __half* dst = (region == 0 ? Q2o : K2o)
                    + (size_t)(b * PH + hh) * PS * 256;
        const int rg = tid >> 6;
        const int ii = tid & 63;
#pragma unroll 4
        for (int rr = 0; rr < 32; ++rr) {
            int r = rg * 32 + rr;
            float x0 = tile[r * HG_PITCH + ii];
            float x1 = tile[r * HG_PITCH + 64 + ii];
            int s = s0 + r;
            float2 cs = tab[s * 64 + ii];
            float o0 = x0 * cs.x - x1 * cs.y;
            float o1 = x1 * cs.x + x0 * cs.y;
            __half* o = dst + (size_t)s * 256;
            if (region == 0) {
                o0 *= ATT_SCALE;
                o1 *= ATT_SCALE;
                __half h0 = __float2half(o0), h1 = __float2half(o1);
                o[ii]       = h0;
                o[64 + ii]  = h1;
                o[128 + ii] = __float2half(o0 - __half2float(h0));
                o[192 + ii] = __float2half(o1 - __half2float(h1));
            } else {
                __half h0 = __float2half(o0), h1 = __float2half(o1);
                o[ii]       = h0;
                o[64 + ii]  = h1;
                o[128 + ii] = h0;
                o[192 + ii] = h1;
            }
        }
    }
}

// ---------------------------------------------------------------------------
// Tensor-core causal flash attention, 64q x 64k tiles, 2 CTAs/SM.
// 8 warps = 4 row-groups x 2 col-groups. QK: K'=256 2-term. PV: p_hi x v_hi.
// Cross-warp row max/sum via smem reduction buffers.
// ---------------------------------------------------------------------------
#define BTS_Q  0          // 8 panels x 4096 = 32768
#define BTS_K  32768      // 8 panels x 4096 = 32768
#define BTS_V  65536      // 16384
#define BTS_P  81920      // 2 panels x 4096 = 8192
#define BTS_R0 90112      // 512 B (rowmax partials: 2 x 64 floats)
#define BTS_R1 90624      // 512 B (rowsum partials)
#define ATT_SMEM 92160

__global__ __launch_bounds__(256, 2)
void attn_tc(const __half* __restrict__ Q2,
             const __half* __restrict__ K2g,
             const __half* __restrict__ Vh,
             __half* __restrict__ AXO)
{
    extern __shared__ __align__(1024) char sm[];
    const uint32_t sb = smem_u32(sm);
    float* red0 = (float*)(sm + BTS_R0);
    float* red1 = (float*)(sm + BTS_R1);

    const int tid  = threadIdx.x;
    const int lane = tid & 31;
    const int w    = tid >> 5;
    const int rg   = w & 3;            // row group (16 rows)
    const int cg   = w >> 2;           // QK key half / PV col half
    const int qt   = 31 - (int)blockIdx.x;   // long tiles first
    const int bh   = blockIdx.y;
    const int qb   = qt * 64;
    const int nkt  = qt + 1;

    const __half* q2 = Q2 + ((size_t)bh * PS + qb) * 256;
    const __half* k2 = K2g + (size_t)bh * PS * 256;
    const __half* vh = Vh + (size_t)bh * PS * PHD;

    // ---- Q tile (64 x 256), K0, V0
    {
        int r = tid >> 2, ch = tid & 3;
        uint32_t sw = swz64(r, ch);
#pragma unroll
        for (int p = 0; p < 8; ++p)
            CP_ASYNC16(sb + BTS_Q + p * 4096 + sw,
                       q2 + (size_t)r * 256 + p * 32 + ch * 8);
#pragma unroll
        for (int p = 0; p < 8; ++p)
            CP_ASYNC16(sb + BTS_K + p * 4096 + sw,
                       k2 + (size_t)r * 256 + p * 32 + ch * 8);
#pragma unroll
        for (int ps = 0; ps < 4; ++ps) {
            int idx = tid + ps * 256;
            int rr = idx >> 4, cc = idx & 15;
            CP_ASYNC16(sb + BTS_V + swzV(rr, cc), vh + (size_t)rr * PHD + cc * 8);
        }
    }
    CP_COMMIT();

    float m0 = -INFINITY, m1 = -INFINITY, l0 = 0.0f, l1 = 0.0f;
    float oa[8][4];
#pragma unroll
    for (int j = 0; j < 8; ++j)
#pragma unroll
        for (int e = 0; e < 4; ++e) oa[j][e] = 0.0f;

    const int arow  = rg * 16 + (lane & 15);
    const int aswz  = (arow >> 1) & 3;
    const int acp   = lane >> 4;
    const int r0    = rg * 16 + (lane >> 2);    // local row (c0/c1)
    const int prow0 = r0;
    const int prow1 = r0 + 8;
    const int pswz0 = (prow0 >> 1) & 3;
    const int pswz1 = (prow1 >> 1) & 3;
    const int vkb   = (lane & 7) + 8 * ((lane >> 3) & 1);

    for (int kt = 0; kt < nkt; ++kt) {
        CP_WAIT0();
        __syncthreads();

        // ---- QK: warp computes S[16 x 32] over K'=256
        float sa[4][4];
#pragma unroll
        for (int j = 0; j < 4; ++j)
#pragma unroll
            for (int e = 0; e < 4; ++e) sa[j][e] = 0.0f;

#pragma unroll
        for (int p = 0; p < 8; ++p) {
#pragma unroll
            for (int h = 0; h < 2; ++h) {
                uint32_t a0, a1, a2, a3;
                LDSM_X4(a0, a1, a2, a3,
                        sb + BTS_Q + p * 4096 + arow * 64
                           + (((2 * h + acp) ^ aswz) << 4));
#pragma unroll
                for (int jj = 0; jj < 2; ++jj) {
                    int brow = cg * 32 + jj * 16 + (lane & 15);
                    uint32_t b0, b1, b2, b3;
                    LDSM_X4(b0, b1, b2, b3,
                            sb + BTS_K + p * 4096 + brow * 64
                               + (((2 * h + acp) ^ ((brow >> 1) & 3)) << 4));
                    MMA_16816_F16(sa[2 * jj][0], sa[2 * jj][1],
                                  sa[2 * jj][2], sa[2 * jj][3],
                                  a0, a1, a2, a3, b0, b2);
                    MMA_16816_F16(sa[2 * jj + 1][0], sa[2 * jj + 1][1],
                                  sa[2 * jj + 1][2], sa[2 * jj + 1][3],
                                  a0, a1, a2, a3, b1, b3);
                }
            }
        }
        __syncthreads();

        // prefetch next K
        if (kt + 1 < nkt) {
            const __half* kp = k2 + (size_t)(kt + 1) * 64 * 256;
            int r = tid >> 2, ch = tid & 3;
            uint32_t sw = swz64(r, ch);
#pragma unroll
            for (int p = 0; p < 8; ++p)
                CP_ASYNC16(sb + BTS_K + p * 4096 + sw,
                           kp + (size_t)r * 256 + p * 32 + ch * 8);
        }
        CP_COMMIT();

        // ---- causal mask (diagonal tile only)
        if (kt == qt) {
            const int gr0 = qb + r0;
            const int gr1 = gr0 + 8;
            const int kb = kt * 64;
#pragma unroll
            for (int nj = 0; nj < 4; ++nj) {
                int c0 = kb + cg * 32 + nj * 8 + 2 * (lane & 3);
                if (c0 > gr0)     sa[nj][0] = -INFINITY;
                if (c0 + 1 > gr0) sa[nj][1] = -INFINITY;
                if (c0 > gr1)     sa[nj][2] = -INFINITY;
                if (c0 + 1 > gr1) sa[nj][3] = -INFINITY;
            }
        }

        // ---- row max: intra-quad + cross-warp (cg halves) via smem
        float pm0 = -INFINITY, pm1 = -INFINITY;
#pragma unroll
        for (int nj = 0; nj < 4; ++nj) {
            pm0 = fmaxf(pm0, fmaxf(sa[nj][0], sa[nj][1]));
            pm1 = fmaxf(pm1, fmaxf(sa[nj][2], sa[nj][3]));
        }
        pm0 = fmaxf(pm0, __shfl_xor_sync(0xffffffffu, pm0, 1));
        pm0 = fmaxf(pm0, __shfl_xor_sync(0xffffffffu, pm0, 2));
        pm1 = fmaxf(pm1, __shfl_xor_sync(0xffffffffu, pm1, 1));
        pm1 = fmaxf(pm1, __shfl_xor_sync(0xffffffffu, pm1, 2));
        if ((lane & 3) == 0) {
            red0[cg * 64 + prow0] = pm0;
            red0[cg * 64 + prow1] = pm1;
        }
        __syncthreads();
        float rm0 = fmaxf(red0[prow0], red0[64 + prow0]);
        float rm1 = fmaxf(red0[prow1], red0[64 + prow1]);

        float mn0 = fmaxf(m0, rm0);
        float mn1 = fmaxf(m1, rm1);
        float corr0 = __expf(m0 - mn0);
        float corr1 = __expf(m1 - mn1);
        m0 = mn0; m1 = mn1;
#pragma unroll
        for (int j = 0; j < 8; ++j) {
            oa[j][0] *= corr0; oa[j][1] *= corr0;
            oa[j][2] *= corr1; oa[j][3] *= corr1;
        }

        // ---- exp + P store + partial sums
        float ps0 = 0.0f, ps1 = 0.0f;
#pragma unroll
        for (int nj = 0; nj < 4; ++nj) {
            float p0 = __expf(sa[nj][0] - mn0);
            float p1 = __expf(sa[nj][1] - mn0);
            float p2 = __expf(sa[nj][2] - mn1);
            float p3 = __expf(sa[nj][3] - mn1);
            ps0 += p0 + p1;
            ps1 += p2 + p3;
            int kin = nj * 8 + 2 * (lane & 3);
            uint32_t inoff = (uint32_t)((kin >> 3) << 4) + ((kin & 7) << 1);
            uint32_t ba0 = (uint32_t)(BTS_P + cg * 4096) + prow0 * 64
                         + ((inoff & 0xF0u) ^ (pswz0 << 4)) + (inoff & 0xFu);
            uint32_t ba1 = (uint32_t)(BTS_P + cg * 4096) + prow1 * 64
                         + ((inoff & 0xF0u) ^ (pswz1 << 4)) + (inoff & 0xFu);
            *(__half2*)(sm + ba0) = __float22half2_rn(make_float2(p0, p1));
            *(__half2*)(sm + ba1) = __float22half2_rn(make_float2(p2, p3));
        }
        ps0 += __shfl_xor_sync(0xffffffffu, ps0, 1);
        ps0 += __shfl_xor_sync(0xffffffffu, ps0, 2);
        ps1 += __shfl_xor_sync(0xffffffffu, ps1, 1);
        ps1 += __shfl_xor_sync(0xffffffffu, ps1, 2);
        if ((lane & 3) == 0) {
            red1[cg * 64 + prow0] = ps0;
            red1[cg * 64 + prow1] = ps1;
        }
        __syncthreads();
        l0 = l0 * corr0 + red1[prow0] + red1[64 + prow0];
        l1 = l1 * corr1 + red1[prow1] + red1[64 + prow1];

        // ---- PV: warp computes O[16 x 64] (cols cg*64..), k = 64 keys
#pragma unroll
        for (int s = 0; s < 4; ++s) {
            uint32_t a0, a1, a2, a3;
            LDSM_X4(a0, a1, a2, a3,
                    sb + BTS_P + (s >> 1) * 4096 + arow * 64
                       + (((2 * (s & 1) + acp) ^ aswz) << 4));
            int vk = s * 16 + vkb;
#pragma unroll
            for (int gg = 0; gg < 4; ++gg) {
                int gp = cg * 4 + gg;
                uint32_t b0, b1, b2, b3;
                LDSM_X4T(b0, b1, b2, b3,
                         sb + BTS_V + vk * 256
                            + ((((2 * gp + (lane >> 4)) ^ (vk & 7))) << 4));
                MMA_16816_F16(oa[2 * gg][0], oa[2 * gg][1],
                              oa[2 * gg][2], oa[2 * gg][3],
                              a0, a1, a2, a3, b0, b1);
                MMA_16816_F16(oa[2 * gg + 1][0], oa[2 * gg + 1][1],
                              oa[2 * gg + 1][2], oa[2 * gg + 1][3],
                              a0, a1, a2, a3, b2, b3);
            }
        }
        __syncthreads();

        // prefetch next V
        if (kt + 1 < nkt) {
            const __half* va = vh + (size_t)(kt + 1) * 64 * PHD;
#pragma unroll
            for (int ps = 0; ps < 4; ++ps) {
                int idx = tid + ps * 256;
                int rr = idx >> 4, cc = idx & 15;
                CP_ASYNC16(sb + BTS_V + swzV(rr, cc), va + (size_t)rr * PHD + cc * 8);
            }
        }
        CP_COMMIT();
    }

    // ---- epilogue: [hi|lo] fp16 split into AXO
    const float inv0 = 1.0f / l0;
    const float inv1 = 1.0f / l1;
    const int b = bh >> 4, h = bh & 15;
    const size_t row0 = (size_t)b * PS + qb + r0;
    const size_t row1 = row0 + 8;
#pragma unroll
    for (int j = 0; j < 8; ++j) {
        int col = h * PHD + cg * 64 + j * 8 + 2 * (lane & 3);
        float2 p0 = make_float2(oa[j][0] * inv0, oa[j][1] * inv0);
        float2 p1 = make_float2(oa[j][2] * inv1, oa[j][3] * inv1);
        __half2 h20 = __float22half2_rn(p0);
        __half2 h21 = __float22half2_rn(p1);
        __half2 l20 = __float22half2_rn(make_float2(
            p0.x - __half2float(__low2half(h20)),
            p0.y - __half2float(__high2half(h20))));
        __half2 l21 = __float22half2_rn(make_float2(
            p1.x - __half2float(__low2half(h21)),
            p1.y - __half2float(__high2half(h21))));
        __half* d0 = AXO + row0 * K2 + col;
        __half* d1 = AXO + row1 * K2 + col;
        *(__half2*)(d0)        = h20;
        *(__half2*)(d0 + 2048) = l20;
        *(__half2*)(d1)        = h21;
        *(__half2*)(d1 + 2048) = l21;
    }
}

// ---------------------------------------------------------------------------
// kernel_launch
// ---------------------------------------------------------------------------
extern "C" void kernel_launch(void* const* d_in, const int* in_sizes, int n_in,
                              void* d_out, int out_size)
{
    const float* x  = (const float*)d_in[0];
    const float* Wq = (const float*)d_in[1];
    const float* Wk = (const float*)d_in[2];
    const float* Wv = (const float*)d_in[3];
    const float* Wo = (const float*)d_in[4];
    float* out = (float*)d_out;

    __half *Ax2p, *Bqkvp, *Bo2p, *AxOp, *Q2p, *K2p, *Vhp;
    float2* tabp;
    cudaGetSymbolAddress((void**)&Ax2p,  g_Ax2);
    cudaGetSymbolAddress((void**)&Bqkvp, g_Bqkv);
    cudaGetSymbolAddress((void**)&Bo2p,  g_Bo2);
    cudaGetSymbolAddress((void**)&AxOp,  g_AxO);
    cudaGetSymbolAddress((void**)&Q2p,   g_Q2h);
    cudaGetSymbolAddress((void**)&K2p,   g_K2h);
    cudaGetSymbolAddress((void**)&Vhp,   g_Vh);
    cudaGetSymbolAddress((void**)&tabp,  g_tab);

    cudaFuncSetAttribute((const void*)gemm_f16<0>,
                         cudaFuncAttributeMaxDynamicSharedMemorySize, HG_SMEM0);
    cudaFuncSetAttribute((const void*)gemm_f16<1>,
                         cudaFuncAttributeMaxDynamicSharedMemorySize, HG_SMEM1);
    cudaFuncSetAttribute((const void*)attn_tc,
                         cudaFuncAttributeMaxDynamicSharedMemorySize, ATT_SMEM);

    // RoPE tables + all splits
    rope_tables<<<512, 256>>>(tabp);
    split_all<<<16384 + 4 * 8192, 256>>>(x, Wq, Wk, Wv, Wo, Ax2p, Bqkvp, Bo2p);

    // fused QKV projection (N = 6144) with RoPE/split epilogue
    gemm_f16<1><<<dim3(NQKV / 128, PM / 128), 256, HG_SMEM1>>>(
        Ax2p, Bqkvp, nullptr, Q2p, K2p, Vhp, tabp);

    // attention (64-query tiles, 2 CTAs/SM)
    attn_tc<<<dim3(PS / 64, PB * PH), 256, ATT_SMEM>>>(Q2p, K2p, Vhp, AxOp);

    // Wo projection
    gemm_f16<0><<<dim3(PD / 128, PM / 128), 256, HG_SMEM0>>>(
        AxOp, Bo2p, out, nullptr, nullptr, nullptr, nullptr);
}

// round 12
// speedup vs baseline: 3.0047x; 1.0859x over previous
#include <cuda_runtime.h>
#include <cuda_fp16.h>
#include <math.h>
#include <stdint.h>

// ---------------------------------------------------------------------------
// Problem constants
// ---------------------------------------------------------------------------
#define PB 2
#define PS 2048
#define PD 2048
#define PH 16
#define PHD 128
#define PM (PB * PS)          // 4096 rows
#define K2 (2 * PD)           // 4096: fp16 2-term split-K
#define NQKV (3 * PD)         // 6144: fused QKV output columns
#define ATT_SCALE 0.08838834764831845f

// ---------------------------------------------------------------------------
// Scratch (device globals; no allocation allowed)
// ---------------------------------------------------------------------------
__device__ __half g_Ax2[(size_t)PM * K2];                // x, fp16 [hi|lo]
__device__ __half g_Bqkv[(size_t)NQKV * K2];             // [Wq;Wk;Wv] fp16 [hi|hi]
__device__ __half g_Bo2[(size_t)PD * K2];                // Wo fp16 [hi|hi]
__device__ __half g_AxO[(size_t)PM * K2];                // attn out fp16 [hi|lo]
__device__ __half g_Q2h[(size_t)PB * PH * PS * 256];     // [qh|ql]*scale
__device__ __half g_K2h[(size_t)PB * PH * PS * 128];     // kh (deduped)
__device__ __half g_Vh[(size_t)PB * PH * PS * PHD];
__device__ float2 g_tab[PS * 64];                        // {cos, sin}

// ---------------------------------------------------------------------------
// PTX helpers (sm_80-compatible: cp.async + ldmatrix + mma.sync)
// ---------------------------------------------------------------------------
__device__ __forceinline__ uint32_t smem_u32(const void* p) {
    uint32_t a;
    asm("{ .reg .u64 t; cvta.to.shared.u64 t, %1; cvt.u32.u64 %0, t; }"
        : "=r"(a) : "l"(p));
    return a;
}

#define CP_ASYNC16(smem, gptr) \
    asm volatile("cp.async.cg.shared.global [%0], [%1], 16;" \
                 :: "r"(smem), "l"(gptr) : "memory")
#define CP_COMMIT() asm volatile("cp.async.commit_group;" ::: "memory")
#define CP_WAIT2()  asm volatile("cp.async.wait_group 2;" ::: "memory")
#define CP_WAIT0()  asm volatile("cp.async.wait_group 0;" ::: "memory")

#define LDSM_X4(r0, r1, r2, r3, addr) \
    asm volatile("ldmatrix.sync.aligned.m8n8.x4.shared.b16 {%0,%1,%2,%3}, [%4];" \
                 : "=r"(r0), "=r"(r1), "=r"(r2), "=r"(r3) : "r"(addr))
#define LDSM_X4T(r0, r1, r2, r3, addr) \
    asm volatile("ldmatrix.sync.aligned.m8n8.x4.trans.shared.b16 {%0,%1,%2,%3}, [%4];" \
                 : "=r"(r0), "=r"(r1), "=r"(r2), "=r"(r3) : "r"(addr))

#define MMA_16816_F16(c0, c1, c2, c3, a0, a1, a2, a3, b0, b1) \
    asm volatile("mma.sync.aligned.m16n8k16.row.col.f32.f16.f16.f32 " \
                 "{%0,%1,%2,%3}, {%4,%5,%6,%7}, {%8,%9}, {%0,%1,%2,%3};" \
                 : "+f"(c0), "+f"(c1), "+f"(c2), "+f"(c3) \
                 : "r"(a0), "r"(a1), "r"(a2), "r"(a3), "r"(b0), "r"(b1))

// swizzles
__device__ __forceinline__ uint32_t swz64(int r, int ch) {   // 64B rows, 4x16B chunks
    return (uint32_t)(r * 64 + (((ch) ^ ((r >> 1) & 3)) << 4));
}
__device__ __forceinline__ uint32_t swzV(int r, int ch) {    // 256B rows, 16x16B chunks
    return (uint32_t)(r * 256 + (((ch) ^ (r & 7)) << 4));
}

// ---------------------------------------------------------------------------
// RoPE tables: invf = exp(-j/64 * ln(10000)) (fp64); angle fp32-rounded chain.
// ---------------------------------------------------------------------------
__global__ __launch_bounds__(256)
void rope_tables(float2* __restrict__ tab)
{
    int idx = blockIdx.x * blockDim.x + threadIdx.x;   // 131072
    int s = idx >> 6;
    int j = idx & 63;
    double invf_d = exp(-(double)j * (9.210340371976184 / 64.0));
    float ang = (float)s * (float)invf_d;
    double cs, sn;
    sincos((double)ang, &sn, &cs);
    tab[idx] = make_float2((float)cs, (float)sn);
}

// ---------------------------------------------------------------------------
// Merged splits: fp32 -> 2-segment fp16.
// ---------------------------------------------------------------------------
__global__ __launch_bounds__(256)
void split_all(const float* __restrict__ x,
               const float* __restrict__ Wq, const float* __restrict__ Wk,
               const float* __restrict__ Wv, const float* __restrict__ Wo,
               __half* __restrict__ Ax, __half* __restrict__ Bqkv,
               __half* __restrict__ Bo)
{
    int bid = blockIdx.x;
    const float* src;
    __half* dst;
    int order, base;
    if (bid < 16384) {
        src = x; dst = Ax; order = 0; base = 0;
    } else {
        int seg = (bid - 16384) >> 13;
        base = 16384 + seg * 8192;
        order = 1;
        if (seg == 0)      { src = Wq; dst = Bqkv; }
        else if (seg == 1) { src = Wk; dst = Bqkv + (size_t)2048 * K2; }
        else if (seg == 2) { src = Wv; dst = Bqkv + (size_t)4096 * K2; }
        else               { src = Wo; dst = Bo; }
    }
    int i = (bid - base) * 256 + threadIdx.x;
    int r = i >> 10;
    int c = (i & 1023) << 1;
    float2 v = *(const float2*)(src + (size_t)r * PD + c);
    __half h0 = __float2half(v.x);
    __half h1 = __float2half(v.y);
    __half2 hh = __halves2half2(h0, h1);
    __half2 seg1;
    if (order) {
        seg1 = hh;
    } else {
        seg1 = __halves2half2(__float2half(v.x - __half2float(h0)),
                              __float2half(v.y - __half2float(h1)));
    }
    __half2* bp = (__half2*)(dst + (size_t)r * K2 + c);
    bp[0]    = hh;
    bp[1024] = seg1;
}

// ---------------------------------------------------------------------------
// fp16 2-term HMMA GEMM, K=4096. B fragments via ldmatrix.x4 (2 n-blocks/op).
//  MODE 0: Wo projection — plain fp32 C stores.
//  MODE 1: fused QKV (N=6144): region 0 Q (RoPE+split), 1 K (RoPE, deduped),
//          2 V (fp16 head-gather).
// ---------------------------------------------------------------------------
#define HG_BK 32
#define HG_STG 4
#define HG_STAGE_BYTES 16384
#define HG_SMEM0 (HG_STG * HG_STAGE_BYTES)      // 65536 (MODE 0)
#define HG_PITCH 136
#define HG_SMEM1 (128 * HG_PITCH * 4)           // 69632 (MODE 1)
#define HG_KT (K2 / HG_BK)                      // 128

template<int MODE>
__global__ __launch_bounds__(256, 2)
void gemm_f16(const __half* __restrict__ A3, const __half* __restrict__ B3,
              float* __restrict__ C,
              __half* __restrict__ Q2o, __half* __restrict__ K2o,
              __half* __restrict__ Vho, const float2* __restrict__ tab)
{
    extern __shared__ __align__(1024) char smem[];
    const uint32_t sbase = smem_u32(smem);

    const int tid  = threadIdx.x;
    const int lane = tid & 31;
    const int wid  = tid >> 5;
    const int wm   = wid & 1;
    const int wn   = wid >> 1;
    const int bm   = blockIdx.y * 128;
    const int bn   = blockIdx.x * 128;

    const __half* Ag = A3 + (size_t)bm * K2;
    const __half* Bg = B3 + (size_t)bn * K2;

    uint32_t lsw[2];
    const __half* gA[2];
    const __half* gB[2];
#pragma unroll
    for (int p = 0; p < 2; ++p) {
        int idx = tid + p * 256;
        int r = idx >> 2, ch = idx & 3;
        lsw[p] = swz64(r, ch);
        gA[p] = Ag + (size_t)r * K2 + ch * 8;
        gB[p] = Bg + (size_t)r * K2 + ch * 8;
    }

    uint32_t a_row_off[4];
    int a_swz[4];
#pragma unroll
    for (int mi = 0; mi < 4; ++mi) {
        int r = wm * 64 + mi * 16 + (lane & 15);
        a_row_off[mi] = (uint32_t)(r * 64);
        a_swz[mi] = (r >> 1) & 3;
    }
    const int a_cpart = lane >> 4;
    // B x4: lanes 0-15 -> n-block njp*2, lanes 16-31 -> njp*2+1; chunk by lane>>3.
    uint32_t b_row_off[2];
    int b_swz[2];
#pragma unroll
    for (int njp = 0; njp < 2; ++njp) {
        int r = wn * 32 + njp * 16 + ((lane >> 4) & 1) * 8 + (lane & 7);
        b_row_off[njp] = (uint32_t)(r * 64);
        b_swz[njp] = (r >> 1) & 3;
    }
    const int b_cpart = (lane >> 3) & 1;

    float acc[4][4][4];
#pragma unroll
    for (int mi = 0; mi < 4; ++mi)
#pragma unroll
        for (int nj = 0; nj < 4; ++nj)
#pragma unroll
            for (int e = 0; e < 4; ++e) acc[mi][nj][e] = 0.0f;

#pragma unroll
    for (int s = 0; s < HG_STG - 1; ++s) {
        uint32_t sA = sbase + s * HG_STAGE_BYTES;
        uint32_t sB = sA + 8192;
        int k0 = s * HG_BK;
#pragma unroll
        for (int p = 0; p < 2; ++p) {
            CP_ASYNC16(sA + lsw[p], gA[p] + k0);
            CP_ASYNC16(sB + lsw[p], gB[p] + k0);
        }
        CP_COMMIT();
    }

    for (int kt = 0; kt < HG_KT; ++kt) {
        CP_WAIT2();
        __syncthreads();

        int nk = kt + HG_STG - 1;
        if (nk < HG_KT) {
            uint32_t sA = sbase + (nk & 3) * HG_STAGE_BYTES;
            uint32_t sB = sA + 8192;
            int k0 = nk * HG_BK;
#pragma unroll
            for (int p = 0; p < 2; ++p) {
                CP_ASYNC16(sA + lsw[p], gA[p] + k0);
                CP_ASYNC16(sB + lsw[p], gB[p] + k0);
            }
        }
        CP_COMMIT();

        uint32_t sA = sbase + (kt & 3) * HG_STAGE_BYTES;
        uint32_t sB = sA + 8192;
#pragma unroll
        for (int h = 0; h < 2; ++h) {
            uint32_t a0[4], a1[4], a2[4], a3[4];
#pragma unroll
            for (int mi = 0; mi < 4; ++mi) {
                uint32_t addr = sA + a_row_off[mi]
                              + (uint32_t)(((2 * h + a_cpart) ^ a_swz[mi]) << 4);
                LDSM_X4(a0[mi], a1[mi], a2[mi], a3[mi], addr);
            }
            uint32_t b0[4], b1[4];
#pragma unroll
            for (int njp = 0; njp < 2; ++njp) {
                uint32_t addr = sB + b_row_off[njp]
                              + (uint32_t)(((2 * h + b_cpart) ^ b_swz[njp]) << 4);
                LDSM_X4(b0[2 * njp], b1[2 * njp],
                        b0[2 * njp + 1], b1[2 * njp + 1], addr);
            }
#pragma unroll
            for (int mi = 0; mi < 4; ++mi)
#pragma unroll
                for (int nj = 0; nj < 4; ++nj)
                    MMA_16816_F16(acc[mi][nj][0], acc[mi][nj][1],
                                  acc[mi][nj][2], acc[mi][nj][3],
                                  a0[mi], a1[mi], a2[mi], a3[mi],
                                  b0[nj], b1[nj]);
        }
        __syncthreads();
    }

    const int erow = (lane >> 2);
    const int ecol = (lane & 3) * 2;
    const int region  = (MODE == 1) ? (bn >> 11) : 0;
    const int colbase = bn - region * 2048;

    if (MODE == 0) {
#pragma unroll
        for (int mi = 0; mi < 4; ++mi)
#pragma unroll
            for (int nj = 0; nj < 4; ++nj) {
                int row = bm + wm * 64 + mi * 16 + erow;
                int col = colbase + wn * 32 + nj * 8 + ecol;
                *(float2*)(C + (size_t)row * PD + col) =
                    make_float2(acc[mi][nj][0], acc[mi][nj][1]);
                *(float2*)(C + (size_t)(row + 8) * PD + col) =
                    make_float2(acc[mi][nj][2], acc[mi][nj][3]);
            }
    } else if (region == 2) {
#pragma unroll
        for (int mi = 0; mi < 4; ++mi)
#pragma unroll
            for (int nj = 0; nj < 4; ++nj) {
                int row = bm + wm * 64 + mi * 16 + erow;
                int col = colbase + wn * 32 + nj * 8 + ecol;
                int b = row >> 11, s = row & 2047;
                int h = col >> 7, hd = col & 127;
                size_t dst = ((size_t)(b * PH + h) * PS + s) * PHD + hd;
                *(__half2*)(Vho + dst) = __float22half2_rn(
                    make_float2(acc[mi][nj][0], acc[mi][nj][1]));
                *(__half2*)(Vho + dst + 8 * PHD) = __float22half2_rn(
                    make_float2(acc[mi][nj][2], acc[mi][nj][3]));
            }
    } else {
        // Q/K: smem stage + RoPE + fp16 emit (Q split 256-wide, K dedup 128-wide)
        float* tile = (float*)smem;
#pragma unroll
        for (int mi = 0; mi < 4; ++mi)
#pragma unroll
            for (int nj = 0; nj < 4; ++nj) {
                int r = wm * 64 + mi * 16 + erow;
                int c = wn * 32 + nj * 8 + ecol;
                *(float2*)(tile + r * HG_PITCH + c) =
                    make_float2(acc[mi][nj][0], acc[mi][nj][1]);
                *(float2*)(tile + (r + 8) * HG_PITCH + c) =
                    make_float2(acc[mi][nj][2], acc[mi][nj][3]);
            }
        __syncthreads();

        const int hh = colbase >> 7;
        const int b  = bm >> 11;
        const int s0 = bm & 2047;
        const int rg = tid >> 6;
        const int ii = tid & 63;
        if (region == 0) {
            __half* dst = Q2o + (size_t)(b * PH + hh) * PS * 256;
#pragma unroll 4
            for (int rr = 0; rr < 32; ++rr) {
                int r = rg * 32 + rr;
                float x0 = tile[r * HG_PITCH + ii];
                float x1 = tile[r * HG_PITCH + 64 + ii];
                int s = s0 + r;
                float2 cs = tab[s * 64 + ii];
                float o0 = (x0 * cs.x - x1 * cs.y) * ATT_SCALE;
                float o1 = (x1 * cs.x + x0 * cs.y) * ATT_SCALE;
                __half* o = dst + (size_t)s * 256;
                __half h0 = __float2half(o0), h1 = __float2half(o1);
                o[ii]       = h0;
                o[64 + ii]  = h1;
                o[128 + ii] = __float2half(o0 - __half2float(h0));
                o[192 + ii] = __float2half(o1 - __half2float(h1));
            }
        } else {
            __half* dst = K2o + (size_t)(b * PH + hh) * PS * 128;
#pragma unroll 4
            for (int rr = 0; rr < 32; ++rr) {
                int r = rg * 32 + rr;
                float x0 = tile[r * HG_PITCH + ii];
                float x1 = tile[r * HG_PITCH + 64 + ii];
                int s = s0 + r;
                float2 cs = tab[s * 64 + ii];
                __half* o = dst + (size_t)s * 128;
                o[ii]      = __float2half(x0 * cs.x - x1 * cs.y);
                o[64 + ii] = __float2half(x1 * cs.x + x0 * cs.y);
            }
        }
    }
}

// ---------------------------------------------------------------------------
// Tensor-core causal flash attention, 64q x 64k tiles, 2 CTAs/SM.
// K stored ONCE (kh); each B fragment reused for Q-hi and Q-lo mmas.
// ---------------------------------------------------------------------------
#define BTS_Q  0          // 8 panels x 4096 = 32768
#define BTS_K  32768      // 4 panels x 4096 = 16384
#define BTS_V  49152      // 16384
#define BTS_P  65536      // 2 panels x 4096 = 8192
#define BTS_R0 73728      // 512 B (rowmax partials)
#define BTS_R1 74240      // 512 B (rowsum partials)
#define ATT_SMEM 74752

__global__ __launch_bounds__(256, 2)
void attn_tc(const __half* __restrict__ Q2,
             const __half* __restrict__ K2g,
             const __half* __restrict__ Vh,
             __half* __restrict__ AXO)
{
    extern __shared__ __align__(1024) char sm[];
    const uint32_t sb = smem_u32(sm);
    float* red0 = (float*)(sm + BTS_R0);
    float* red1 = (float*)(sm + BTS_R1);

    const int tid  = threadIdx.x;
    const int lane = tid & 31;
    const int w    = tid >> 5;
    const int rg   = w & 3;
    const int cg   = w >> 2;
    const int qt   = 31 - (int)blockIdx.x;
    const int bh   = blockIdx.y;
    const int qb   = qt * 64;
    const int nkt  = qt + 1;

    const __half* q2 = Q2 + ((size_t)bh * PS + qb) * 256;
    const __half* k2 = K2g + (size_t)bh * PS * 128;
    const __half* vh = Vh + (size_t)bh * PS * PHD;

    // ---- Q tile (64 x 256), K0 (64 x 128), V0
    {
        int r = tid >> 2, ch = tid & 3;
        uint32_t sw = swz64(r, ch);
#pragma unroll
        for (int p = 0; p < 8; ++p)
            CP_ASYNC16(sb + BTS_Q + p * 4096 + sw,
                       q2 + (size_t)r * 256 + p * 32 + ch * 8);
#pragma unroll
        for (int p = 0; p < 4; ++p)
            CP_ASYNC16(sb + BTS_K + p * 4096 + sw,
                       k2 + (size_t)r * 128 + p * 32 + ch * 8);
#pragma unroll
        for (int ps = 0; ps < 4; ++ps) {
            int idx = tid + ps * 256;
            int rr = idx >> 4, cc = idx & 15;
            CP_ASYNC16(sb + BTS_V + swzV(rr, cc), vh + (size_t)rr * PHD + cc * 8);
        }
    }
    CP_COMMIT();

    float m0 = -INFINITY, m1 = -INFINITY, l0 = 0.0f, l1 = 0.0f;
    float oa[8][4];
#pragma unroll
    for (int j = 0; j < 8; ++j)
#pragma unroll
        for (int e = 0; e < 4; ++e) oa[j][e] = 0.0f;

    const int arow  = rg * 16 + (lane & 15);
    const int aswz  = (arow >> 1) & 3;
    const int acp   = lane >> 4;
    const int r0    = rg * 16 + (lane >> 2);
    const int prow0 = r0;
    const int prow1 = r0 + 8;
    const int pswz0 = (prow0 >> 1) & 3;
    const int pswz1 = (prow1 >> 1) & 3;
    const int vkb   = (lane & 7) + 8 * ((lane >> 3) & 1);

    for (int kt = 0; kt < nkt; ++kt) {
        CP_WAIT0();
        __syncthreads();

        // ---- QK: S[16 x 32] per warp; K'=128, hi/lo Q reuse the same B frags
        float sa[4][4];
#pragma unroll
        for (int j = 0; j < 4; ++j)
#pragma unroll
            for (int e = 0; e < 4; ++e) sa[j][e] = 0.0f;

#pragma unroll
        for (int p = 0; p < 4; ++p) {
#pragma unroll
            for (int h = 0; h < 2; ++h) {
                uint32_t aoff = (uint32_t)(((2 * h + acp) ^ aswz) << 4);
                uint32_t ah0, ah1, ah2, ah3, al0, al1, al2, al3;
                LDSM_X4(ah0, ah1, ah2, ah3,
                        sb + BTS_Q + p * 4096 + arow * 64 + aoff);
                LDSM_X4(al0, al1, al2, al3,
                        sb + BTS_Q + (p + 4) * 4096 + arow * 64 + aoff);
#pragma unroll
                for (int jj = 0; jj < 2; ++jj) {
                    int brow = cg * 32 + jj * 16 + (lane & 15);
                    uint32_t b0, b1, b2, b3;
                    LDSM_X4(b0, b1, b2, b3,
                            sb + BTS_K + p * 4096 + brow * 64
                               + (((2 * h + acp) ^ ((brow >> 1) & 3)) << 4));
                    MMA_16816_F16(sa[2 * jj][0], sa[2 * jj][1],
                                  sa[2 * jj][2], sa[2 * jj][3],
                                  ah0, ah1, ah2, ah3, b0, b2);
                    MMA_16816_F16(sa[2 * jj + 1][0], sa[2 * jj + 1][1],
                                  sa[2 * jj + 1][2], sa[2 * jj + 1][3],
                                  ah0, ah1, ah2, ah3, b1, b3);
                    MMA_16816_F16(sa[2 * jj][0], sa[2 * jj][1],
                                  sa[2 * jj][2], sa[2 * jj][3],
                                  al0, al1, al2, al3, b0, b2);
                    MMA_16816_F16(sa[2 * jj + 1][0], sa[2 * jj + 1][1],
                                  sa[2 * jj + 1][2], sa[2 * jj + 1][3],
                                  al0, al1, al2, al3, b1, b3);
                }
            }
        }
        __syncthreads();

        // prefetch next K
        if (kt + 1 < nkt) {
            const __half* kp = k2 + (size_t)(kt + 1) * 64 * 128;
            int r = tid >> 2, ch = tid & 3;
            uint32_t sw = swz64(r, ch);
#pragma unroll
            for (int p = 0; p < 4; ++p)
                CP_ASYNC16(sb + BTS_K + p * 4096 + sw,
                           kp + (size_t)r * 128 + p * 32 + ch * 8);
        }
        CP_COMMIT();

        // ---- causal mask (diagonal tile only)
        if (kt == qt) {
            const int gr0 = qb + r0;
            const int gr1 = gr0 + 8;
            const int kb = kt * 64;
#pragma unroll
            for (int nj = 0; nj < 4; ++nj) {
                int c0 = kb + cg * 32 + nj * 8 + 2 * (lane & 3);
                if (c0 > gr0)     sa[nj][0] = -INFINITY;
                if (c0 + 1 > gr0) sa[nj][1] = -INFINITY;
                if (c0 > gr1)     sa[nj][2] = -INFINITY;
                if (c0 + 1 > gr1) sa[nj][3] = -INFINITY;
            }
        }

        // ---- row max: intra-quad + cross-warp (cg halves) via smem
        float pm0 = -INFINITY, pm1 = -INFINITY;
#pragma unroll
        for (int nj = 0; nj < 4; ++nj) {
            pm0 = fmaxf(pm0, fmaxf(sa[nj][0], sa[nj][1]));
            pm1 = fmaxf(pm1, fmaxf(sa[nj][2], sa[nj][3]));
        }
        pm0 = fmaxf(pm0, __shfl_xor_sync(0xffffffffu, pm0, 1));
        pm0 = fmaxf(pm0, __shfl_xor_sync(0xffffffffu, pm0, 2));
        pm1 = fmaxf(pm1, __shfl_xor_sync(0xffffffffu, pm1, 1));
        pm1 = fmaxf(pm1, __shfl_xor_sync(0xffffffffu, pm1, 2));
        if ((lane & 3) == 0) {
            red0[cg * 64 + prow0] = pm0;
            red0[cg * 64 + prow1] = pm1;
        }
        __syncthreads();
        float rm0 = fmaxf(red0[prow0], red0[64 + prow0]);
        float rm1 = fmaxf(red0[prow1], red0[64 + prow1]);

        float mn0 = fmaxf(m0, rm0);
        float mn1 = fmaxf(m1, rm1);
        float corr0 = __expf(m0 - mn0);
        float corr1 = __expf(m1 - mn1);
        m0 = mn0; m1 = mn1;
#pragma unroll
        for (int j = 0; j < 8; ++j) {
            oa[j][0] *= corr0; oa[j][1] *= corr0;
            oa[j][2] *= corr1; oa[j][3] *= corr1;
        }

        // ---- exp + P store + partial sums
        float ps0 = 0.0f, ps1 = 0.0f;
#pragma unroll
        for (int nj = 0; nj < 4; ++nj) {
            float p0 = __expf(sa[nj][0] - mn0);
            float p1 = __expf(sa[nj][1] - mn0);
            float p2 = __expf(sa[nj][2] - mn1);
            float p3 = __expf(sa[nj][3] - mn1);
            ps0 += p0 + p1;
            ps1 += p2 + p3;
            int kin = nj * 8 + 2 * (lane & 3);
            uint32_t inoff = (uint32_t)((kin >> 3) << 4) + ((kin & 7) << 1);
            uint32_t ba0 = (uint32_t)(BTS_P + cg * 4096) + prow0 * 64
                         + ((inoff & 0xF0u) ^ (pswz0 << 4)) + (inoff & 0xFu);
            uint32_t ba1 = (uint32_t)(BTS_P + cg * 4096) + prow1 * 64
                         + ((inoff & 0xF0u) ^ (pswz1 << 4)) + (inoff & 0xFu);
            *(__half2*)(sm + ba0) = __float22half2_rn(make_float2(p0, p1));
            *(__half2*)(sm + ba1) = __float22half2_rn(make_float2(p2, p3));
        }
        ps0 += __shfl_xor_sync(0xffffffffu, ps0, 1);
        ps0 += __shfl_xor_sync(0xffffffffu, ps0, 2);
        ps1 += __shfl_xor_sync(0xffffffffu, ps1, 1);
        ps1 += __shfl_xor_sync(0xffffffffu, ps1, 2);
        if ((lane & 3) == 0) {
            red1[cg * 64 + prow0] = ps0;
            red1[cg * 64 + prow1] = ps1;
        }
        __syncthreads();
        l0 = l0 * corr0 + red1[prow0] + red1[64 + prow0];
        l1 = l1 * corr1 + red1[prow1] + red1[64 + prow1];

        // ---- PV: warp computes O[16 x 64] (cols cg*64..), k = 64 keys
#pragma unroll
        for (int s = 0; s < 4; ++s) {
            uint32_t a0, a1, a2, a3;
            LDSM_X4(a0, a1, a2, a3,
                    sb + BTS_P + (s >> 1) * 4096 + arow * 64
                       + (((2 * (s & 1) + acp) ^ aswz) << 4));
            int vk = s * 16 + vkb;
#pragma unroll
            for (int gg = 0; gg < 4; ++gg) {
                int gp = cg * 4 + gg;
                uint32_t b0, b1, b2, b3;
                LDSM_X4T(b0, b1, b2, b3,
                         sb + BTS_V + vk * 256
                            + ((((2 * gp + (lane >> 4)) ^ (vk & 7))) << 4));
                MMA_16816_F16(oa[2 * gg][0], oa[2 * gg][1],
                              oa[2 * gg][2], oa[2 * gg][3],
                              a0, a1, a2, a3, b0, b1);
                MMA_16816_F16(oa[2 * gg + 1][0], oa[2 * gg + 1][1],
                              oa[2 * gg + 1][2], oa[2 * gg + 1][3],
                              a0, a1, a2, a3, b2, b3);
            }
        }
        __syncthreads();

        // prefetch next V
        if (kt + 1 < nkt) {
            const __half* va = vh + (size_t)(kt + 1) * 64 * PHD;
#pragma unroll
            for (int ps = 0; ps < 4; ++ps) {
                int idx = tid + ps * 256;
                int rr = idx >> 4, cc = idx & 15;
                CP_ASYNC16(sb + BTS_V + swzV(rr, cc), va + (size_t)rr * PHD + cc * 8);
            }
        }
        CP_COMMIT();
    }

    // ---- epilogue: [hi|lo] fp16 split into AXO
    const float inv0 = 1.0f / l0;
    const float inv1 = 1.0f / l1;
    const int b = bh >> 4, h = bh & 15;
    const size_t row0 = (size_t)b * PS + qb + r0;
    const size_t row1 = row0 + 8;
#pragma unroll
    for (int j = 0; j < 8; ++j) {
        int col = h * PHD + cg * 64 + j * 8 + 2 * (lane & 3);
        float2 p0 = make_float2(oa[j][0] * inv0, oa[j][1] * inv0);
        float2 p1 = make_float2(oa[j][2] * inv1, oa[j][3] * inv1);
        __half2 h20 = __float22half2_rn(p0);
        __half2 h21 = __float22half2_rn(p1);
        __half2 l20 = __float22half2_rn(make_float2(
            p0.x - __half2float(__low2half(h20)),
            p0.y - __half2float(__high2half(h20))));
        __half2 l21 = __float22half2_rn(make_float2(
            p1.x - __half2float(__low2half(h21)),
            p1.y - __half2float(__high2half(h21))));
        __half* d0 = AXO + row0 * K2 + col;
        __half* d1 = AXO + row1 * K2 + col;
        *(__half2*)(d0)        = h20;
        *(__half2*)(d0 + 2048) = l20;
        *(__half2*)(d1)        = h21;
        *(__half2*)(d1 + 2048) = l21;
    }
}

// ---------------------------------------------------------------------------
// kernel_launch
// ---------------------------------------------------------------------------
extern "C" void kernel_launch(void* const* d_in, const int* in_sizes, int n_in,
                              void* d_out, int out_size)
{
    const float* x  = (const float*)d_in[0];
    const float* Wq = (const float*)d_in[1];
    const float* Wk = (const float*)d_in[2];
    const float* Wv = (const float*)d_in[3];
    const float* Wo = (const float*)d_in[4];
    float* out = (float*)d_out;

    __half *Ax2p, *Bqkvp, *Bo2p, *AxOp, *Q2p, *K2p, *Vhp;
    float2* tabp;
    cudaGetSymbolAddress((void**)&Ax2p,  g_Ax2);
    cudaGetSymbolAddress((void**)&Bqkvp, g_Bqkv);
    cudaGetSymbolAddress((void**)&Bo2p,  g_Bo2);
    cudaGetSymbolAddress((void**)&AxOp,  g_AxO);
    cudaGetSymbolAddress((void**)&Q2p,   g_Q2h);
    cudaGetSymbolAddress((void**)&K2p,   g_K2h);
    cudaGetSymbolAddress((void**)&Vhp,   g_Vh);
    cudaGetSymbolAddress((void**)&tabp,  g_tab);

    cudaFuncSetAttribute((const void*)gemm_f16<0>,
                         cudaFuncAttributeMaxDynamicSharedMemorySize, HG_SMEM0);
    cudaFuncSetAttribute((const void*)gemm_f16<1>,
                         cudaFuncAttributeMaxDynamicSharedMemorySize, HG_SMEM1);
    cudaFuncSetAttribute((const void*)attn_tc,
                         cudaFuncAttributeMaxDynamicSharedMemorySize, ATT_SMEM);

    // RoPE tables + all splits
    rope_tables<<<512, 256>>>(tabp);
    split_all<<<16384 + 4 * 8192, 256>>>(x, Wq, Wk, Wv, Wo, Ax2p, Bqkvp, Bo2p);

    // fused QKV projection (N = 6144) with RoPE/split epilogue
    gemm_f16<1><<<dim3(NQKV / 128, PM / 128), 256, HG_SMEM1>>>(
        Ax2p, Bqkvp, nullptr, Q2p, K2p, Vhp, tabp);

    // attention (64-query tiles, deduped K, 2 CTAs/SM)
    attn_tc<<<dim3(PS / 64, PB * PH), 256, ATT_SMEM>>>(Q2p, K2p, Vhp, AxOp);

    // Wo projection
    gemm_f16<0><<<dim3(PD / 128, PM / 128), 256, HG_SMEM0>>>(
        AxOp, Bo2p, out, nullptr, nullptr, nullptr, nullptr);
}

// round 13
// speedup vs baseline: 4.7448x; 1.5791x over previous
#include <cuda_runtime.h>
#include <cuda_fp16.h>
#include <math.h>
#include <stdint.h>

// ---------------------------------------------------------------------------
// Problem constants
// ---------------------------------------------------------------------------
#define PB 2
#define PS 2048
#define PD 2048
#define PH 16
#define PHD 128
#define PM (PB * PS)          // 4096 rows
#define KC 2048               // GEMM K (plain fp16, 1-term)
#define NQKV (3 * PD)         // 6144: fused QKV output columns
#define ATT_SCALE 0.08838834764831845f

// ---------------------------------------------------------------------------
// Scratch (device globals; no allocation allowed)
// ---------------------------------------------------------------------------
__device__ __half g_Ax[(size_t)PM * KC];                 // x, fp16
__device__ __half g_Bqkv[(size_t)NQKV * KC];             // [Wq;Wk;Wv] fp16
__device__ __half g_Bo[(size_t)PD * KC];                 // Wo fp16
__device__ __half g_AxO[(size_t)PM * KC];                // attn out fp16
__device__ __half g_Q2h[(size_t)PB * PH * PS * 256];     // [qh|ql]*scale
__device__ __half g_K2h[(size_t)PB * PH * PS * 128];     // kh
__device__ __half g_Vh[(size_t)PB * PH * PS * PHD];
__device__ float2 g_tab[PS * 64];                        // {cos, sin}

// ---------------------------------------------------------------------------
// PTX helpers (sm_80-compatible: cp.async + ldmatrix + mma.sync)
// ---------------------------------------------------------------------------
__device__ __forceinline__ uint32_t smem_u32(const void* p) {
    uint32_t a;
    asm("{ .reg .u64 t; cvta.to.shared.u64 t, %1; cvt.u32.u64 %0, t; }"
        : "=r"(a) : "l"(p));
    return a;
}

#define CP_ASYNC16(smem, gptr) \
    asm volatile("cp.async.cg.shared.global [%0], [%1], 16;" \
                 :: "r"(smem), "l"(gptr) : "memory")
#define CP_COMMIT() asm volatile("cp.async.commit_group;" ::: "memory")
#define CP_WAIT2()  asm volatile("cp.async.wait_group 2;" ::: "memory")
#define CP_WAIT0()  asm volatile("cp.async.wait_group 0;" ::: "memory")

#define LDSM_X4(r0, r1, r2, r3, addr) \
    asm volatile("ldmatrix.sync.aligned.m8n8.x4.shared.b16 {%0,%1,%2,%3}, [%4];" \
                 : "=r"(r0), "=r"(r1), "=r"(r2), "=r"(r3) : "r"(addr))
#define LDSM_X4T(r0, r1, r2, r3, addr) \
    asm volatile("ldmatrix.sync.aligned.m8n8.x4.trans.shared.b16 {%0,%1,%2,%3}, [%4];" \
                 : "=r"(r0), "=r"(r1), "=r"(r2), "=r"(r3) : "r"(addr))

#define MMA_16816_F16(c0, c1, c2, c3, a0, a1, a2, a3, b0, b1) \
    asm volatile("mma.sync.aligned.m16n8k16.row.col.f32.f16.f16.f32 " \
                 "{%0,%1,%2,%3}, {%4,%5,%6,%7}, {%8,%9}, {%0,%1,%2,%3};" \
                 : "+f"(c0), "+f"(c1), "+f"(c2), "+f"(c3) \
                 : "r"(a0), "r"(a1), "r"(a2), "r"(a3), "r"(b0), "r"(b1))

// swizzles
__device__ __forceinline__ uint32_t swz64(int r, int ch) {   // 64B rows, 4x16B chunks
    return (uint32_t)(r * 64 + (((ch) ^ ((r >> 1) & 3)) << 4));
}
__device__ __forceinline__ uint32_t swzV(int r, int ch) {    // 256B rows, 16x16B chunks
    return (uint32_t)(r * 256 + (((ch) ^ (r & 7)) << 4));
}

// ---------------------------------------------------------------------------
// RoPE tables: invf = exp(-j/64 * ln(10000)) (fp64); angle fp32-rounded chain.
// ---------------------------------------------------------------------------
__global__ __launch_bounds__(256)
void rope_tables(float2* __restrict__ tab)
{
    int idx = blockIdx.x * blockDim.x + threadIdx.x;   // 131072
    int s = idx >> 6;
    int j = idx & 63;
    double invf_d = exp(-(double)j * (9.210340371976184 / 64.0));
    float ang = (float)s * (float)invf_d;
    double cs, sn;
    sincos((double)ang, &sn, &cs);
    tab[idx] = make_float2((float)cs, (float)sn);
}

// ---------------------------------------------------------------------------
// Merged converts: fp32 -> fp16 (plain cast).
//   blocks [0, 8192): x -> Ax
//   blocks [8192 + 4096*seg): Wq/Wk/Wv -> Bqkv segs, Wo -> Bo
// ---------------------------------------------------------------------------
__global__ __launch_bounds__(256)
void convert_all(const float* __restrict__ x,
                 const float* __restrict__ Wq, const float* __restrict__ Wk,
                 const float* __restrict__ Wv, const float* __restrict__ Wo,
                 __half* __restrict__ Ax, __half* __restrict__ Bqkv,
                 __half* __restrict__ Bo)
{
    int bid = blockIdx.x;
    const float* src;
    __half* dst;
    int off;
    if (bid < 8192) {
        src = x; dst = Ax; off = bid;
    } else {
        int seg = (bid - 8192) >> 12;
        off = bid - 8192 - seg * 4096;
        if (seg == 0)      { src = Wq; dst = Bqkv; }
        else if (seg == 1) { src = Wk; dst = Bqkv + (size_t)2048 * KC; }
        else if (seg == 2) { src = Wv; dst = Bqkv + (size_t)4096 * KC; }
        else               { src = Wo; dst = Bo; }
    }
    size_t i = (size_t)off * 1024 + threadIdx.x * 4;
    float4 v = *(const float4*)(src + i);
    __half2 a = __floats2half2_rn(v.x, v.y);
    __half2 b = __floats2half2_rn(v.z, v.w);
    *(__half2*)(dst + i)     = a;
    *(__half2*)(dst + i + 2) = b;
}

// ---------------------------------------------------------------------------
// fp16 HMMA GEMM, K=2048. B fragments via ldmatrix.x4 (2 n-blocks/op).
//  MODE 0: Wo projection — plain fp32 C stores.
//  MODE 1: fused QKV (N=6144): region 0 Q (RoPE+2-term split), 1 K (RoPE),
//          2 V (fp16 head-gather).
// ---------------------------------------------------------------------------
#define HG_BK 32
#define HG_STG 4
#define HG_STAGE_BYTES 16384
#define HG_SMEM0 (HG_STG * HG_STAGE_BYTES)      // 65536 (MODE 0)
#define HG_PITCH 136
#define HG_SMEM1 (128 * HG_PITCH * 4)           // 69632 (MODE 1)
#define HG_KT (KC / HG_BK)                      // 64

template<int MODE>
__global__ __launch_bounds__(256, 2)
void gemm_f16(const __half* __restrict__ A3, const __half* __restrict__ B3,
              float* __restrict__ C,
              __half* __restrict__ Q2o, __half* __restrict__ K2o,
              __half* __restrict__ Vho, const float2* __restrict__ tab)
{
    extern __shared__ __align__(1024) char smem[];
    const uint32_t sbase = smem_u32(smem);

    const int tid  = threadIdx.x;
    const int lane = tid & 31;
    const int wid  = tid >> 5;
    const int wm   = wid & 1;
    const int wn   = wid >> 1;
    const int bm   = blockIdx.y * 128;
    const int bn   = blockIdx.x * 128;

    const __half* Ag = A3 + (size_t)bm * KC;
    const __half* Bg = B3 + (size_t)bn * KC;

    uint32_t lsw[2];
    const __half* gA[2];
    const __half* gB[2];
#pragma unroll
    for (int p = 0; p < 2; ++p) {
        int idx = tid + p * 256;
        int r = idx >> 2, ch = idx & 3;
        lsw[p] = swz64(r, ch);
        gA[p] = Ag + (size_t)r * KC + ch * 8;
        gB[p] = Bg + (size_t)r * KC + ch * 8;
    }

    uint32_t a_row_off[4];
    int a_swz[4];
#pragma unroll
    for (int mi = 0; mi < 4; ++mi) {
        int r = wm * 64 + mi * 16 + (lane & 15);
        a_row_off[mi] = (uint32_t)(r * 64);
        a_swz[mi] = (r >> 1) & 3;
    }
    const int a_cpart = lane >> 4;
    uint32_t b_row_off[2];
    int b_swz[2];
#pragma unroll
    for (int njp = 0; njp < 2; ++njp) {
        int r = wn * 32 + njp * 16 + ((lane >> 4) & 1) * 8 + (lane & 7);
        b_row_off[njp] = (uint32_t)(r * 64);
        b_swz[njp] = (r >> 1) & 3;
    }
    const int b_cpart = (lane >> 3) & 1;

    float acc[4][4][4];
#pragma unroll
    for (int mi = 0; mi < 4; ++mi)
#pragma unroll
        for (int nj = 0; nj < 4; ++nj)
#pragma unroll
            for (int e = 0; e < 4; ++e) acc[mi][nj][e] = 0.0f;

#pragma unroll
    for (int s = 0; s < HG_STG - 1; ++s) {
        uint32_t sA = sbase + s * HG_STAGE_BYTES;
        uint32_t sB = sA + 8192;
        int k0 = s * HG_BK;
#pragma unroll
        for (int p = 0; p < 2; ++p) {
            CP_ASYNC16(sA + lsw[p], gA[p] + k0);
            CP_ASYNC16(sB + lsw[p], gB[p] + k0);
        }
        CP_COMMIT();
    }

    for (int kt = 0; kt < HG_KT; ++kt) {
        CP_WAIT2();
        __syncthreads();

        int nk = kt + HG_STG - 1;
        if (nk < HG_KT) {
            uint32_t sA = sbase + (nk & 3) * HG_STAGE_BYTES;
            uint32_t sB = sA + 8192;
            int k0 = nk * HG_BK;
#pragma unroll
            for (int p = 0; p < 2; ++p) {
                CP_ASYNC16(sA + lsw[p], gA[p] + k0);
                CP_ASYNC16(sB + lsw[p], gB[p] + k0);
            }
        }
        CP_COMMIT();

        uint32_t sA = sbase + (kt & 3) * HG_STAGE_BYTES;
        uint32_t sB = sA + 8192;
#pragma unroll
        for (int h = 0; h < 2; ++h) {
            uint32_t a0[4], a1[4], a2[4], a3[4];
#pragma unroll
            for (int mi = 0; mi < 4; ++mi) {
                uint32_t addr = sA + a_row_off[mi]
                              + (uint32_t)(((2 * h + a_cpart) ^ a_swz[mi]) << 4);
                LDSM_X4(a0[mi], a1[mi], a2[mi], a3[mi], addr);
            }
            uint32_t b0[4], b1[4];
#pragma unroll
            for (int njp = 0; njp < 2; ++njp) {
                uint32_t addr = sB + b_row_off[njp]
                              + (uint32_t)(((2 * h + b_cpart) ^ b_swz[njp]) << 4);
                LDSM_X4(b0[2 * njp], b1[2 * njp],
                        b0[2 * njp + 1], b1[2 * njp + 1], addr);
            }
#pragma unroll
            for (int mi = 0; mi < 4; ++mi)
#pragma unroll
                for (int nj = 0; nj < 4; ++nj)
                    MMA_16816_F16(acc[mi][nj][0], acc[mi][nj][1],
                                  acc[mi][nj][2], acc[mi][nj][3],
                                  a0[mi], a1[mi], a2[mi], a3[mi],
                                  b0[nj], b1[nj]);
        }
        __syncthreads();
    }

    const int erow = (lane >> 2);
    const int ecol = (lane & 3) * 2;
    const int region  = (MODE == 1) ? (bn >> 11) : 0;
    const int colbase = bn - region * 2048;

    if (MODE == 0) {
#pragma unroll
        for (int mi = 0; mi < 4; ++mi)
#pragma unroll
            for (int nj = 0; nj < 4; ++nj) {
                int row = bm + wm * 64 + mi * 16 + erow;
                int col = colbase + wn * 32 + nj * 8 + ecol;
                *(float2*)(C + (size_t)row * PD + col) =
                    make_float2(acc[mi][nj][0], acc[mi][nj][1]);
                *(float2*)(C + (size_t)(row + 8) * PD + col) =
                    make_float2(acc[mi][nj][2], acc[mi][nj][3]);
            }
    } else if (region == 2) {
#pragma unroll
        for (int mi = 0; mi < 4; ++mi)
#pragma unroll
            for (int nj = 0; nj < 4; ++nj) {
                int row = bm + wm * 64 + mi * 16 + erow;
                int col = colbase + wn * 32 + nj * 8 + ecol;
                int b = row >> 11, s = row & 2047;
                int h = col >> 7, hd = col & 127;
                size_t dst = ((size_t)(b * PH + h) * PS + s) * PHD + hd;
                *(__half2*)(Vho + dst) = __float22half2_rn(
                    make_float2(acc[mi][nj][0], acc[mi][nj][1]));
                *(__half2*)(Vho + dst + 8 * PHD) = __float22half2_rn(
                    make_float2(acc[mi][nj][2], acc[mi][nj][3]));
            }
    } else {
        // Q/K: smem stage + RoPE + fp16 emit (Q 2-term 256-wide, K 128-wide)
        float* tile = (float*)smem;
#pragma unroll
        for (int mi = 0; mi < 4; ++mi)
#pragma unroll
            for (int nj = 0; nj < 4; ++nj) {
                int r = wm * 64 + mi * 16 + erow;
                int c = wn * 32 + nj * 8 + ecol;
                *(float2*)(tile + r * HG_PITCH + c) =
                    make_float2(acc[mi][nj][0], acc[mi][nj][1]);
                *(float2*)(tile + (r + 8) * HG_PITCH + c) =
                    make_float2(acc[mi][nj][2], acc[mi][nj][3]);
            }
        __syncthreads();

        const int hh = colbase >> 7;
        const int b  = bm >> 11;
        const int s0 = bm & 2047;
        const int rg = tid >> 6;
        const int ii = tid & 63;
        if (region == 0) {
            __half* dst = Q2o + (size_t)(b * PH + hh) * PS * 256;
#pragma unroll 4
            for (int rr = 0; rr < 32; ++rr) {
                int r = rg * 32 + rr;
                float x0 = tile[r * HG_PITCH + ii];
                float x1 = tile[r * HG_PITCH + 64 + ii];
                int s = s0 + r;
                float2 cs = tab[s * 64 + ii];
                float o0 = (x0 * cs.x - x1 * cs.y) * ATT_SCALE;
                float o1 = (x1 * cs.x + x0 * cs.y) * ATT_SCALE;
                __half* o = dst + (size_t)s * 256;
                __half h0 = __float2half(o0), h1 = __float2half(o1);
                o[ii]       = h0;
                o[64 + ii]  = h1;
                o[128 + ii] = __float2half(o0 - __half2float(h0));
                o[192 + ii] = __float2half(o1 - __half2float(h1));
            }
        } else {
            __half* dst = K2o + (size_t)(b * PH + hh) * PS * 128;
#pragma unroll 4
            for (int rr = 0; rr < 32; ++rr) {
                int r = rg * 32 + rr;
                float x0 = tile[r * HG_PITCH + ii];
                float x1 = tile[r * HG_PITCH + 64 + ii];
                int s = s0 + r;
                float2 cs = tab[s * 64 + ii];
                __half* o = dst + (size_t)s * 128;
                o[ii]      = __float2half(x0 * cs.x - x1 * cs.y);
                o[64 + ii] = __float2half(x1 * cs.x + x0 * cs.y);
            }
        }
    }
}

// ---------------------------------------------------------------------------
// Tensor-core causal flash attention, 64q x 64k tiles, 2 CTAs/SM.
// K stored ONCE (kh); Q 2-term ([qh|ql]) reusing each B fragment.
// Epilogue emits plain fp16 into AXO (KC-wide).
// ---------------------------------------------------------------------------
#define BTS_Q  0          // 8 panels x 4096 = 32768
#define BTS_K  32768      // 4 panels x 4096 = 16384
#define BTS_V  49152      // 16384
#define BTS_P  65536      // 2 panels x 4096 = 8192
#define BTS_R0 73728      // 512 B (rowmax partials)
#define BTS_R1 74240      // 512 B (rowsum partials)
#define ATT_SMEM 74752

__global__ __launch_bounds__(256, 2)
void attn_tc(const __half* __restrict__ Q2,
             const __half* __restrict__ K2g,
             const __half* __restrict__ Vh,
             __half* __restrict__ AXO)
{
    extern __shared__ __align__(1024) char sm[];
    const uint32_t sb = smem_u32(sm);
    float* red0 = (float*)(sm + BTS_R0);
    float* red1 = (float*)(sm + BTS_R1);

    const int tid  = threadIdx.x;
    const int lane = tid & 31;
    const int w    = tid >> 5;
    const int rg   = w & 3;
    const int cg   = w >> 2;
    const int qt   = 31 - (int)blockIdx.x;
    const int bh   = blockIdx.y;
    const int qb   = qt * 64;
    const int nkt  = qt + 1;

    const __half* q2 = Q2 + ((size_t)bh * PS + qb) * 256;
    const __half* k2 = K2g + (size_t)bh * PS * 128;
    const __half* vh = Vh + (size_t)bh * PS * PHD;

    {
        int r = tid >> 2, ch = tid & 3;
        uint32_t sw = swz64(r, ch);
#pragma unroll
        for (int p = 0; p < 8; ++p)
            CP_ASYNC16(sb + BTS_Q + p * 4096 + sw,
                       q2 + (size_t)r * 256 + p * 32 + ch * 8);
#pragma unroll
        for (int p = 0; p < 4; ++p)
            CP_ASYNC16(sb + BTS_K + p * 4096 + sw,
                       k2 + (size_t)r * 128 + p * 32 + ch * 8);
#pragma unroll
        for (int ps = 0; ps < 4; ++ps) {
            int idx = tid + ps * 256;
            int rr = idx >> 4, cc = idx & 15;
            CP_ASYNC16(sb + BTS_V + swzV(rr, cc), vh + (size_t)rr * PHD + cc * 8);
        }
    }
    CP_COMMIT();

    float m0 = -INFINITY, m1 = -INFINITY, l0 = 0.0f, l1 = 0.0f;
    float oa[8][4];
#pragma unroll
    for (int j = 0; j < 8; ++j)
#pragma unroll
        for (int e = 0; e < 4; ++e) oa[j][e] = 0.0f;

    const int arow  = rg * 16 + (lane & 15);
    const int aswz  = (arow >> 1) & 3;
    const int acp   = lane >> 4;
    const int r0    = rg * 16 + (lane >> 2);
    const int prow0 = r0;
    const int prow1 = r0 + 8;
    const int pswz0 = (prow0 >> 1) & 3;
    const int pswz1 = (prow1 >> 1) & 3;
    const int vkb   = (lane & 7) + 8 * ((lane >> 3) & 1);

    for (int kt = 0; kt < nkt; ++kt) {
        CP_WAIT0();
        __syncthreads();

        float sa[4][4];
#pragma unroll
        for (int j = 0; j < 4; ++j)
#pragma unroll
            for (int e = 0; e < 4; ++e) sa[j][e] = 0.0f;

#pragma unroll
        for (int p = 0; p < 4; ++p) {
#pragma unroll
            for (int h = 0; h < 2; ++h) {
                uint32_t aoff = (uint32_t)(((2 * h + acp) ^ aswz) << 4);
                uint32_t ah0, ah1, ah2, ah3, al0, al1, al2, al3;
                LDSM_X4(ah0, ah1, ah2, ah3,
                        sb + BTS_Q + p * 4096 + arow * 64 + aoff);
                LDSM_X4(al0, al1, al2, al3,
                        sb + BTS_Q + (p + 4) * 4096 + arow * 64 + aoff);
#pragma unroll
                for (int jj = 0; jj < 2; ++jj) {
                    int brow = cg * 32 + jj * 16 + (lane & 15);
                    uint32_t b0, b1, b2, b3;
                    LDSM_X4(b0, b1, b2, b3,
                            sb + BTS_K + p * 4096 + brow * 64
                               + (((2 * h + acp) ^ ((brow >> 1) & 3)) << 4));
                    MMA_16816_F16(sa[2 * jj][0], sa[2 * jj][1],
                                  sa[2 * jj][2], sa[2 * jj][3],
                                  ah0, ah1, ah2, ah3, b0, b2);
                    MMA_16816_F16(sa[2 * jj + 1][0], sa[2 * jj + 1][1],
                                  sa[2 * jj + 1][2], sa[2 * jj + 1][3],
                                  ah0, ah1, ah2, ah3, b1, b3);
                    MMA_16816_F16(sa[2 * jj][0], sa[2 * jj][1],
                                  sa[2 * jj][2], sa[2 * jj][3],
                                  al0, al1, al2, al3, b0, b2);
                    MMA_16816_F16(sa[2 * jj + 1][0], sa[2 * jj + 1][1],
                                  sa[2 * jj + 1][2], sa[2 * jj + 1][3],
                                  al0, al1, al2, al3, b1, b3);
                }
            }
        }
        __syncthreads();

        if (kt + 1 < nkt) {
            const __half* kp = k2 + (size_t)(kt + 1) * 64 * 128;
            int r = tid >> 2, ch = tid & 3;
            uint32_t sw = swz64(r, ch);
#pragma unroll
            for (int p = 0; p < 4; ++p)
                CP_ASYNC16(sb + BTS_K + p * 4096 + sw,
                           kp + (size_t)r * 128 + p * 32 + ch * 8);
        }
        CP_COMMIT();

        if (kt == qt) {
            const int gr0 = qb + r0;
            const int gr1 = gr0 + 8;
            const int kb = kt * 64;
#pragma unroll
            for (int nj = 0; nj < 4; ++nj) {
                int c0 = kb + cg * 32 + nj * 8 + 2 * (lane & 3);
                if (c0 > gr0)     sa[nj][0] = -INFINITY;
                if (c0 + 1 > gr0) sa[nj][1] = -INFINITY;
                if (c0 > gr1)     sa[nj][2] = -INFINITY;
                if (c0 + 1 > gr1) sa[nj][3] = -INFINITY;
            }
        }

        float pm0 = -INFINITY, pm1 = -INFINITY;
#pragma unroll
        for (int nj = 0; nj < 4; ++nj) {
            pm0 = fmaxf(pm0, fmaxf(sa[nj][0], sa[nj][1]));
            pm1 = fmaxf(pm1, fmaxf(sa[nj][2], sa[nj][3]));
        }
        pm0 = fmaxf(pm0, __shfl_xor_sync(0xffffffffu, pm0, 1));
        pm0 = fmaxf(pm0, __shfl_xor_sync(0xffffffffu, pm0, 2));
        pm1 = fmaxf(pm1, __shfl_xor_sync(0xffffffffu, pm1, 1));
        pm1 = fmaxf(pm1, __shfl_xor_sync(0xffffffffu, pm1, 2));
        if ((lane & 3) == 0) {
            red0[cg * 64 + prow0] = pm0;
            red0[cg * 64 + prow1] = pm1;
        }
        __syncthreads();
        float rm0 = fmaxf(red0[prow0], red0[64 + prow0]);
        float rm1 = fmaxf(red0[prow1], red0[64 + prow1]);

        float mn0 = fmaxf(m0, rm0);
        float mn1 = fmaxf(m1, rm1);
        float corr0 = __expf(m0 - mn0);
        float corr1 = __expf(m1 - mn1);
        m0 = mn0; m1 = mn1;
#pragma unroll
        for (int j = 0; j < 8; ++j) {
            oa[j][0] *= corr0; oa[j][1] *= corr0;
            oa[j][2] *= corr1; oa[j][3] *= corr1;
        }

        float ps0 = 0.0f, ps1 = 0.0f;
#pragma unroll
        for (int nj = 0; nj < 4; ++nj) {
            float p0 = __expf(sa[nj][0] - mn0);
            float p1 = __expf(sa[nj][1] - mn0);
            float p2 = __expf(sa[nj][2] - mn1);
            float p3 = __expf(sa[nj][3] - mn1);
            ps0 += p0 + p1;
            ps1 += p2 + p3;
            int kin = nj * 8 + 2 * (lane & 3);
            uint32_t inoff = (uint32_t)((kin >> 3) << 4) + ((kin & 7) << 1);
            uint32_t ba0 = (uint32_t)(BTS_P + cg * 4096) + prow0 * 64
                         + ((inoff & 0xF0u) ^ (pswz0 << 4)) + (inoff & 0xFu);
            uint32_t ba1 = (uint32_t)(BTS_P + cg * 4096) + prow1 * 64
                         + ((inoff & 0xF0u) ^ (pswz1 << 4)) + (inoff & 0xFu);
            *(__half2*)(sm + ba0) = __float22half2_rn(make_float2(p0, p1));
            *(__half2*)(sm + ba1) = __float22half2_rn(make_float2(p2, p3));
        }
        ps0 += __shfl_xor_sync(0xffffffffu, ps0, 1);
        ps0 += __shfl_xor_sync(0xffffffffu, ps0, 2);
        ps1 += __shfl_xor_sync(0xffffffffu, ps1, 1);
        ps1 += __shfl_xor_sync(0xffffffffu, ps1, 2);
        if ((lane & 3) == 0) {
            red1[cg * 64 + prow0] = ps0;
            red1[cg * 64 + prow1] = ps1;
        }
        __syncthreads();
        l0 = l0 * corr0 + red1[prow0] + red1[64 + prow0];
        l1 = l1 * corr1 + red1[prow1] + red1[64 + prow1];

#pragma unroll
        for (int s = 0; s < 4; ++s) {
            uint32_t a0, a1, a2, a3;
            LDSM_X4(a0, a1, a2, a3,
                    sb + BTS_P + (s >> 1) * 4096 + arow * 64
                       + (((2 * (s & 1) + acp) ^ aswz) << 4));
            int vk = s * 16 + vkb;
#pragma unroll
            for (int gg = 0; gg < 4; ++gg) {
                int gp = cg * 4 + gg;
                uint32_t b0, b1, b2, b3;
                LDSM_X4T(b0, b1, b2, b3,
                         sb + BTS_V + vk * 256
                            + ((((2 * gp + (lane >> 4)) ^ (vk & 7))) << 4));
                MMA_16816_F16(oa[2 * gg][0], oa[2 * gg][1],
                              oa[2 * gg][2], oa[2 * gg][3],
                              a0, a1, a2, a3, b0, b1);
                MMA_16816_F16(oa[2 * gg + 1][0], oa[2 * gg + 1][1],
                              oa[2 * gg + 1][2], oa[2 * gg + 1][3],
                              a0, a1, a2, a3, b2, b3);
            }
        }
        __syncthreads();

        if (kt + 1 < nkt) {
            const __half* va = vh + (size_t)(kt + 1) * 64 * PHD;
#pragma unroll
            for (int ps = 0; ps < 4; ++ps) {
                int idx = tid + ps * 256;
                int rr = idx >> 4, cc = idx & 15;
                CP_ASYNC16(sb + BTS_V + swzV(rr, cc), va + (size_t)rr * PHD + cc * 8);
            }
        }
        CP_COMMIT();
    }

    // ---- epilogue: plain fp16 into AXO [PM x 2048]
    const float inv0 = 1.0f / l0;
    const float inv1 = 1.0f / l1;
    const int b = bh >> 4, h = bh & 15;
    const size_t row0 = (size_t)b * PS + qb + r0;
    const size_t row1 = row0 + 8;
#pragma unroll
    for (int j = 0; j < 8; ++j) {
        int col = h * PHD + cg * 64 + j * 8 + 2 * (lane & 3);
        __half2 h20 = __float22half2_rn(
            make_float2(oa[j][0] * inv0, oa[j][1] * inv0));
        __half2 h21 = __float22half2_rn(
            make_float2(oa[j][2] * inv1, oa[j][3] * inv1));
        *(__half2*)(AXO + row0 * KC + col) = h20;
        *(__half2*)(AXO + row1 * KC + col) = h21;
    }
}

// ---------------------------------------------------------------------------
// kernel_launch
// ---------------------------------------------------------------------------
extern "C" void kernel_launch(void* const* d_in, const int* in_sizes, int n_in,
                              void* d_out, int out_size)
{
    const float* x  = (const float*)d_in[0];
    const float* Wq = (const float*)d_in[1];
    const float* Wk = (const float*)d_in[2];
    const float* Wv = (const float*)d_in[3];
    const float* Wo = (const float*)d_in[4];
    float* out = (float*)d_out;

    __half *Axp, *Bqkvp, *Bop, *AxOp, *Q2p, *K2p, *Vhp;
    float2* tabp;
    cudaGetSymbolAddress((void**)&Axp,   g_Ax);
    cudaGetSymbolAddress((void**)&Bqkvp, g_Bqkv);
    cudaGetSymbolAddress((void**)&Bop,   g_Bo);
    cudaGetSymbolAddress((void**)&AxOp,  g_AxO);
    cudaGetSymbolAddress((void**)&Q2p,   g_Q2h);
    cudaGetSymbolAddress((void**)&K2p,   g_K2h);
    cudaGetSymbolAddress((void**)&Vhp,   g_Vh);
    cudaGetSymbolAddress((void**)&tabp,  g_tab);

    cudaFuncSetAttribute((const void*)gemm_f16<0>,
                         cudaFuncAttributeMaxDynamicSharedMemorySize, HG_SMEM0);
    cudaFuncSetAttribute((const void*)gemm_f16<1>,
                         cudaFuncAttributeMaxDynamicSharedMemorySize, HG_SMEM1);
    cudaFuncSetAttribute((const void*)attn_tc,
                         cudaFuncAttributeMaxDynamicSharedMemorySize, ATT_SMEM);

    // RoPE tables + all fp16 converts
    rope_tables<<<512, 256>>>(tabp);
    convert_all<<<8192 + 4 * 4096, 256>>>(x, Wq, Wk, Wv, Wo, Axp, Bqkvp, Bop);

    // fused QKV projection (N = 6144) with RoPE/split epilogue
    gemm_f16<1><<<dim3(NQKV / 128, PM / 128), 256, HG_SMEM1>>>(
        Axp, Bqkvp, nullptr, Q2p, K2p, Vhp, tabp);

    // attention (64-query tiles, deduped K, 2 CTAs/SM)
    attn_tc<<<dim3(PS / 64, PB * PH), 256, ATT_SMEM>>>(Q2p, K2p, Vhp, AxOp);

    // Wo projection
    gemm_f16<0><<<dim3(PD / 128, PM / 128), 256, HG_SMEM0>>>(
        AxOp, Bop, out, nullptr, nullptr, nullptr, nullptr);
}

// round 14
// speedup vs baseline: 5.0667x; 1.0678x over previous
#include <cuda_runtime.h>
#include <cuda_fp16.h>
#include <math.h>
#include <stdint.h>

// ---------------------------------------------------------------------------
// Problem constants
// ---------------------------------------------------------------------------
#define PB 2
#define PS 2048
#define PD 2048
#define PH 16
#define PHD 128
#define PM (PB * PS)          // 4096 rows
#define KC 2048               // GEMM K (plain fp16)
#define NQKV (3 * PD)         // 6144: fused QKV output columns
#define ATT_SCALE 0.08838834764831845f

// ---------------------------------------------------------------------------
// Scratch (device globals; no allocation allowed)
// ---------------------------------------------------------------------------
__device__ __half g_Ax[(size_t)PM * KC];                 // x, fp16
__device__ __half g_Bqkv[(size_t)NQKV * KC];             // [Wq;Wk;Wv] fp16
__device__ __half g_Bo[(size_t)PD * KC];                 // Wo fp16
__device__ __half g_AxO[(size_t)PM * KC];                // attn out fp16
__device__ __half g_Qh[(size_t)PB * PH * PS * 128];      // qh*scale
__device__ __half g_Kh[(size_t)PB * PH * PS * 128];      // kh
__device__ __half g_Vh[(size_t)PB * PH * PS * PHD];
__device__ float2 g_tab[PS * 64];                        // {cos, sin}

// ---------------------------------------------------------------------------
// PTX helpers (sm_80-compatible: cp.async + ldmatrix + mma.sync)
// ---------------------------------------------------------------------------
__device__ __forceinline__ uint32_t smem_u32(const void* p) {
    uint32_t a;
    asm("{ .reg .u64 t; cvta.to.shared.u64 t, %1; cvt.u32.u64 %0, t; }"
        : "=r"(a) : "l"(p));
    return a;
}

#define CP_ASYNC16(smem, gptr) \
    asm volatile("cp.async.cg.shared.global [%0], [%1], 16;" \
                 :: "r"(smem), "l"(gptr) : "memory")
#define CP_COMMIT() asm volatile("cp.async.commit_group;" ::: "memory")
#define CP_WAIT2()  asm volatile("cp.async.wait_group 2;" ::: "memory")
#define CP_WAIT0()  asm volatile("cp.async.wait_group 0;" ::: "memory")

#define LDSM_X4(r0, r1, r2, r3, addr) \
    asm volatile("ldmatrix.sync.aligned.m8n8.x4.shared.b16 {%0,%1,%2,%3}, [%4];" \
                 : "=r"(r0), "=r"(r1), "=r"(r2), "=r"(r3) : "r"(addr))
#define LDSM_X4T(r0, r1, r2, r3, addr) \
    asm volatile("ldmatrix.sync.aligned.m8n8.x4.trans.shared.b16 {%0,%1,%2,%3}, [%4];" \
                 : "=r"(r0), "=r"(r1), "=r"(r2), "=r"(r3) : "r"(addr))

#define MMA_16816_F16(c0, c1, c2, c3, a0, a1, a2, a3, b0, b1) \
    asm volatile("mma.sync.aligned.m16n8k16.row.col.f32.f16.f16.f32 " \
                 "{%0,%1,%2,%3}, {%4,%5,%6,%7}, {%8,%9}, {%0,%1,%2,%3};" \
                 : "+f"(c0), "+f"(c1), "+f"(c2), "+f"(c3) \
                 : "r"(a0), "r"(a1), "r"(a2), "r"(a3), "r"(b0), "r"(b1))

// swizzles
__device__ __forceinline__ uint32_t swz64(int r, int ch) {   // 64B rows, 4x16B chunks
    return (uint32_t)(r * 64 + (((ch) ^ ((r >> 1) & 3)) << 4));
}
__device__ __forceinline__ uint32_t swzV(int r, int ch) {    // 256B rows, 16x16B chunks
    return (uint32_t)(r * 256 + (((ch) ^ (r & 7)) << 4));
}

// ---------------------------------------------------------------------------
// RoPE tables: invf = exp(-j/64 * ln(10000)) (fp64); angle fp32-rounded chain.
// ---------------------------------------------------------------------------
__global__ __launch_bounds__(256)
void rope_tables(float2* __restrict__ tab)
{
    int idx = blockIdx.x * blockDim.x + threadIdx.x;   // 131072
    int s = idx >> 6;
    int j = idx & 63;
    double invf_d = exp(-(double)j * (9.210340371976184 / 64.0));
    float ang = (float)s * (float)invf_d;
    double cs, sn;
    sincos((double)ang, &sn, &cs);
    tab[idx] = make_float2((float)cs, (float)sn);
}

// ---------------------------------------------------------------------------
// Merged converts: fp32 -> fp16 (plain cast).
// ---------------------------------------------------------------------------
__global__ __launch_bounds__(256)
void convert_all(const float* __restrict__ x,
                 const float* __restrict__ Wq, const float* __restrict__ Wk,
                 const float* __restrict__ Wv, const float* __restrict__ Wo,
                 __half* __restrict__ Ax, __half* __restrict__ Bqkv,
                 __half* __restrict__ Bo)
{
    int bid = blockIdx.x;
    const float* src;
    __half* dst;
    int off;
    if (bid < 8192) {
        src = x; dst = Ax; off = bid;
    } else {
        int seg = (bid - 8192) >> 12;
        off = bid - 8192 - seg * 4096;
        if (seg == 0)      { src = Wq; dst = Bqkv; }
        else if (seg == 1) { src = Wk; dst = Bqkv + (size_t)2048 * KC; }
        else if (seg == 2) { src = Wv; dst = Bqkv + (size_t)4096 * KC; }
        else               { src = Wo; dst = Bo; }
    }
    size_t i = (size_t)off * 1024 + threadIdx.x * 4;
    float4 v = *(const float4*)(src + i);
    __half2 a = __floats2half2_rn(v.x, v.y);
    __half2 b = __floats2half2_rn(v.z, v.w);
    *(__half2*)(dst + i)     = a;
    *(__half2*)(dst + i + 2) = b;
}

// ---------------------------------------------------------------------------
// fp16 HMMA GEMM, K=2048. B fragments via ldmatrix.x4 (2 n-blocks/op).
//  MODE 0: Wo projection — plain fp32 C stores.
//  MODE 1: fused QKV (N=6144): region 0 Q (RoPE+scale), 1 K (RoPE),
//          2 V (fp16 head-gather).
// ---------------------------------------------------------------------------
#define HG_BK 32
#define HG_STG 4
#define HG_STAGE_BYTES 16384
#define HG_SMEM0 (HG_STG * HG_STAGE_BYTES)      // 65536 (MODE 0)
#define HG_PITCH 136
#define HG_SMEM1 (128 * HG_PITCH * 4)           // 69632 (MODE 1)
#define HG_KT (KC / HG_BK)                      // 64

template<int MODE>
__global__ __launch_bounds__(256, 2)
void gemm_f16(const __half* __restrict__ A3, const __half* __restrict__ B3,
              float* __restrict__ C,
              __half* __restrict__ Qho, __half* __restrict__ Kho,
              __half* __restrict__ Vho, const float2* __restrict__ tab)
{
    extern __shared__ __align__(1024) char smem[];
    const uint32_t sbase = smem_u32(smem);

    const int tid  = threadIdx.x;
    const int lane = tid & 31;
    const int wid  = tid >> 5;
    const int wm   = wid & 1;
    const int wn   = wid >> 1;
    const int bm   = blockIdx.y * 128;
    const int bn   = blockIdx.x * 128;

    const __half* Ag = A3 + (size_t)bm * KC;
    const __half* Bg = B3 + (size_t)bn * KC;

    uint32_t lsw[2];
    const __half* gA[2];
    const __half* gB[2];
#pragma unroll
    for (int p = 0; p < 2; ++p) {
        int idx = tid + p * 256;
        int r = idx >> 2, ch = idx & 3;
        lsw[p] = swz64(r, ch);
        gA[p] = Ag + (size_t)r * KC + ch * 8;
        gB[p] = Bg + (size_t)r * KC + ch * 8;
    }

    uint32_t a_row_off[4];
    int a_swz[4];
#pragma unroll
    for (int mi = 0; mi < 4; ++mi) {
        int r = wm * 64 + mi * 16 + (lane & 15);
        a_row_off[mi] = (uint32_t)(r * 64);
        a_swz[mi] = (r >> 1) & 3;
    }
    const int a_cpart = lane >> 4;
    uint32_t b_row_off[2];
    int b_swz[2];
#pragma unroll
    for (int njp = 0; njp < 2; ++njp) {
        int r = wn * 32 + njp * 16 + ((lane >> 4) & 1) * 8 + (lane & 7);
        b_row_off[njp] = (uint32_t)(r * 64);
        b_swz[njp] = (r >> 1) & 3;
    }
    const int b_cpart = (lane >> 3) & 1;

    float acc[4][4][4];
#pragma unroll
    for (int mi = 0; mi < 4; ++mi)
#pragma unroll
        for (int nj = 0; nj < 4; ++nj)
#pragma unroll
            for (int e = 0; e < 4; ++e) acc[mi][nj][e] = 0.0f;

#pragma unroll
    for (int s = 0; s < HG_STG - 1; ++s) {
        uint32_t sA = sbase + s * HG_STAGE_BYTES;
        uint32_t sB = sA + 8192;
        int k0 = s * HG_BK;
#pragma unroll
        for (int p = 0; p < 2; ++p) {
            CP_ASYNC16(sA + lsw[p], gA[p] + k0);
            CP_ASYNC16(sB + lsw[p], gB[p] + k0);
        }
        CP_COMMIT();
    }

    for (int kt = 0; kt < HG_KT; ++kt) {
        CP_WAIT2();
        __syncthreads();

        int nk = kt + HG_STG - 1;
        if (nk < HG_KT) {
            uint32_t sA = sbase + (nk & 3) * HG_STAGE_BYTES;
            uint32_t sB = sA + 8192;
            int k0 = nk * HG_BK;
#pragma unroll
            for (int p = 0; p < 2; ++p) {
                CP_ASYNC16(sA + lsw[p], gA[p] + k0);
                CP_ASYNC16(sB + lsw[p], gB[p] + k0);
            }
        }
        CP_COMMIT();

        uint32_t sA = sbase + (kt & 3) * HG_STAGE_BYTES;
        uint32_t sB = sA + 8192;
#pragma unroll
        for (int h = 0; h < 2; ++h) {
            uint32_t a0[4], a1[4], a2[4], a3[4];
#pragma unroll
            for (int mi = 0; mi < 4; ++mi) {
                uint32_t addr = sA + a_row_off[mi]
                              + (uint32_t)(((2 * h + a_cpart) ^ a_swz[mi]) << 4);
                LDSM_X4(a0[mi], a1[mi], a2[mi], a3[mi], addr);
            }
            uint32_t b0[4], b1[4];
#pragma unroll
            for (int njp = 0; njp < 2; ++njp) {
                uint32_t addr = sB + b_row_off[njp]
                              + (uint32_t)(((2 * h + b_cpart) ^ b_swz[njp]) << 4);
                LDSM_X4(b0[2 * njp], b1[2 * njp],
                        b0[2 * njp + 1], b1[2 * njp + 1], addr);
            }
#pragma unroll
            for (int mi = 0; mi < 4; ++mi)
#pragma unroll
                for (int nj = 0; nj < 4; ++nj)
                    MMA_16816_F16(acc[mi][nj][0], acc[mi][nj][1],
                                  acc[mi][nj][2], acc[mi][nj][3],
                                  a0[mi], a1[mi], a2[mi], a3[mi],
                                  b0[nj], b1[nj]);
        }
        __syncthreads();
    }

    const int erow = (lane >> 2);
    const int ecol = (lane & 3) * 2;
    const int region  = (MODE == 1) ? (bn >> 11) : 0;
    const int colbase = bn - region * 2048;

    if (MODE == 0) {
#pragma unroll
        for (int mi = 0; mi < 4; ++mi)
#pragma unroll
            for (int nj = 0; nj < 4; ++nj) {
                int row = bm + wm * 64 + mi * 16 + erow;
                int col = colbase + wn * 32 + nj * 8 + ecol;
                *(float2*)(C + (size_t)row * PD + col) =
                    make_float2(acc[mi][nj][0], acc[mi][nj][1]);
                *(float2*)(C + (size_t)(row + 8) * PD + col) =
                    make_float2(acc[mi][nj][2], acc[mi][nj][3]);
            }
    } else if (region == 2) {
#pragma unroll
        for (int mi = 0; mi < 4; ++mi)
#pragma unroll
            for (int nj = 0; nj < 4; ++nj) {
                int row = bm + wm * 64 + mi * 16 + erow;
                int col = colbase + wn * 32 + nj * 8 + ecol;
                int b = row >> 11, s = row & 2047;
                int h = col >> 7, hd = col & 127;
                size_t dst = ((size_t)(b * PH + h) * PS + s) * PHD + hd;
                *(__half2*)(Vho + dst) = __float22half2_rn(
                    make_float2(acc[mi][nj][0], acc[mi][nj][1]));
                *(__half2*)(Vho + dst + 8 * PHD) = __float22half2_rn(
                    make_float2(acc[mi][nj][2], acc[mi][nj][3]));
            }
    } else {
        // Q/K: smem stage + RoPE + fp16 emit (both 128-wide; Q scaled)
        float* tile = (float*)smem;
#pragma unroll
        for (int mi = 0; mi < 4; ++mi)
#pragma unroll
            for (int nj = 0; nj < 4; ++nj) {
                int r = wm * 64 + mi * 16 + erow;
                int c = wn * 32 + nj * 8 + ecol;
                *(float2*)(tile + r * HG_PITCH + c) =
                    make_float2(acc[mi][nj][0], acc[mi][nj][1]);
                *(float2*)(tile + (r + 8) * HG_PITCH + c) =
                    make_float2(acc[mi][nj][2], acc[mi][nj][3]);
            }
        __syncthreads();

        const int hh = colbase >> 7;
        const int b  = bm >> 11;
        const int s0 = bm & 2047;
        const int rg = tid >> 6;
        const int ii = tid & 63;
        const float sc = (region == 0) ? ATT_SCALE : 1.0f;
        __half* dst = (region == 0 ? Qho : Kho)
                    + (size_t)(b * PH + hh) * PS * 128;
#pragma unroll 4
        for (int rr = 0; rr < 32; ++rr) {
            int r = rg * 32 + rr;
            float x0 = tile[r * HG_PITCH + ii];
            float x1 = tile[r * HG_PITCH + 64 + ii];
            int s = s0 + r;
            float2 cs = tab[s * 64 + ii];
            __half* o = dst + (size_t)s * 128;
            o[ii]      = __float2half((x0 * cs.x - x1 * cs.y) * sc);
            o[64 + ii] = __float2half((x1 * cs.x + x0 * cs.y) * sc);
        }
    }
}

// ---------------------------------------------------------------------------
// Tensor-core causal flash attention, 64q x 64k tiles, plain fp16 operands.
// 8 warps = 4 row-groups x 2 col-groups. 2 CTAs/SM.
// ---------------------------------------------------------------------------
#define BTS_Q  0          // 4 panels x 4096 = 16384
#define BTS_K  16384      // 4 panels x 4096 = 16384
#define BTS_V  32768      // 16384
#define BTS_P  49152      // 2 panels x 4096 = 8192
#define BTS_R0 57344      // 512 B (rowmax partials)
#define BTS_R1 57856      // 512 B (rowsum partials)
#define ATT_SMEM 58368

__global__ __launch_bounds__(256, 2)
void attn_tc(const __half* __restrict__ Qh,
             const __half* __restrict__ Kh,
             const __half* __restrict__ Vh,
             __half* __restrict__ AXO)
{
    extern __shared__ __align__(1024) char sm[];
    const uint32_t sb = smem_u32(sm);
    float* red0 = (float*)(sm + BTS_R0);
    float* red1 = (float*)(sm + BTS_R1);

    const int tid  = threadIdx.x;
    const int lane = tid & 31;
    const int w    = tid >> 5;
    const int rg   = w & 3;
    const int cg   = w >> 2;
    const int qt   = 31 - (int)blockIdx.x;
    const int bh   = blockIdx.y;
    const int qb   = qt * 64;
    const int nkt  = qt + 1;

    const __half* qh = Qh + ((size_t)bh * PS + qb) * 128;
    const __half* k2 = Kh + (size_t)bh * PS * 128;
    const __half* vh = Vh + (size_t)bh * PS * PHD;

    {
        int r = tid >> 2, ch = tid & 3;
        uint32_t sw = swz64(r, ch);
#pragma unroll
        for (int p = 0; p < 4; ++p)
            CP_ASYNC16(sb + BTS_Q + p * 4096 + sw,
                       qh + (size_t)r * 128 + p * 32 + ch * 8);
#pragma unroll
        for (int p = 0; p < 4; ++p)
            CP_ASYNC16(sb + BTS_K + p * 4096 + sw,
                       k2 + (size_t)r * 128 + p * 32 + ch * 8);
#pragma unroll
        for (int ps = 0; ps < 4; ++ps) {
            int idx = tid + ps * 256;
            int rr = idx >> 4, cc = idx & 15;
            CP_ASYNC16(sb + BTS_V + swzV(rr, cc), vh + (size_t)rr * PHD + cc * 8);
        }
    }
    CP_COMMIT();

    float m0 = -INFINITY, m1 = -INFINITY, l0 = 0.0f, l1 = 0.0f;
    float oa[8][4];
#pragma unroll
    for (int j = 0; j < 8; ++j)
#pragma unroll
        for (int e = 0; e < 4; ++e) oa[j][e] = 0.0f;

    const int arow  = rg * 16 + (lane & 15);
    const int aswz  = (arow >> 1) & 3;
    const int acp   = lane >> 4;
    const int r0    = rg * 16 + (lane >> 2);
    const int prow0 = r0;
    const int prow1 = r0 + 8;
    const int pswz0 = (prow0 >> 1) & 3;
    const int pswz1 = (prow1 >> 1) & 3;
    const int vkb   = (lane & 7) + 8 * ((lane >> 3) & 1);

    for (int kt = 0; kt < nkt; ++kt) {
        CP_WAIT0();
        __syncthreads();

        // ---- QK: S[16 x 32] per warp; K'=128, plain fp16
        float sa[4][4];
#pragma unroll
        for (int j = 0; j < 4; ++j)
#pragma unroll
            for (int e = 0; e < 4; ++e) sa[j][e] = 0.0f;

#pragma unroll
        for (int p = 0; p < 4; ++p) {
#pragma unroll
            for (int h = 0; h < 2; ++h) {
                uint32_t a0, a1, a2, a3;
                LDSM_X4(a0, a1, a2, a3,
                        sb + BTS_Q + p * 4096 + arow * 64
                           + (((2 * h + acp) ^ aswz) << 4));
#pragma unroll
                for (int jj = 0; jj < 2; ++jj) {
                    int brow = cg * 32 + jj * 16 + (lane & 15);
                    uint32_t b0, b1, b2, b3;
                    LDSM_X4(b0, b1, b2, b3,
                            sb + BTS_K + p * 4096 + brow * 64
                               + (((2 * h + acp) ^ ((brow >> 1) & 3)) << 4));
                    MMA_16816_F16(sa[2 * jj][0], sa[2 * jj][1],
                                  sa[2 * jj][2], sa[2 * jj][3],
                                  a0, a1, a2, a3, b0, b2);
                    MMA_16816_F16(sa[2 * jj + 1][0], sa[2 * jj + 1][1],
                                  sa[2 * jj + 1][2], sa[2 * jj + 1][3],
                                  a0, a1, a2, a3, b1, b3);
                }
            }
        }
        __syncthreads();

        if (kt + 1 < nkt) {
            const __half* kp = k2 + (size_t)(kt + 1) * 64 * 128;
            int r = tid >> 2, ch = tid & 3;
            uint32_t sw = swz64(r, ch);
#pragma unroll
            for (int p = 0; p < 4; ++p)
                CP_ASYNC16(sb + BTS_K + p * 4096 + sw,
                           kp + (size_t)r * 128 + p * 32 + ch * 8);
        }
        CP_COMMIT();

        if (kt == qt) {
            const int gr0 = qb + r0;
            const int gr1 = gr0 + 8;
            const int kb = kt * 64;
#pragma unroll
            for (int nj = 0; nj < 4; ++nj) {
                int c0 = kb + cg * 32 + nj * 8 + 2 * (lane & 3);
                if (c0 > gr0)     sa[nj][0] = -INFINITY;
                if (c0 + 1 > gr0) sa[nj][1] = -INFINITY;
                if (c0 > gr1)     sa[nj][2] = -INFINITY;
                if (c0 + 1 > gr1) sa[nj][3] = -INFINITY;
            }
        }

        float pm0 = -INFINITY, pm1 = -INFINITY;
#pragma unroll
        for (int nj = 0; nj < 4; ++nj) {
            pm0 = fmaxf(pm0, fmaxf(sa[nj][0], sa[nj][1]));
            pm1 = fmaxf(pm1, fmaxf(sa[nj][2], sa[nj][3]));
        }
        pm0 = fmaxf(pm0, __shfl_xor_sync(0xffffffffu, pm0, 1));
        pm0 = fmaxf(pm0, __shfl_xor_sync(0xffffffffu, pm0, 2));
        pm1 = fmaxf(pm1, __shfl_xor_sync(0xffffffffu, pm1, 1));
        pm1 = fmaxf(pm1, __shfl_xor_sync(0xffffffffu, pm1, 2));
        if ((lane & 3) == 0) {
            red0[cg * 64 + prow0] = pm0;
            red0[cg * 64 + prow1] = pm1;
        }
        __syncthreads();
        float rm0 = fmaxf(red0[prow0], red0[64 + prow0]);
        float rm1 = fmaxf(red0[prow1], red0[64 + prow1]);

        float mn0 = fmaxf(m0, rm0);
        float mn1 = fmaxf(m1, rm1);
        float corr0 = __expf(m0 - mn0);
        float corr1 = __expf(m1 - mn1);
        m0 = mn0; m1 = mn1;
#pragma unroll
        for (int j = 0; j < 8; ++j) {
            oa[j][0] *= corr0; oa[j][1] *= corr0;
            oa[j][2] *= corr1; oa[j][3] *= corr1;
        }

        float ps0 = 0.0f, ps1 = 0.0f;
#pragma unroll
        for (int nj = 0; nj < 4; ++nj) {
            float p0 = __expf(sa[nj][0] - mn0);
            float p1 = __expf(sa[nj][1] - mn0);
            float p2 = __expf(sa[nj][2] - mn1);
            float p3 = __expf(sa[nj][3] - mn1);
            ps0 += p0 + p1;
            ps1 += p2 + p3;
            int kin = nj * 8 + 2 * (lane & 3);
            uint32_t inoff = (uint32_t)((kin >> 3) << 4) + ((kin & 7) << 1);
            uint32_t ba0 = (uint32_t)(BTS_P + cg * 4096) + prow0 * 64
                         + ((inoff & 0xF0u) ^ (pswz0 << 4)) + (inoff & 0xFu);
            uint32_t ba1 = (uint32_t)(BTS_P + cg * 4096) + prow1 * 64
                         + ((inoff & 0xF0u) ^ (pswz1 << 4)) + (inoff & 0xFu);
            *(__half2*)(sm + ba0) = __float22half2_rn(make_float2(p0, p1));
            *(__half2*)(sm + ba1) = __float22half2_rn(make_float2(p2, p3));
        }
        ps0 += __shfl_xor_sync(0xffffffffu, ps0, 1);
        ps0 += __shfl_xor_sync(0xffffffffu, ps0, 2);
        ps1 += __shfl_xor_sync(0xffffffffu, ps1, 1);
        ps1 += __shfl_xor_sync(0xffffffffu, ps1, 2);
        if ((lane & 3) == 0) {
            red1[cg * 64 + prow0] = ps0;
            red1[cg * 64 + prow1] = ps1;
        }
        __syncthreads();
        l0 = l0 * corr0 + red1[prow0] + red1[64 + prow0];
        l1 = l1 * corr1 + red1[prow1] + red1[64 + prow1];

#pragma unroll
        for (int s = 0; s < 4; ++s) {
            uint32_t a0, a1, a2, a3;
            LDSM_X4(a0, a1, a2, a3,
                    sb + BTS_P + (s >> 1) * 4096 + arow * 64
                       + (((2 * (s & 1) + acp) ^ aswz) << 4));
            int vk = s * 16 + vkb;
#pragma unroll
            for (int gg = 0; gg < 4; ++gg) {
                int gp = cg * 4 + gg;
                uint32_t b0, b1, b2, b3;
                LDSM_X4T(b0, b1, b2, b3,
                         sb + BTS_V + vk * 256
                            + ((((2 * gp + (lane >> 4)) ^ (vk & 7))) << 4));
                MMA_16816_F16(oa[2 * gg][0], oa[2 * gg][1],
                              oa[2 * gg][2], oa[2 * gg][3],
                              a0, a1, a2, a3, b0, b1);
                MMA_16816_F16(oa[2 * gg + 1][0], oa[2 * gg + 1][1],
                              oa[2 * gg + 1][2], oa[2 * gg + 1][3],
                              a0, a1, a2, a3, b2, b3);
            }
        }
        __syncthreads();

        if (kt + 1 < nkt) {
            const __half* va = vh + (size_t)(kt + 1) * 64 * PHD;
#pragma unroll
            for (int ps = 0; ps < 4; ++ps) {
                int idx = tid + ps * 256;
                int rr = idx >> 4, cc = idx & 15;
                CP_ASYNC16(sb + BTS_V + swzV(rr, cc), va + (size_t)rr * PHD + cc * 8);
            }
        }
        CP_COMMIT();
    }

    // ---- epilogue: plain fp16 into AXO [PM x 2048]
    const float inv0 = 1.0f / l0;
    const float inv1 = 1.0f / l1;
    const int b = bh >> 4, h = bh & 15;
    const size_t row0 = (size_t)b * PS + qb + r0;
    const size_t row1 = row0 + 8;
#pragma unroll
    for (int j = 0; j < 8; ++j) {
        int col = h * PHD + cg * 64 + j * 8 + 2 * (lane & 3);
        __half2 h20 = __float22half2_rn(
            make_float2(oa[j][0] * inv0, oa[j][1] * inv0));
        __half2 h21 = __float22half2_rn(
            make_float2(oa[j][2] * inv1, oa[j][3] * inv1));
        *(__half2*)(AXO + row0 * KC + col) = h20;
        *(__half2*)(AXO + row1 * KC + col) = h21;
    }
}

// ---------------------------------------------------------------------------
// kernel_launch
// ---------------------------------------------------------------------------
extern "C" void kernel_launch(void* const* d_in, const int* in_sizes, int n_in,
                              void* d_out, int out_size)
{
    const float* x  = (const float*)d_in[0];
    const float* Wq = (const float*)d_in[1];
    const float* Wk = (const float*)d_in[2];
    const float* Wv = (const float*)d_in[3];
    const float* Wo = (const float*)d_in[4];
    float* out = (float*)d_out;

    __half *Axp, *Bqkvp, *Bop, *AxOp, *Qhp, *Khp, *Vhp;
    float2* tabp;
    cudaGetSymbolAddress((void**)&Axp,   g_Ax);
    cudaGetSymbolAddress((void**)&Bqkvp, g_Bqkv);
    cudaGetSymbolAddress((void**)&Bop,   g_Bo);
    cudaGetSymbolAddress((void**)&AxOp,  g_AxO);
    cudaGetSymbolAddress((void**)&Qhp,   g_Qh);
    cudaGetSymbolAddress((void**)&Khp,   g_Kh);
    cudaGetSymbolAddress((void**)&Vhp,   g_Vh);
    cudaGetSymbolAddress((void**)&tabp,  g_tab);

    cudaFuncSetAttribute((const void*)gemm_f16<0>,
                         cudaFuncAttributeMaxDynamicSharedMemorySize, HG_SMEM0);
    cudaFuncSetAttribute((const void*)gemm_f16<1>,
                         cudaFuncAttributeMaxDynamicSharedMemorySize, HG_SMEM1);
    cudaFuncSetAttribute((const void*)attn_tc,
                         cudaFuncAttributeMaxDynamicSharedMemorySize, ATT_SMEM);

    // RoPE tables + all fp16 converts
    rope_tables<<<512, 256>>>(tabp);
    convert_all<<<8192 + 4 * 4096, 256>>>(x, Wq, Wk, Wv, Wo, Axp, Bqkvp, Bop);

    // fused QKV projection (N = 6144) with RoPE epilogue
    gemm_f16<1><<<dim3(NQKV / 128, PM / 128), 256, HG_SMEM1>>>(
        Axp, Bqkvp, nullptr, Qhp, Khp, Vhp, tabp);

    // attention (64-query tiles, plain fp16, 2 CTAs/SM)
    attn_tc<<<dim3(PS / 64, PB * PH), 256, ATT_SMEM>>>(Qhp, Khp, Vhp, AxOp);

    // Wo projection
    gemm_f16<0><<<dim3(PD / 128, PM / 128), 256, HG_SMEM0>>>(
        AxOp, Bop, out, nullptr, nullptr, nullptr, nullptr);
}

// round 15
// speedup vs baseline: 5.1563x; 1.0177x over previous
#include <cuda_runtime.h>
#include <cuda_fp16.h>
#include <math.h>
#include <stdint.h>

// ---------------------------------------------------------------------------
// Problem constants
// ---------------------------------------------------------------------------
#define PB 2
#define PS 2048
#define PD 2048
#define PH 16
#define PHD 128
#define PM (PB * PS)          // 4096 rows
#define KC 2048               // GEMM K (plain fp16)
#define NQKV (3 * PD)         // 6144: fused QKV output columns
#define ATT_SCALE 0.08838834764831845f

// ---------------------------------------------------------------------------
// Scratch (device globals; no allocation allowed)
// ---------------------------------------------------------------------------
__device__ __half g_Ax[(size_t)PM * KC];                 // x, fp16
__device__ __half g_Bqkv[(size_t)NQKV * KC];             // [Wq;Wk;Wv] fp16
__device__ __half g_Bo[(size_t)PD * KC];                 // Wo fp16
__device__ __half g_AxO[(size_t)PM * KC];                // attn out fp16
__device__ __half g_Qh[(size_t)PB * PH * PS * 128];      // qh*scale
__device__ __half g_Kh[(size_t)PB * PH * PS * 128];      // kh
__device__ __half g_Vh[(size_t)PB * PH * PS * PHD];
__device__ float2 g_tab[PS * 64];                        // {cos, sin}

// ---------------------------------------------------------------------------
// PTX helpers (sm_80-compatible: cp.async + ldmatrix + mma.sync)
// ---------------------------------------------------------------------------
__device__ __forceinline__ uint32_t smem_u32(const void* p) {
    uint32_t a;
    asm("{ .reg .u64 t; cvta.to.shared.u64 t, %1; cvt.u32.u64 %0, t; }"
        : "=r"(a) : "l"(p));
    return a;
}

#define CP_ASYNC16(smem, gptr) \
    asm volatile("cp.async.cg.shared.global [%0], [%1], 16;" \
                 :: "r"(smem), "l"(gptr) : "memory")
#define CP_COMMIT() asm volatile("cp.async.commit_group;" ::: "memory")
#define CP_WAIT2()  asm volatile("cp.async.wait_group 2;" ::: "memory")
#define CP_WAIT0()  asm volatile("cp.async.wait_group 0;" ::: "memory")

#define LDSM_X4(r0, r1, r2, r3, addr) \
    asm volatile("ldmatrix.sync.aligned.m8n8.x4.shared.b16 {%0,%1,%2,%3}, [%4];" \
                 : "=r"(r0), "=r"(r1), "=r"(r2), "=r"(r3) : "r"(addr))
#define LDSM_X4T(r0, r1, r2, r3, addr) \
    asm volatile("ldmatrix.sync.aligned.m8n8.x4.trans.shared.b16 {%0,%1,%2,%3}, [%4];" \
                 : "=r"(r0), "=r"(r1), "=r"(r2), "=r"(r3) : "r"(addr))

#define MMA_16816_F16(c0, c1, c2, c3, a0, a1, a2, a3, b0, b1) \
    asm volatile("mma.sync.aligned.m16n8k16.row.col.f32.f16.f16.f32 " \
                 "{%0,%1,%2,%3}, {%4,%5,%6,%7}, {%8,%9}, {%0,%1,%2,%3};" \
                 : "+f"(c0), "+f"(c1), "+f"(c2), "+f"(c3) \
                 : "r"(a0), "r"(a1), "r"(a2), "r"(a3), "r"(b0), "r"(b1))

// swizzles
__device__ __forceinline__ uint32_t swz64(int r, int ch) {   // 64B rows, 4x16B chunks
    return (uint32_t)(r * 64 + (((ch) ^ ((r >> 1) & 3)) << 4));
}
__device__ __forceinline__ uint32_t swzV(int r, int ch) {    // 256B rows, 16x16B chunks
    return (uint32_t)(r * 256 + (((ch) ^ (r & 7)) << 4));
}

__device__ __forceinline__ uint32_t h2u(__half2 h) {
    uint32_t u;
    *(__half2*)&u = h;
    return u;
}

// ---------------------------------------------------------------------------
// RoPE tables: invf = exp(-j/64 * ln(10000)) (fp64); angle fp32-rounded chain.
// ---------------------------------------------------------------------------
__global__ __launch_bounds__(256)
void rope_tables(float2* __restrict__ tab)
{
    int idx = blockIdx.x * blockDim.x + threadIdx.x;   // 131072
    int s = idx >> 6;
    int j = idx & 63;
    double invf_d = exp(-(double)j * (9.210340371976184 / 64.0));
    float ang = (float)s * (float)invf_d;
    double cs, sn;
    sincos((double)ang, &sn, &cs);
    tab[idx] = make_float2((float)cs, (float)sn);
}

// ---------------------------------------------------------------------------
// Merged converts: fp32 -> fp16 (plain cast).
// ---------------------------------------------------------------------------
__global__ __launch_bounds__(256)
void convert_all(const float* __restrict__ x,
                 const float* __restrict__ Wq, const float* __restrict__ Wk,
                 const float* __restrict__ Wv, const float* __restrict__ Wo,
                 __half* __restrict__ Ax, __half* __restrict__ Bqkv,
                 __half* __restrict__ Bo)
{
    int bid = blockIdx.x;
    const float* src;
    __half* dst;
    int off;
    if (bid < 8192) {
        src = x; dst = Ax; off = bid;
    } else {
        int seg = (bid - 8192) >> 12;
        off = bid - 8192 - seg * 4096;
        if (seg == 0)      { src = Wq; dst = Bqkv; }
        else if (seg == 1) { src = Wk; dst = Bqkv + (size_t)2048 * KC; }
        else if (seg == 2) { src = Wv; dst = Bqkv + (size_t)4096 * KC; }
        else               { src = Wo; dst = Bo; }
    }
    size_t i = (size_t)off * 1024 + threadIdx.x * 4;
    float4 v = *(const float4*)(src + i);
    __half2 a = __floats2half2_rn(v.x, v.y);
    __half2 b = __floats2half2_rn(v.z, v.w);
    *(__half2*)(dst + i)     = a;
    *(__half2*)(dst + i + 2) = b;
}

// ---------------------------------------------------------------------------
// fp16 HMMA GEMM, K=2048 (proven round-13/14 body).
//  MODE 0: Wo projection — plain fp32 C stores.
//  MODE 1: fused QKV (N=6144): region 0 Q (RoPE+scale), 1 K (RoPE),
//          2 V (fp16 head-gather).
// ---------------------------------------------------------------------------
#define HG_BK 32
#define HG_STG 4
#define HG_STAGE_BYTES 16384
#define HG_SMEM0 (HG_STG * HG_STAGE_BYTES)      // 65536 (MODE 0)
#define HG_PITCH 136
#define HG_SMEM1 (128 * HG_PITCH * 4)           // 69632 (MODE 1)
#define HG_KT (KC / HG_BK)                      // 64

template<int MODE>
__global__ __launch_bounds__(256, 2)
void gemm_f16(const __half* __restrict__ A3, const __half* __restrict__ B3,
              float* __restrict__ C,
              __half* __restrict__ Qho, __half* __restrict__ Kho,
              __half* __restrict__ Vho, const float2* __restrict__ tab)
{
    extern __shared__ __align__(1024) char smem[];
    const uint32_t sbase = smem_u32(smem);

    const int tid  = threadIdx.x;
    const int lane = tid & 31;
    const int wid  = tid >> 5;
    const int wm   = wid & 1;
    const int wn   = wid >> 1;
    const int bm   = blockIdx.y * 128;
    const int bn   = blockIdx.x * 128;

    const __half* Ag = A3 + (size_t)bm * KC;
    const __half* Bg = B3 + (size_t)bn * KC;

    uint32_t lsw[2];
    const __half* gA[2];
    const __half* gB[2];
#pragma unroll
    for (int p = 0; p < 2; ++p) {
        int idx = tid + p * 256;
        int r = idx >> 2, ch = idx & 3;
        lsw[p] = swz64(r, ch);
        gA[p] = Ag + (size_t)r * KC + ch * 8;
        gB[p] = Bg + (size_t)r * KC + ch * 8;
    }

    uint32_t a_row_off[4];
    int a_swz[4];
#pragma unroll
    for (int mi = 0; mi < 4; ++mi) {
        int r = wm * 64 + mi * 16 + (lane & 15);
        a_row_off[mi] = (uint32_t)(r * 64);
        a_swz[mi] = (r >> 1) & 3;
    }
    const int a_cpart = lane >> 4;
    uint32_t b_row_off[2];
    int b_swz[2];
#pragma unroll
    for (int njp = 0; njp < 2; ++njp) {
        int r = wn * 32 + njp * 16 + ((lane >> 4) & 1) * 8 + (lane & 7);
        b_row_off[njp] = (uint32_t)(r * 64);
        b_swz[njp] = (r >> 1) & 3;
    }
    const int b_cpart = (lane >> 3) & 1;

    float acc[4][4][4];
#pragma unroll
    for (int mi = 0; mi < 4; ++mi)
#pragma unroll
        for (int nj = 0; nj < 4; ++nj)
#pragma unroll
            for (int e = 0; e < 4; ++e) acc[mi][nj][e] = 0.0f;

#pragma unroll
    for (int s = 0; s < HG_STG - 1; ++s) {
        uint32_t sA = sbase + s * HG_STAGE_BYTES;
        uint32_t sB = sA + 8192;
        int k0 = s * HG_BK;
#pragma unroll
        for (int p = 0; p < 2; ++p) {
            CP_ASYNC16(sA + lsw[p], gA[p] + k0);
            CP_ASYNC16(sB + lsw[p], gB[p] + k0);
        }
        CP_COMMIT();
    }

    for (int kt = 0; kt < HG_KT; ++kt) {
        CP_WAIT2();
        __syncthreads();

        int nk = kt + HG_STG - 1;
        if (nk < HG_KT) {
            uint32_t sA = sbase + (nk & 3) * HG_STAGE_BYTES;
            uint32_t sB = sA + 8192;
            int k0 = nk * HG_BK;
#pragma unroll
            for (int p = 0; p < 2; ++p) {
                CP_ASYNC16(sA + lsw[p], gA[p] + k0);
                CP_ASYNC16(sB + lsw[p], gB[p] + k0);
            }
        }
        CP_COMMIT();

        uint32_t sA = sbase + (kt & 3) * HG_STAGE_BYTES;
        uint32_t sB = sA + 8192;
#pragma unroll
        for (int h = 0; h < 2; ++h) {
            uint32_t a0[4], a1[4], a2[4], a3[4];
#pragma unroll
            for (int mi = 0; mi < 4; ++mi) {
                uint32_t addr = sA + a_row_off[mi]
                              + (uint32_t)(((2 * h + a_cpart) ^ a_swz[mi]) << 4);
                LDSM_X4(a0[mi], a1[mi], a2[mi], a3[mi], addr);
            }
            uint32_t b0[4], b1[4];
#pragma unroll
            for (int njp = 0; njp < 2; ++njp) {
                uint32_t addr = sB + b_row_off[njp]
                              + (uint32_t)(((2 * h + b_cpart) ^ b_swz[njp]) << 4);
                LDSM_X4(b0[2 * njp], b1[2 * njp],
                        b0[2 * njp + 1], b1[2 * njp + 1], addr);
            }
#pragma unroll
            for (int mi = 0; mi < 4; ++mi)
#pragma unroll
                for (int nj = 0; nj < 4; ++nj)
                    MMA_16816_F16(acc[mi][nj][0], acc[mi][nj][1],
                                  acc[mi][nj][2], acc[mi][nj][3],
                                  a0[mi], a1[mi], a2[mi], a3[mi],
                                  b0[nj], b1[nj]);
        }
        __syncthreads();
    }

    const int erow = (lane >> 2);
    const int ecol = (lane & 3) * 2;
    const int region  = (MODE == 1) ? (bn >> 11) : 0;
    const int colbase = bn - region * 2048;

    if (MODE == 0) {
#pragma unroll
        for (int mi = 0; mi < 4; ++mi)
#pragma unroll
            for (int nj = 0; nj < 4; ++nj) {
                int row = bm + wm * 64 + mi * 16 + erow;
                int col = colbase + wn * 32 + nj * 8 + ecol;
                *(float2*)(C + (size_t)row * PD + col) =
                    make_float2(acc[mi][nj][0], acc[mi][nj][1]);
                *(float2*)(C + (size_t)(row + 8) * PD + col) =
                    make_float2(acc[mi][nj][2], acc[mi][nj][3]);
            }
    } else if (region == 2) {
#pragma unroll
        for (int mi = 0; mi < 4; ++mi)
#pragma unroll
            for (int nj = 0; nj < 4; ++nj) {
                int row = bm + wm * 64 + mi * 16 + erow;
                int col = colbase + wn * 32 + nj * 8 + ecol;
                int b = row >> 11, s = row & 2047;
                int h = col >> 7, hd = col & 127;
                size_t dst = ((size_t)(b * PH + h) * PS + s) * PHD + hd;
                *(__half2*)(Vho + dst) = __float22half2_rn(
                    make_float2(acc[mi][nj][0], acc[mi][nj][1]));
                *(__half2*)(Vho + dst + 8 * PHD) = __float22half2_rn(
                    make_float2(acc[mi][nj][2], acc[mi][nj][3]));
            }
    } else {
        // Q/K: smem stage + RoPE + fp16 emit (both 128-wide; Q scaled)
        float* tile = (float*)smem;
#pragma unroll
        for (int mi = 0; mi < 4; ++mi)
#pragma unroll
            for (int nj = 0; nj < 4; ++nj) {
                int r = wm * 64 + mi * 16 + erow;
                int c = wn * 32 + nj * 8 + ecol;
                *(float2*)(tile + r * HG_PITCH + c) =
                    make_float2(acc[mi][nj][0], acc[mi][nj][1]);
                *(float2*)(tile + (r + 8) * HG_PITCH + c) =
                    make_float2(acc[mi][nj][2], acc[mi][nj][3]);
            }
        __syncthreads();

        const int hh = colbase >> 7;
        const int b  = bm >> 11;
        const int s0 = bm & 2047;
        const int rg = tid >> 6;
        const int ii = tid & 63;
        const float sc = (region == 0) ? ATT_SCALE : 1.0f;
        __half* dst = (region == 0 ? Qho : Kho)
                    + (size_t)(b * PH + hh) * PS * 128;
#pragma unroll 4
        for (int rr = 0; rr < 32; ++rr) {
            int r = rg * 32 + rr;
            float x0 = tile[r * HG_PITCH + ii];
            float x1 = tile[r * HG_PITCH + 64 + ii];
            int s = s0 + r;
            float2 cs = tab[s * 64 + ii];
            __half* o = dst + (size_t)s * 128;
            o[ii]      = __float2half((x0 * cs.x - x1 * cs.y) * sc);
            o[64 + ii] = __float2half((x1 * cs.x + x0 * cs.y) * sc);
        }
    }
}

// ---------------------------------------------------------------------------
// Tensor-core causal flash attention, 64q x 64k tiles, 4 warps (128 thr).
// Each warp owns 16 full rows: in-warp softmax, P kept in registers
// (QK C-fragments == PV A-fragments). 4 CTAs/SM.
// ---------------------------------------------------------------------------
#define BTS_Q  0          // 4 panels x 4096 = 16384
#define BTS_K  16384      // 16384
#define BTS_V  32768      // 16384
#define ATT_SMEM 49152

__global__ __launch_bounds__(128, 4)
void attn_tc(const __half* __restrict__ Qh,
             const __half* __restrict__ Kh,
             const __half* __restrict__ Vh,
             __half* __restrict__ AXO)
{
    extern __shared__ __align__(1024) char sm[];
    const uint32_t sb = smem_u32(sm);

    const int tid  = threadIdx.x;
    const int lane = tid & 31;
    const int w    = tid >> 5;               // 0..3: 16-row group
    const int qt   = 31 - (int)blockIdx.x;
    const int bh   = blockIdx.y;
    const int qb   = qt * 64;
    const int nkt  = qt + 1;

    const __half* qh = Qh + ((size_t)bh * PS + qb) * 128;
    const __half* k2 = Kh + (size_t)bh * PS * 128;
    const __half* vh = Vh + (size_t)bh * PS * PHD;

    // ---- Q (64x128), K0, V0 loads: 128 threads
    {
#pragma unroll
        for (int p = 0; p < 4; ++p)
#pragma unroll
            for (int ps = 0; ps < 2; ++ps) {
                int idx = tid + ps * 128;
                int r = idx >> 2, ch = idx & 3;
                uint32_t sw = swz64(r, ch);
                CP_ASYNC16(sb + BTS_Q + p * 4096 + sw,
                           qh + (size_t)r * 128 + p * 32 + ch * 8);
                CP_ASYNC16(sb + BTS_K + p * 4096 + sw,
                           k2 + (size_t)r * 128 + p * 32 + ch * 8);
            }
#pragma unroll
        for (int ps = 0; ps < 8; ++ps) {
            int idx = tid + ps * 128;
            int rr = idx >> 4, cc = idx & 15;
            CP_ASYNC16(sb + BTS_V + swzV(rr, cc), vh + (size_t)rr * PHD + cc * 8);
        }
    }
    CP_COMMIT();

    float m0 = -INFINITY, m1 = -INFINITY, l0 = 0.0f, l1 = 0.0f;
    float oa[16][4];
#pragma unroll
    for (int j = 0; j < 16; ++j)
#pragma unroll
        for (int e = 0; e < 4; ++e) oa[j][e] = 0.0f;

    const int arow = w * 16 + (lane & 15);
    const int aswz = (arow >> 1) & 3;
    const int acp  = lane >> 4;
    const int r0   = w * 16 + (lane >> 2);
    const int vkb  = (lane & 7) + 8 * ((lane >> 3) & 1);

    for (int kt = 0; kt < nkt; ++kt) {
        CP_WAIT0();
        __syncthreads();

        // ---- QK: S[16 x 64] per warp over K'=128
        float sa[8][4];
#pragma unroll
        for (int j = 0; j < 8; ++j)
#pragma unroll
            for (int e = 0; e < 4; ++e) sa[j][e] = 0.0f;

#pragma unroll
        for (int p = 0; p < 4; ++p) {
#pragma unroll
            for (int h = 0; h < 2; ++h) {
                uint32_t a0, a1, a2, a3;
                LDSM_X4(a0, a1, a2, a3,
                        sb + BTS_Q + p * 4096 + arow * 64
                           + (((2 * h + acp) ^ aswz) << 4));
#pragma unroll
                for (int jj = 0; jj < 4; ++jj) {
                    int brow = jj * 16 + (lane & 15);
                    uint32_t b0, b1, b2, b3;
                    LDSM_X4(b0, b1, b2, b3,
                            sb + BTS_K + p * 4096 + brow * 64
                               + (((2 * h + acp) ^ ((brow >> 1) & 3)) << 4));
                    MMA_16816_F16(sa[2 * jj][0], sa[2 * jj][1],
                                  sa[2 * jj][2], sa[2 * jj][3],
                                  a0, a1, a2, a3, b0, b2);
                    MMA_16816_F16(sa[2 * jj + 1][0], sa[2 * jj + 1][1],
                                  sa[2 * jj + 1][2], sa[2 * jj + 1][3],
                                  a0, a1, a2, a3, b1, b3);
                }
            }
        }
        __syncthreads();      // all warps done reading K

        // prefetch next K (same buffer)
        if (kt + 1 < nkt) {
            const __half* kp = k2 + (size_t)(kt + 1) * 64 * 128;
#pragma unroll
            for (int p = 0; p < 4; ++p)
#pragma unroll
                for (int ps = 0; ps < 2; ++ps) {
                    int idx = tid + ps * 128;
                    int r = idx >> 2, ch = idx & 3;
                    CP_ASYNC16(sb + BTS_K + p * 4096 + swz64(r, ch),
                               kp + (size_t)r * 128 + p * 32 + ch * 8);
                }
        }
        CP_COMMIT();

        // ---- causal mask (diagonal tile only)
        if (kt == qt) {
            const int gr0 = qb + r0;
            const int gr1 = gr0 + 8;
            const int kb = kt * 64;
#pragma unroll
            for (int nb = 0; nb < 8; ++nb) {
                int c0 = kb + nb * 8 + 2 * (lane & 3);
                if (c0 > gr0)     sa[nb][0] = -INFINITY;
                if (c0 + 1 > gr0) sa[nb][1] = -INFINITY;
                if (c0 > gr1)     sa[nb][2] = -INFINITY;
                if (c0 + 1 > gr1) sa[nb][3] = -INFINITY;
            }
        }

        // ---- in-warp softmax (rows fully owned: quad shuffles only)
        float rm0 = -INFINITY, rm1 = -INFINITY;
#pragma unroll
        for (int nb = 0; nb < 8; ++nb) {
            rm0 = fmaxf(rm0, fmaxf(sa[nb][0], sa[nb][1]));
            rm1 = fmaxf(rm1, fmaxf(sa[nb][2], sa[nb][3]));
        }
        rm0 = fmaxf(rm0, __shfl_xor_sync(0xffffffffu, rm0, 1));
        rm0 = fmaxf(rm0, __shfl_xor_sync(0xffffffffu, rm0, 2));
        rm1 = fmaxf(rm1, __shfl_xor_sync(0xffffffffu, rm1, 1));
        rm1 = fmaxf(rm1, __shfl_xor_sync(0xffffffffu, rm1, 2));

        float mn0 = fmaxf(m0, rm0);
        float mn1 = fmaxf(m1, rm1);
        float corr0 = __expf(m0 - mn0);
        float corr1 = __expf(m1 - mn1);
        m0 = mn0; m1 = mn1;
#pragma unroll
        for (int j = 0; j < 16; ++j) {
            oa[j][0] *= corr0; oa[j][1] *= corr0;
            oa[j][2] *= corr1; oa[j][3] *= corr1;
        }

        float rs0 = 0.0f, rs1 = 0.0f;
#pragma unroll
        for (int nb = 0; nb < 8; ++nb) {
            sa[nb][0] = __expf(sa[nb][0] - mn0);
            sa[nb][1] = __expf(sa[nb][1] - mn0);
            sa[nb][2] = __expf(sa[nb][2] - mn1);
            sa[nb][3] = __expf(sa[nb][3] - mn1);
            rs0 += sa[nb][0] + sa[nb][1];
            rs1 += sa[nb][2] + sa[nb][3];
        }
        rs0 += __shfl_xor_sync(0xffffffffu, rs0, 1);
        rs0 += __shfl_xor_sync(0xffffffffu, rs0, 2);
        rs1 += __shfl_xor_sync(0xffffffffu, rs1, 1);
        rs1 += __shfl_xor_sync(0xffffffffu, rs1, 2);
        l0 = l0 * corr0 + rs0;
        l1 = l1 * corr1 + rs1;

        // ---- pack P into mma A-fragments (C-frag layout == A-frag layout)
        uint32_t pa[4][4];
#pragma unroll
        for (int c = 0; c < 4; ++c) {
            pa[c][0] = h2u(__floats2half2_rn(sa[2 * c][0], sa[2 * c][1]));
            pa[c][1] = h2u(__floats2half2_rn(sa[2 * c][2], sa[2 * c][3]));
            pa[c][2] = h2u(__floats2half2_rn(sa[2 * c + 1][0], sa[2 * c + 1][1]));
            pa[c][3] = h2u(__floats2half2_rn(sa[2 * c + 1][2], sa[2 * c + 1][3]));
        }

        // ---- PV: O[16 x 128] per warp; P from registers, V via ldsm.trans
#pragma unroll
        for (int c = 0; c < 4; ++c) {
            int vk = c * 16 + vkb;
#pragma unroll
            for (int gp = 0; gp < 8; ++gp) {
                uint32_t b0, b1, b2, b3;
                LDSM_X4T(b0, b1, b2, b3,
                         sb + BTS_V + vk * 256
                            + ((((2 * gp + (lane >> 4)) ^ (vk & 7))) << 4));
                MMA_16816_F16(oa[2 * gp][0], oa[2 * gp][1],
                              oa[2 * gp][2], oa[2 * gp][3],
                              pa[c][0], pa[c][1], pa[c][2], pa[c][3],
                              b0, b1);
                MMA_16816_F16(oa[2 * gp + 1][0], oa[2 * gp + 1][1],
                              oa[2 * gp + 1][2], oa[2 * gp + 1][3],
                              pa[c][0], pa[c][1], pa[c][2], pa[c][3],
                              b2, b3);
            }
        }
        __syncthreads();      // all warps done reading V

        // prefetch next V (same buffer)
        if (kt + 1 < nkt) {
            const __half* va = vh + (size_t)(kt + 1) * 64 * PHD;
#pragma unroll
            for (int ps = 0; ps < 8; ++ps) {
                int idx = tid + ps * 128;
                int rr = idx >> 4, cc = idx & 15;
                CP_ASYNC16(sb + BTS_V + swzV(rr, cc), va + (size_t)rr * PHD + cc * 8);
            }
        }
        CP_COMMIT();
    }

    // ---- epilogue: plain fp16 into AXO [PM x 2048]
    const float inv0 = 1.0f / l0;
    const float inv1 = 1.0f / l1;
    const int b = bh >> 4, h = bh & 15;
    const size_t row0 = (size_t)b * PS + qb + r0;
    const size_t row1 = row0 + 8;
#pragma unroll
    for (int j = 0; j < 16; ++j) {
        int col = h * PHD + j * 8 + 2 * (lane & 3);
        __half2 h20 = __float22half2_rn(
            make_float2(oa[j][0] * inv0, oa[j][1] * inv0));
        __half2 h21 = __float22half2_rn(
            make_float2(oa[j][2] * inv1, oa[j][3] * inv1));
        *(__half2*)(AXO + row0 * KC + col) = h20;
        *(__half2*)(AXO + row1 * KC + col) = h21;
    }
}

// ---------------------------------------------------------------------------
// kernel_launch
// ---------------------------------------------------------------------------
extern "C" void kernel_launch(void* const* d_in, const int* in_sizes, int n_in,
                              void* d_out, int out_size)
{
    const float* x  = (const float*)d_in[0];
    const float* Wq = (const float*)d_in[1];
    const float* Wk = (const float*)d_in[2];
    const float* Wv = (const float*)d_in[3];
    const float* Wo = (const float*)d_in[4];
    float* out = (float*)d_out;

    __half *Axp, *Bqkvp, *Bop, *AxOp, *Qhp, *Khp, *Vhp;
    float2* tabp;
    cudaGetSymbolAddress((void**)&Axp,   g_Ax);
    cudaGetSymbolAddress((void**)&Bqkvp, g_Bqkv);
    cudaGetSymbolAddress((void**)&Bop,   g_Bo);
    cudaGetSymbolAddress((void**)&AxOp,  g_AxO);
    cudaGetSymbolAddress((void**)&Qhp,   g_Qh);
    cudaGetSymbolAddress((void**)&Khp,   g_Kh);
    cudaGetSymbolAddress((void**)&Vhp,   g_Vh);
    cudaGetSymbolAddress((void**)&tabp,  g_tab);

    cudaFuncSetAttribute((const void*)gemm_f16<0>,
                         cudaFuncAttributeMaxDynamicSharedMemorySize, HG_SMEM0);
    cudaFuncSetAttribute((const void*)gemm_f16<1>,
                         cudaFuncAttributeMaxDynamicSharedMemorySize, HG_SMEM1);
    cudaFuncSetAttribute((const void*)attn_tc,
                         cudaFuncAttributeMaxDynamicSharedMemorySize, ATT_SMEM);

    // RoPE tables + all fp16 converts
    rope_tables<<<512, 256>>>(tabp);
    convert_all<<<8192 + 4 * 4096, 256>>>(x, Wq, Wk, Wv, Wo, Axp, Bqkvp, Bop);

    // fused QKV projection (N = 6144) with RoPE epilogue
    gemm_f16<1><<<dim3(NQKV / 128, PM / 128), 256, HG_SMEM1>>>(
        Axp, Bqkvp, nullptr, Qhp, Khp, Vhp, tabp);

    // attention (64-query tiles, register-resident P, 4 CTAs/SM)
    attn_tc<<<dim3(PS / 64, PB * PH), 128, ATT_SMEM>>>(Qhp, Khp, Vhp, AxOp);

    // Wo projection
    gemm_f16<0><<<dim3(PD / 128, PM / 128), 256, HG_SMEM0>>>(
        AxOp, Bop, out, nullptr, nullptr, nullptr, nullptr);
}

// round 16
// speedup vs baseline: 5.1776x; 1.0041x over previous
#include <cuda_runtime.h>
#include <cuda_fp16.h>
#include <math.h>
#include <stdint.h>

// ---------------------------------------------------------------------------
// Problem constants
// ---------------------------------------------------------------------------
#define PB 2
#define PS 2048
#define PD 2048
#define PH 16
#define PHD 128
#define PM (PB * PS)          // 4096 rows
#define KC 2048               // GEMM K (plain fp16)
#define NQKV (3 * PD)         // 6144: fused QKV output columns
#define ATT_SCALE 0.08838834764831845f

// ---------------------------------------------------------------------------
// Scratch (device globals; no allocation allowed)
// ---------------------------------------------------------------------------
__device__ __half g_Ax[(size_t)PM * KC];                 // x, fp16
__device__ __half g_Bqkv[(size_t)NQKV * KC];             // [Wq;Wk;Wv] fp16
__device__ __half g_Bo[(size_t)PD * KC];                 // Wo fp16
__device__ __half g_AxO[(size_t)PM * KC];                // attn out fp16
__device__ __half g_Qh[(size_t)PB * PH * PS * 128];      // qh*scale
__device__ __half g_Kh[(size_t)PB * PH * PS * 128];      // kh
__device__ __half g_Vh[(size_t)PB * PH * PS * PHD];
__device__ float2 g_tab[PS * 64];                        // {cos, sin}

// ---------------------------------------------------------------------------
// PTX helpers (sm_80-compatible: cp.async + ldmatrix + mma.sync)
// ---------------------------------------------------------------------------
__device__ __forceinline__ uint32_t smem_u32(const void* p) {
    uint32_t a;
    asm("{ .reg .u64 t; cvta.to.shared.u64 t, %1; cvt.u32.u64 %0, t; }"
        : "=r"(a) : "l"(p));
    return a;
}

#define CP_ASYNC16(smem, gptr) \
    asm volatile("cp.async.cg.shared.global [%0], [%1], 16;" \
                 :: "r"(smem), "l"(gptr) : "memory")
#define CP_COMMIT() asm volatile("cp.async.commit_group;" ::: "memory")
#define CP_WAIT2()  asm volatile("cp.async.wait_group 2;" ::: "memory")
#define CP_WAIT1()  asm volatile("cp.async.wait_group 1;" ::: "memory")
#define CP_WAIT0()  asm volatile("cp.async.wait_group 0;" ::: "memory")

#define LDSM_X4(r0, r1, r2, r3, addr) \
    asm volatile("ldmatrix.sync.aligned.m8n8.x4.shared.b16 {%0,%1,%2,%3}, [%4];" \
                 : "=r"(r0), "=r"(r1), "=r"(r2), "=r"(r3) : "r"(addr))
#define LDSM_X4T(r0, r1, r2, r3, addr) \
    asm volatile("ldmatrix.sync.aligned.m8n8.x4.trans.shared.b16 {%0,%1,%2,%3}, [%4];" \
                 : "=r"(r0), "=r"(r1), "=r"(r2), "=r"(r3) : "r"(addr))

#define MMA_16816_F16(c0, c1, c2, c3, a0, a1, a2, a3, b0, b1) \
    asm volatile("mma.sync.aligned.m16n8k16.row.col.f32.f16.f16.f32 " \
                 "{%0,%1,%2,%3}, {%4,%5,%6,%7}, {%8,%9}, {%0,%1,%2,%3};" \
                 : "+f"(c0), "+f"(c1), "+f"(c2), "+f"(c3) \
                 : "r"(a0), "r"(a1), "r"(a2), "r"(a3), "r"(b0), "r"(b1))

// swizzles
__device__ __forceinline__ uint32_t swz64(int r, int ch) {   // 64B rows, 4x16B chunks
    return (uint32_t)(r * 64 + (((ch) ^ ((r >> 1) & 3)) << 4));
}
__device__ __forceinline__ uint32_t swzV(int r, int ch) {    // 256B rows, 16x16B chunks
    return (uint32_t)(r * 256 + (((ch) ^ (r & 7)) << 4));
}

__device__ __forceinline__ uint32_t h2u(__half2 h) {
    uint32_t u;
    *(__half2*)&u = h;
    return u;
}

// ---------------------------------------------------------------------------
// RoPE tables: invf = exp(-j/64 * ln(10000)) (fp64); angle fp32-rounded chain.
// ---------------------------------------------------------------------------
__global__ __launch_bounds__(256)
void rope_tables(float2* __restrict__ tab)
{
    int idx = blockIdx.x * blockDim.x + threadIdx.x;   // 131072
    int s = idx >> 6;
    int j = idx & 63;
    double invf_d = exp(-(double)j * (9.210340371976184 / 64.0));
    float ang = (float)s * (float)invf_d;
    double cs, sn;
    sincos((double)ang, &sn, &cs);
    tab[idx] = make_float2((float)cs, (float)sn);
}

// ---------------------------------------------------------------------------
// Merged converts: fp32 -> fp16 (plain cast).
// ---------------------------------------------------------------------------
__global__ __launch_bounds__(256)
void convert_all(const float* __restrict__ x,
                 const float* __restrict__ Wq, const float* __restrict__ Wk,
                 const float* __restrict__ Wv, const float* __restrict__ Wo,
                 __half* __restrict__ Ax, __half* __restrict__ Bqkv,
                 __half* __restrict__ Bo)
{
    int bid = blockIdx.x;
    const float* src;
    __half* dst;
    int off;
    if (bid < 8192) {
        src = x; dst = Ax; off = bid;
    } else {
        int seg = (bid - 8192) >> 12;
        off = bid - 8192 - seg * 4096;
        if (seg == 0)      { src = Wq; dst = Bqkv; }
        else if (seg == 1) { src = Wk; dst = Bqkv + (size_t)2048 * KC; }
        else if (seg == 2) { src = Wv; dst = Bqkv + (size_t)4096 * KC; }
        else               { src = Wo; dst = Bo; }
    }
    size_t i = (size_t)off * 1024 + threadIdx.x * 4;
    float4 v = *(const float4*)(src + i);
    __half2 a = __floats2half2_rn(v.x, v.y);
    __half2 b = __floats2half2_rn(v.z, v.w);
    *(__half2*)(dst + i)     = a;
    *(__half2*)(dst + i + 2) = b;
}

// ---------------------------------------------------------------------------
// fp16 HMMA GEMM, K=2048 (proven round-13/14 body).
//  MODE 0: Wo projection — plain fp32 C stores.
//  MODE 1: fused QKV (N=6144): region 0 Q (RoPE+scale), 1 K (RoPE),
//          2 V (fp16 head-gather).
// ---------------------------------------------------------------------------
#define HG_BK 32
#define HG_STG 4
#define HG_STAGE_BYTES 16384
#define HG_SMEM0 (HG_STG * HG_STAGE_BYTES)      // 65536 (MODE 0)
#define HG_PITCH 136
#define HG_SMEM1 (128 * HG_PITCH * 4)           // 69632 (MODE 1)
#define HG_KT (KC / HG_BK)                      // 64

template<int MODE>
__global__ __launch_bounds__(256, 2)
void gemm_f16(const __half* __restrict__ A3, const __half* __restrict__ B3,
              float* __restrict__ C,
              __half* __restrict__ Qho, __half* __restrict__ Kho,
              __half* __restrict__ Vho, const float2* __restrict__ tab)
{
    extern __shared__ __align__(1024) char smem[];
    const uint32_t sbase = smem_u32(smem);

    const int tid  = threadIdx.x;
    const int lane = tid & 31;
    const int wid  = tid >> 5;
    const int wm   = wid & 1;
    const int wn   = wid >> 1;
    const int bm   = blockIdx.y * 128;
    const int bn   = blockIdx.x * 128;

    const __half* Ag = A3 + (size_t)bm * KC;
    const __half* Bg = B3 + (size_t)bn * KC;

    uint32_t lsw[2];
    const __half* gA[2];
    const __half* gB[2];
#pragma unroll
    for (int p = 0; p < 2; ++p) {
        int idx = tid + p * 256;
        int r = idx >> 2, ch = idx & 3;
        lsw[p] = swz64(r, ch);
        gA[p] = Ag + (size_t)r * KC + ch * 8;
        gB[p] = Bg + (size_t)r * KC + ch * 8;
    }

    uint32_t a_row_off[4];
    int a_swz[4];
#pragma unroll
    for (int mi = 0; mi < 4; ++mi) {
        int r = wm * 64 + mi * 16 + (lane & 15);
        a_row_off[mi] = (uint32_t)(r * 64);
        a_swz[mi] = (r >> 1) & 3;
    }
    const int a_cpart = lane >> 4;
    uint32_t b_row_off[2];
    int b_swz[2];
#pragma unroll
    for (int njp = 0; njp < 2; ++njp) {
        int r = wn * 32 + njp * 16 + ((lane >> 4) & 1) * 8 + (lane & 7);
        b_row_off[njp] = (uint32_t)(r * 64);
        b_swz[njp] = (r >> 1) & 3;
    }
    const int b_cpart = (lane >> 3) & 1;

    float acc[4][4][4];
#pragma unroll
    for (int mi = 0; mi < 4; ++mi)
#pragma unroll
        for (int nj = 0; nj < 4; ++nj)
#pragma unroll
            for (int e = 0; e < 4; ++e) acc[mi][nj][e] = 0.0f;

#pragma unroll
    for (int s = 0; s < HG_STG - 1; ++s) {
        uint32_t sA = sbase + s * HG_STAGE_BYTES;
        uint32_t sB = sA + 8192;
        int k0 = s * HG_BK;
#pragma unroll
        for (int p = 0; p < 2; ++p) {
            CP_ASYNC16(sA + lsw[p], gA[p] + k0);
            CP_ASYNC16(sB + lsw[p], gB[p] + k0);
        }
        CP_COMMIT();
    }

    for (int kt = 0; kt < HG_KT; ++kt) {
        CP_WAIT2();
        __syncthreads();

        int nk = kt + HG_STG - 1;
        if (nk < HG_KT) {
            uint32_t sA = sbase + (nk & 3) * HG_STAGE_BYTES;
            uint32_t sB = sA + 8192;
            int k0 = nk * HG_BK;
#pragma unroll
            for (int p = 0; p < 2; ++p) {
                CP_ASYNC16(sA + lsw[p], gA[p] + k0);
                CP_ASYNC16(sB + lsw[p], gB[p] + k0);
            }
        }
        CP_COMMIT();

        uint32_t sA = sbase + (kt & 3) * HG_STAGE_BYTES;
        uint32_t sB = sA + 8192;
#pragma unroll
        for (int h = 0; h < 2; ++h) {
            uint32_t a0[4], a1[4], a2[4], a3[4];
#pragma unroll
            for (int mi = 0; mi < 4; ++mi) {
                uint32_t addr = sA + a_row_off[mi]
                              + (uint32_t)(((2 * h + a_cpart) ^ a_swz[mi]) << 4);
                LDSM_X4(a0[mi], a1[mi], a2[mi], a3[mi], addr);
            }
            uint32_t b0[4], b1[4];
#pragma unroll
            for (int njp = 0; njp < 2; ++njp) {
                uint32_t addr = sB + b_row_off[njp]
                              + (uint32_t)(((2 * h + b_cpart) ^ b_swz[njp]) << 4);
                LDSM_X4(b0[2 * njp], b1[2 * njp],
                        b0[2 * njp + 1], b1[2 * njp + 1], addr);
            }
#pragma unroll
            for (int mi = 0; mi < 4; ++mi)
#pragma unroll
                for (int nj = 0; nj < 4; ++nj)
                    MMA_16816_F16(acc[mi][nj][0], acc[mi][nj][1],
                                  acc[mi][nj][2], acc[mi][nj][3],
                                  a0[mi], a1[mi], a2[mi], a3[mi],
                                  b0[nj], b1[nj]);
        }
        __syncthreads();
    }

    const int erow = (lane >> 2);
    const int ecol = (lane & 3) * 2;
    const int region  = (MODE == 1) ? (bn >> 11) : 0;
    const int colbase = bn - region * 2048;

    if (MODE == 0) {
#pragma unroll
        for (int mi = 0; mi < 4; ++mi)
#pragma unroll
            for (int nj = 0; nj < 4; ++nj) {
                int row = bm + wm * 64 + mi * 16 + erow;
                int col = colbase + wn * 32 + nj * 8 + ecol;
                *(float2*)(C + (size_t)row * PD + col) =
                    make_float2(acc[mi][nj][0], acc[mi][nj][1]);
                *(float2*)(C + (size_t)(row + 8) * PD + col) =
                    make_float2(acc[mi][nj][2], acc[mi][nj][3]);
            }
    } else if (region == 2) {
#pragma unroll
        for (int mi = 0; mi < 4; ++mi)
#pragma unroll
            for (int nj = 0; nj < 4; ++nj) {
                int row = bm + wm * 64 + mi * 16 + erow;
                int col = colbase + wn * 32 + nj * 8 + ecol;
                int b = row >> 11, s = row & 2047;
                int h = col >> 7, hd = col & 127;
                size_t dst = ((size_t)(b * PH + h) * PS + s) * PHD + hd;
                *(__half2*)(Vho + dst) = __float22half2_rn(
                    make_float2(acc[mi][nj][0], acc[mi][nj][1]));
                *(__half2*)(Vho + dst + 8 * PHD) = __float22half2_rn(
                    make_float2(acc[mi][nj][2], acc[mi][nj][3]));
            }
    } else {
        // Q/K: smem stage + RoPE + fp16 emit (both 128-wide; Q scaled)
        float* tile = (float*)smem;
#pragma unroll
        for (int mi = 0; mi < 4; ++mi)
#pragma unroll
            for (int nj = 0; nj < 4; ++nj) {
                int r = wm * 64 + mi * 16 + erow;
                int c = wn * 32 + nj * 8 + ecol;
                *(float2*)(tile + r * HG_PITCH + c) =
                    make_float2(acc[mi][nj][0], acc[mi][nj][1]);
                *(float2*)(tile + (r + 8) * HG_PITCH + c) =
                    make_float2(acc[mi][nj][2], acc[mi][nj][3]);
            }
        __syncthreads();

        const int hh = colbase >> 7;
        const int b  = bm >> 11;
        const int s0 = bm & 2047;
        const int rg = tid >> 6;
        const int ii = tid & 63;
        const float sc = (region == 0) ? ATT_SCALE : 1.0f;
        __half* dst = (region == 0 ? Qho : Kho)
                    + (size_t)(b * PH + hh) * PS * 128;
#pragma unroll 4
        for (int rr = 0; rr < 32; ++rr) {
            int r = rg * 32 + rr;
            float x0 = tile[r * HG_PITCH + ii];
            float x1 = tile[r * HG_PITCH + 64 + ii];
            int s = s0 + r;
            float2 cs = tab[s * 64 + ii];
            __half* o = dst + (size_t)s * 128;
            o[ii]      = __float2half((x0 * cs.x - x1 * cs.y) * sc);
            o[64 + ii] = __float2half((x1 * cs.x + x0 * cs.y) * sc);
        }
    }
}

// ---------------------------------------------------------------------------
// Tensor-core causal flash attention, 64q x 64k tiles, 4 warps (128 thr).
// Each warp owns 16 full rows: in-warp softmax, register-resident P.
// Split cp.async wait groups: K waits don't couple to in-flight V and
// vice versa, so each load overlaps ~half an iteration. 4 CTAs/SM.
// ---------------------------------------------------------------------------
#define BTS_Q  0          // 4 panels x 4096 = 16384
#define BTS_K  16384      // 16384
#define BTS_V  32768      // 16384
#define ATT_SMEM 49152

__global__ __launch_bounds__(128, 4)
void attn_tc(const __half* __restrict__ Qh,
             const __half* __restrict__ Kh,
             const __half* __restrict__ Vh,
             __half* __restrict__ AXO)
{
    extern __shared__ __align__(1024) char sm[];
    const uint32_t sb = smem_u32(sm);

    const int tid  = threadIdx.x;
    const int lane = tid & 31;
    const int w    = tid >> 5;               // 0..3: 16-row group
    const int qt   = 31 - (int)blockIdx.x;
    const int bh   = blockIdx.y;
    const int qb   = qt * 64;
    const int nkt  = qt + 1;

    const __half* qh = Qh + ((size_t)bh * PS + qb) * 128;
    const __half* k2 = Kh + (size_t)bh * PS * 128;
    const __half* vh = Vh + (size_t)bh * PS * PHD;

    // ---- group A: Q (64x128) + K0; group B: V0
    {
#pragma unroll
        for (int p = 0; p < 4; ++p)
#pragma unroll
            for (int ps = 0; ps < 2; ++ps) {
                int idx = tid + ps * 128;
                int r = idx >> 2, ch = idx & 3;
                uint32_t sw = swz64(r, ch);
                CP_ASYNC16(sb + BTS_Q + p * 4096 + sw,
                           qh + (size_t)r * 128 + p * 32 + ch * 8);
                CP_ASYNC16(sb + BTS_K + p * 4096 + sw,
                           k2 + (size_t)r * 128 + p * 32 + ch * 8);
            }
        CP_COMMIT();
#pragma unroll
        for (int ps = 0; ps < 8; ++ps) {
            int idx = tid + ps * 128;
            int rr = idx >> 4, cc = idx & 15;
            CP_ASYNC16(sb + BTS_V + swzV(rr, cc), vh + (size_t)rr * PHD + cc * 8);
        }
        CP_COMMIT();
    }

    float m0 = -INFINITY, m1 = -INFINITY, l0 = 0.0f, l1 = 0.0f;
    float oa[16][4];
#pragma unroll
    for (int j = 0; j < 16; ++j)
#pragma unroll
        for (int e = 0; e < 4; ++e) oa[j][e] = 0.0f;

    const int arow = w * 16 + (lane & 15);
    const int aswz = (arow >> 1) & 3;
    const int acp  = lane >> 4;
    const int r0   = w * 16 + (lane >> 2);
    const int vkb  = (lane & 7) + 8 * ((lane >> 3) & 1);

    for (int kt = 0; kt < nkt; ++kt) {
        // K(kt) ready (V(kt) may still be in flight)
        CP_WAIT1();
        __syncthreads();

        // ---- QK: S[16 x 64] per warp over K'=128
        float sa[8][4];
#pragma unroll
        for (int j = 0; j < 8; ++j)
#pragma unroll
            for (int e = 0; e < 4; ++e) sa[j][e] = 0.0f;

#pragma unroll
        for (int p = 0; p < 4; ++p) {
#pragma unroll
            for (int h = 0; h < 2; ++h) {
                uint32_t a0, a1, a2, a3;
                LDSM_X4(a0, a1, a2, a3,
                        sb + BTS_Q + p * 4096 + arow * 64
                           + (((2 * h + acp) ^ aswz) << 4));
#pragma unroll
                for (int jj = 0; jj < 4; ++jj) {
                    int brow = jj * 16 + (lane & 15);
                    uint32_t b0, b1, b2, b3;
                    LDSM_X4(b0, b1, b2, b3,
                            sb + BTS_K + p * 4096 + brow * 64
                               + (((2 * h + acp) ^ ((brow >> 1) & 3)) << 4));
                    MMA_16816_F16(sa[2 * jj][0], sa[2 * jj][1],
                                  sa[2 * jj][2], sa[2 * jj][3],
                                  a0, a1, a2, a3, b0, b2);
                    MMA_16816_F16(sa[2 * jj + 1][0], sa[2 * jj + 1][1],
                                  sa[2 * jj + 1][2], sa[2 * jj + 1][3],
                                  a0, a1, a2, a3, b1, b3);
                }
            }
        }
        __syncthreads();      // all warps done reading K

        // issue K(kt+1) prefetch (hides under softmax + PV)
        if (kt + 1 < nkt) {
            const __half* kp = k2 + (size_t)(kt + 1) * 64 * 128;
#pragma unroll
            for (int p = 0; p < 4; ++p)
#pragma unroll
                for (int ps = 0; ps < 2; ++ps) {
                    int idx = tid + ps * 128;
                    int r = idx >> 2, ch = idx & 3;
                    CP_ASYNC16(sb + BTS_K + p * 4096 + swz64(r, ch),
                               kp + (size_t)r * 128 + p * 32 + ch * 8);
                }
        }
        CP_COMMIT();

        // ---- causal mask (diagonal tile only)
        if (kt == qt) {
            const int gr0 = qb + r0;
            const int gr1 = gr0 + 8;
            const int kb = kt * 64;
#pragma unroll
            for (int nb = 0; nb < 8; ++nb) {
                int c0 = kb + nb * 8 + 2 * (lane & 3);
                if (c0 > gr0)     sa[nb][0] = -INFINITY;
                if (c0 + 1 > gr0) sa[nb][1] = -INFINITY;
                if (c0 > gr1)     sa[nb][2] = -INFINITY;
                if (c0 + 1 > gr1) sa[nb][3] = -INFINITY;
            }
        }

        // ---- in-warp softmax (quad shuffles only)
        float rm0 = -INFINITY, rm1 = -INFINITY;
#pragma unroll
        for (int nb = 0; nb < 8; ++nb) {
            rm0 = fmaxf(rm0, fmaxf(sa[nb][0], sa[nb][1]));
            rm1 = fmaxf(rm1, fmaxf(sa[nb][2], sa[nb][3]));
        }
        rm0 = fmaxf(rm0, __shfl_xor_sync(0xffffffffu, rm0, 1));
        rm0 = fmaxf(rm0, __shfl_xor_sync(0xffffffffu, rm0, 2));
        rm1 = fmaxf(rm1, __shfl_xor_sync(0xffffffffu, rm1, 1));
        rm1 = fmaxf(rm1, __shfl_xor_sync(0xffffffffu, rm1, 2));

        float mn0 = fmaxf(m0, rm0);
        float mn1 = fmaxf(m1, rm1);
        float corr0 = __expf(m0 - mn0);
        float corr1 = __expf(m1 - mn1);
        m0 = mn0; m1 = mn1;
#pragma unroll
        for (int j = 0; j < 16; ++j) {
            oa[j][0] *= corr0; oa[j][1] *= corr0;
            oa[j][2] *= corr1; oa[j][3] *= corr1;
        }

        float rs0 = 0.0f, rs1 = 0.0f;
#pragma unroll
        for (int nb = 0; nb < 8; ++nb) {
            sa[nb][0] = __expf(sa[nb][0] - mn0);
            sa[nb][1] = __expf(sa[nb][1] - mn0);
            sa[nb][2] = __expf(sa[nb][2] - mn1);
            sa[nb][3] = __expf(sa[nb][3] - mn1);
            rs0 += sa[nb][0] + sa[nb][1];
            rs1 += sa[nb][2] + sa[nb][3];
        }
        rs0 += __shfl_xor_sync(0xffffffffu, rs0, 1);
        rs0 += __shfl_xor_sync(0xffffffffu, rs0, 2);
        rs1 += __shfl_xor_sync(0xffffffffu, rs1, 1);
        rs1 += __shfl_xor_sync(0xffffffffu, rs1, 2);
        l0 = l0 * corr0 + rs0;
        l1 = l1 * corr1 + rs1;

        // ---- pack P into mma A-fragments (C-frag layout == A-frag layout)
        uint32_t pa[4][4];
#pragma unroll
        for (int c = 0; c < 4; ++c) {
            pa[c][0] = h2u(__floats2half2_rn(sa[2 * c][0], sa[2 * c][1]));
            pa[c][1] = h2u(__floats2half2_rn(sa[2 * c][2], sa[2 * c][3]));
            pa[c][2] = h2u(__floats2half2_rn(sa[2 * c + 1][0], sa[2 * c + 1][1]));
            pa[c][3] = h2u(__floats2half2_rn(sa[2 * c + 1][2], sa[2 * c + 1][3]));
        }

        // V(kt) ready (K(kt+1) may still be in flight)
        CP_WAIT1();
        __syncthreads();

        // ---- PV: O[16 x 128] per warp; P from registers, V via ldsm.trans
#pragma unroll
        for (int c = 0; c < 4; ++c) {
            int vk = c * 16 + vkb;
#pragma unroll
            for (int gp = 0; gp < 8; ++gp) {
                uint32_t b0, b1, b2, b3;
                LDSM_X4T(b0, b1, b2, b3,
                         sb + BTS_V + vk * 256
                            + ((((2 * gp + (lane >> 4)) ^ (vk & 7))) << 4));
                MMA_16816_F16(oa[2 * gp][0], oa[2 * gp][1],
                              oa[2 * gp][2], oa[2 * gp][3],
                              pa[c][0], pa[c][1], pa[c][2], pa[c][3],
                              b0, b1);
                MMA_16816_F16(oa[2 * gp + 1][0], oa[2 * gp + 1][1],
                              oa[2 * gp + 1][2], oa[2 * gp + 1][3],
                              pa[c][0], pa[c][1], pa[c][2], pa[c][3],
                              b2, b3);
            }
        }
        __syncthreads();      // all warps done reading V

        // issue V(kt+1) prefetch (hides under next QK + softmax)
        if (kt + 1 < nkt) {
            const __half* va = vh + (size_t)(kt + 1) * 64 * PHD;
#pragma unroll
            for (int ps = 0; ps < 8; ++ps) {
                int idx = tid + ps * 128;
                int rr = idx >> 4, cc = idx & 15;
                CP_ASYNC16(sb + BTS_V + swzV(rr, cc), va + (size_t)rr * PHD + cc * 8);
            }
        }
        CP_COMMIT();
    }

    // ---- epilogue: plain fp16 into AXO [PM x 2048]
    const float inv0 = 1.0f / l0;
    const float inv1 = 1.0f / l1;
    const int b = bh >> 4, h = bh & 15;
    const size_t row0 = (size_t)b * PS + qb + r0;
    const size_t row1 = row0 + 8;
#pragma unroll
    for (int j = 0; j < 16; ++j) {
        int col = h * PHD + j * 8 + 2 * (lane & 3);
        __half2 h20 = __float22half2_rn(
            make_float2(oa[j][0] * inv0, oa[j][1] * inv0));
        __half2 h21 = __float22half2_rn(
            make_float2(oa[j][2] * inv1, oa[j][3] * inv1));
        *(__half2*)(AXO + row0 * KC + col) = h20;
        *(__half2*)(AXO + row1 * KC + col) = h21;
    }
}

// ---------------------------------------------------------------------------
// kernel_launch
// ---------------------------------------------------------------------------
extern "C" void kernel_launch(void* const* d_in, const int* in_sizes, int n_in,
                              void* d_out, int out_size)
{
    const float* x  = (const float*)d_in[0];
    const float* Wq = (const float*)d_in[1];
    const float* Wk = (const float*)d_in[2];
    const float* Wv = (const float*)d_in[3];
    const float* Wo = (const float*)d_in[4];
    float* out = (float*)d_out;

    __half *Axp, *Bqkvp, *Bop, *AxOp, *Qhp, *Khp, *Vhp;
    float2* tabp;
    cudaGetSymbolAddress((void**)&Axp,   g_Ax);
    cudaGetSymbolAddress((void**)&Bqkvp, g_Bqkv);
    cudaGetSymbolAddress((void**)&Bop,   g_Bo);
    cudaGetSymbolAddress((void**)&AxOp,  g_AxO);
    cudaGetSymbolAddress((void**)&Qhp,   g_Qh);
    cudaGetSymbolAddress((void**)&Khp,   g_Kh);
    cudaGetSymbolAddress((void**)&Vhp,   g_Vh);
    cudaGetSymbolAddress((void**)&tabp,  g_tab);

    cudaFuncSetAttribute((const void*)gemm_f16<0>,
                         cudaFuncAttributeMaxDynamicSharedMemorySize, HG_SMEM0);
    cudaFuncSetAttribute((const void*)gemm_f16<1>,
                         cudaFuncAttributeMaxDynamicSharedMemorySize, HG_SMEM1);
    cudaFuncSetAttribute((const void*)attn_tc,
                         cudaFuncAttributeMaxDynamicSharedMemorySize, ATT_SMEM);

    // RoPE tables + all fp16 converts
    rope_tables<<<512, 256>>>(tabp);
    convert_all<<<8192 + 4 * 4096, 256>>>(x, Wq, Wk, Wv, Wo, Axp, Bqkvp, Bop);

    // fused QKV projection (N = 6144) with RoPE epilogue
    gemm_f16<1><<<dim3(NQKV / 128, PM / 128), 256, HG_SMEM1>>>(
        Axp, Bqkvp, nullptr, Qhp, Khp, Vhp, tabp);

    // attention (64-query tiles, register-resident P, split wait groups)
    attn_tc<<<dim3(PS / 64, PB * PH), 128, ATT_SMEM>>>(Qhp, Khp, Vhp, AxOp);

    // Wo projection
    gemm_f16<0><<<dim3(PD / 128, PM / 128), 256, HG_SMEM0>>>(
        AxOp, Bop, out, nullptr, nullptr, nullptr, nullptr);
}

// round 17
// speedup vs baseline: 5.5554x; 1.0730x over previous
#include <cuda_runtime.h>
#include <cuda_fp16.h>
#include <math.h>
#include <stdint.h>

// ---------------------------------------------------------------------------
// Problem constants
// ---------------------------------------------------------------------------
#define PB 2
#define PS 2048
#define PD 2048
#define PH 16
#define PHD 128
#define PM (PB * PS)          // 4096 rows
#define KC 2048               // GEMM K (plain fp16)
#define NQKV (3 * PD)         // 6144: fused QKV output columns
#define ATT_SCALE 0.08838834764831845f

// ---------------------------------------------------------------------------
// Scratch (device globals; no allocation allowed)
// ---------------------------------------------------------------------------
__device__ __half g_Ax[(size_t)PM * KC];                 // x, fp16
__device__ __half g_Bqkv[(size_t)NQKV * KC];             // [Wq;Wk;Wv] fp16
__device__ __half g_Bo[(size_t)PD * KC];                 // Wo fp16
__device__ __half g_AxO[(size_t)PM * KC];                // attn out fp16
__device__ __half g_Qh[(size_t)PB * PH * PS * 128];      // qh*scale
__device__ __half g_Kh[(size_t)PB * PH * PS * 128];      // kh
__device__ __half g_Vh[(size_t)PB * PH * PS * PHD];
__device__ float2 g_tab[PS * 64];                        // {cos, sin}

// ---------------------------------------------------------------------------
// PTX helpers (sm_80-compatible: cp.async + ldmatrix + mma.sync)
// ---------------------------------------------------------------------------
__device__ __forceinline__ uint32_t smem_u32(const void* p) {
    uint32_t a;
    asm("{ .reg .u64 t; cvta.to.shared.u64 t, %1; cvt.u32.u64 %0, t; }"
        : "=r"(a) : "l"(p));
    return a;
}

#define CP_ASYNC16(smem, gptr) \
    asm volatile("cp.async.cg.shared.global [%0], [%1], 16;" \
                 :: "r"(smem), "l"(gptr) : "memory")
#define CP_COMMIT() asm volatile("cp.async.commit_group;" ::: "memory")
#define CP_WAIT2()  asm volatile("cp.async.wait_group 2;" ::: "memory")
#define CP_WAIT1()  asm volatile("cp.async.wait_group 1;" ::: "memory")
#define CP_WAIT0()  asm volatile("cp.async.wait_group 0;" ::: "memory")

#define LDSM_X4(r0, r1, r2, r3, addr) \
    asm volatile("ldmatrix.sync.aligned.m8n8.x4.shared.b16 {%0,%1,%2,%3}, [%4];" \
                 : "=r"(r0), "=r"(r1), "=r"(r2), "=r"(r3) : "r"(addr))
#define LDSM_X4T(r0, r1, r2, r3, addr) \
    asm volatile("ldmatrix.sync.aligned.m8n8.x4.trans.shared.b16 {%0,%1,%2,%3}, [%4];" \
                 : "=r"(r0), "=r"(r1), "=r"(r2), "=r"(r3) : "r"(addr))

#define MMA_16816_F16(c0, c1, c2, c3, a0, a1, a2, a3, b0, b1) \
    asm volatile("mma.sync.aligned.m16n8k16.row.col.f32.f16.f16.f32 " \
                 "{%0,%1,%2,%3}, {%4,%5,%6,%7}, {%8,%9}, {%0,%1,%2,%3};" \
                 : "+f"(c0), "+f"(c1), "+f"(c2), "+f"(c3) \
                 : "r"(a0), "r"(a1), "r"(a2), "r"(a3), "r"(b0), "r"(b1))

// swizzles
__device__ __forceinline__ uint32_t swz64(int r, int ch) {   // 64B rows, 4x16B chunks
    return (uint32_t)(r * 64 + (((ch) ^ ((r >> 1) & 3)) << 4));
}
__device__ __forceinline__ uint32_t swzV(int r, int ch) {    // 256B rows, 16x16B chunks
    return (uint32_t)(r * 256 + (((ch) ^ (r & 7)) << 4));
}

__device__ __forceinline__ uint32_t h2u(__half2 h) {
    uint32_t u;
    *(__half2*)&u = h;
    return u;
}

// ---------------------------------------------------------------------------
// RoPE tables: invf = exp(-j/64 * ln(10000)) (fp64); angle fp32-rounded chain.
// ---------------------------------------------------------------------------
__global__ __launch_bounds__(256)
void rope_tables(float2* __restrict__ tab)
{
    int idx = blockIdx.x * blockDim.x + threadIdx.x;   // 131072
    int s = idx >> 6;
    int j = idx & 63;
    double invf_d = exp(-(double)j * (9.210340371976184 / 64.0));
    float ang = (float)s * (float)invf_d;
    double cs, sn;
    sincos((double)ang, &sn, &cs);
    tab[idx] = make_float2((float)cs, (float)sn);
}

// ---------------------------------------------------------------------------
// Merged converts: fp32 -> fp16 (plain cast).
// ---------------------------------------------------------------------------
__global__ __launch_bounds__(256)
void convert_all(const float* __restrict__ x,
                 const float* __restrict__ Wq, const float* __restrict__ Wk,
                 const float* __restrict__ Wv, const float* __restrict__ Wo,
                 __half* __restrict__ Ax, __half* __restrict__ Bqkv,
                 __half* __restrict__ Bo)
{
    int bid = blockIdx.x;
    const float* src;
    __half* dst;
    int off;
    if (bid < 8192) {
        src = x; dst = Ax; off = bid;
    } else {
        int seg = (bid - 8192) >> 12;
        off = bid - 8192 - seg * 4096;
        if (seg == 0)      { src = Wq; dst = Bqkv; }
        else if (seg == 1) { src = Wk; dst = Bqkv + (size_t)2048 * KC; }
        else if (seg == 2) { src = Wv; dst = Bqkv + (size_t)4096 * KC; }
        else               { src = Wo; dst = Bo; }
    }
    size_t i = (size_t)off * 1024 + threadIdx.x * 4;
    float4 v = *(const float4*)(src + i);
    __half2 a = __floats2half2_rn(v.x, v.y);
    __half2 b = __floats2half2_rn(v.z, v.w);
    *(__half2*)(dst + i)     = a;
    *(__half2*)(dst + i + 2) = b;
}

// ---------------------------------------------------------------------------
// fp16 HMMA GEMM, K=2048. 4 warps, warp tile 64x64 (halved smem bytes/mma).
//  MODE 0: Wo projection — plain fp32 C stores.
//  MODE 1: fused QKV (N=6144): region 0 Q (RoPE+scale), 1 K (RoPE),
//          2 V (fp16 head-gather).
// ---------------------------------------------------------------------------
#define HG_BK 32
#define HG_STG 4
#define HG_STAGE_BYTES 16384
#define HG_SMEM0 (HG_STG * HG_STAGE_BYTES)      // 65536 (MODE 0)
#define HG_PITCH 136
#define HG_SMEM1 (128 * HG_PITCH * 4)           // 69632 (MODE 1)
#define HG_KT (KC / HG_BK)                      // 64

template<int MODE>
__global__ __launch_bounds__(128, 2)
void gemm_f16(const __half* __restrict__ A3, const __half* __restrict__ B3,
              float* __restrict__ C,
              __half* __restrict__ Qho, __half* __restrict__ Kho,
              __half* __restrict__ Vho, const float2* __restrict__ tab)
{
    extern __shared__ __align__(1024) char smem[];
    const uint32_t sbase = smem_u32(smem);

    const int tid  = threadIdx.x;
    const int lane = tid & 31;
    const int wid  = tid >> 5;
    const int wm   = wid & 1;          // 64-row half
    const int wn   = wid >> 1;         // 64-col half
    const int bm   = blockIdx.y * 128;
    const int bn   = blockIdx.x * 128;

    const __half* Ag = A3 + (size_t)bm * KC;
    const __half* Bg = B3 + (size_t)bn * KC;

    // loaders: 8 x 16B chunks per thread per stage (4 A + 4 B)
    uint32_t lsw[4];
    const __half* gA[4];
    const __half* gB[4];
#pragma unroll
    for (int p = 0; p < 4; ++p) {
        int idx = tid + p * 128;
        int r = idx >> 2, ch = idx & 3;
        lsw[p] = swz64(r, ch);
        gA[p] = Ag + (size_t)r * KC + ch * 8;
        gB[p] = Bg + (size_t)r * KC + ch * 8;
    }

    uint32_t a_row_off[4];
    int a_swz[4];
#pragma unroll
    for (int mi = 0; mi < 4; ++mi) {
        int r = wm * 64 + mi * 16 + (lane & 15);
        a_row_off[mi] = (uint32_t)(r * 64);
        a_swz[mi] = (r >> 1) & 3;
    }
    const int a_cpart = lane >> 4;
    // B x4 pairs: njp 0..3, row = wn*64 + njp*16 + ((lane>>4)&1)*8 + (lane&7)
    uint32_t b_row_off[4];
    int b_swz[4];
#pragma unroll
    for (int njp = 0; njp < 4; ++njp) {
        int r = wn * 64 + njp * 16 + ((lane >> 4) & 1) * 8 + (lane & 7);
        b_row_off[njp] = (uint32_t)(r * 64);
        b_swz[njp] = (r >> 1) & 3;
    }
    const int b_cpart = (lane >> 3) & 1;

    float acc[4][8][4];
#pragma unroll
    for (int mi = 0; mi < 4; ++mi)
#pragma unroll
        for (int nj = 0; nj < 8; ++nj)
#pragma unroll
            for (int e = 0; e < 4; ++e) acc[mi][nj][e] = 0.0f;

#pragma unroll
    for (int s = 0; s < HG_STG - 1; ++s) {
        uint32_t sA = sbase + s * HG_STAGE_BYTES;
        uint32_t sB = sA + 8192;
        int k0 = s * HG_BK;
#pragma unroll
        for (int p = 0; p < 4; ++p) {
            CP_ASYNC16(sA + lsw[p], gA[p] + k0);
            CP_ASYNC16(sB + lsw[p], gB[p] + k0);
        }
        CP_COMMIT();
    }

    for (int kt = 0; kt < HG_KT; ++kt) {
        CP_WAIT2();
        __syncthreads();

        int nk = kt + HG_STG - 1;
        if (nk < HG_KT) {
            uint32_t sA = sbase + (nk & 3) * HG_STAGE_BYTES;
            uint32_t sB = sA + 8192;
            int k0 = nk * HG_BK;
#pragma unroll
            for (int p = 0; p < 4; ++p) {
                CP_ASYNC16(sA + lsw[p], gA[p] + k0);
                CP_ASYNC16(sB + lsw[p], gB[p] + k0);
            }
        }
        CP_COMMIT();

        uint32_t sA = sbase + (kt & 3) * HG_STAGE_BYTES;
        uint32_t sB = sA + 8192;
#pragma unroll
        for (int h = 0; h < 2; ++h) {
            uint32_t a0[4], a1[4], a2[4], a3[4];
#pragma unroll
            for (int mi = 0; mi < 4; ++mi) {
                uint32_t addr = sA + a_row_off[mi]
                              + (uint32_t)(((2 * h + a_cpart) ^ a_swz[mi]) << 4);
                LDSM_X4(a0[mi], a1[mi], a2[mi], a3[mi], addr);
            }
            uint32_t b0[8], b1[8];
#pragma unroll
            for (int njp = 0; njp < 4; ++njp) {
                uint32_t addr = sB + b_row_off[njp]
                              + (uint32_t)(((2 * h + b_cpart) ^ b_swz[njp]) << 4);
                LDSM_X4(b0[2 * njp], b1[2 * njp],
                        b0[2 * njp + 1], b1[2 * njp + 1], addr);
            }
#pragma unroll
            for (int mi = 0; mi < 4; ++mi)
#pragma unroll
                for (int nj = 0; nj < 8; ++nj)
                    MMA_16816_F16(acc[mi][nj][0], acc[mi][nj][1],
                                  acc[mi][nj][2], acc[mi][nj][3],
                                  a0[mi], a1[mi], a2[mi], a3[mi],
                                  b0[nj], b1[nj]);
        }
        __syncthreads();
    }

    const int erow = (lane >> 2);
    const int ecol = (lane & 3) * 2;
    const int region  = (MODE == 1) ? (bn >> 11) : 0;
    const int colbase = bn - region * 2048;

    if (MODE == 0) {
#pragma unroll
        for (int mi = 0; mi < 4; ++mi)
#pragma unroll
            for (int nj = 0; nj < 8; ++nj) {
                int row = bm + wm * 64 + mi * 16 + erow;
                int col = colbase + wn * 64 + nj * 8 + ecol;
                *(float2*)(C + (size_t)row * PD + col) =
                    make_float2(acc[mi][nj][0], acc[mi][nj][1]);
                *(float2*)(C + (size_t)(row + 8) * PD + col) =
                    make_float2(acc[mi][nj][2], acc[mi][nj][3]);
            }
    } else if (region == 2) {
#pragma unroll
        for (int mi = 0; mi < 4; ++mi)
#pragma unroll
            for (int nj = 0; nj < 8; ++nj) {
                int row = bm + wm * 64 + mi * 16 + erow;
                int col = colbase + wn * 64 + nj * 8 + ecol;
                int b = row >> 11, s = row & 2047;
                int h = col >> 7, hd = col & 127;
                size_t dst = ((size_t)(b * PH + h) * PS + s) * PHD + hd;
                *(__half2*)(Vho + dst) = __float22half2_rn(
                    make_float2(acc[mi][nj][0], acc[mi][nj][1]));
                *(__half2*)(Vho + dst + 8 * PHD) = __float22half2_rn(
                    make_float2(acc[mi][nj][2], acc[mi][nj][3]));
            }
    } else {
        // Q/K: smem stage + RoPE + fp16 emit (both 128-wide; Q scaled)
        float* tile = (float*)smem;
#pragma unroll
        for (int mi = 0; mi < 4; ++mi)
#pragma unroll
            for (int nj = 0; nj < 8; ++nj) {
                int r = wm * 64 + mi * 16 + erow;
                int c = wn * 64 + nj * 8 + ecol;
                *(float2*)(tile + r * HG_PITCH + c) =
                    make_float2(acc[mi][nj][0], acc[mi][nj][1]);
                *(float2*)(tile + (r + 8) * HG_PITCH + c) =
                    make_float2(acc[mi][nj][2], acc[mi][nj][3]);
            }
        __syncthreads();

        const int hh = colbase >> 7;
        const int b  = bm >> 11;
        const int s0 = bm & 2047;
        const int rg = tid >> 6;           // 2 groups x 64 rows
        const int ii = tid & 63;
        const float sc = (region == 0) ? ATT_SCALE : 1.0f;
        __half* dst = (region == 0 ? Qho : Kho)
                    + (size_t)(b * PH + hh) * PS * 128;
#pragma unroll 4
        for (int rr = 0; rr < 64; ++rr) {
            int r = rg * 64 + rr;
            float x0 = tile[r * HG_PITCH + ii];
            float x1 = tile[r * HG_PITCH + 64 + ii];
            int s = s0 + r;
            float2 cs = tab[s * 64 + ii];
            __half* o = dst + (size_t)s * 128;
            o[ii]      = __float2half((x0 * cs.x - x1 * cs.y) * sc);
            o[64 + ii] = __float2half((x1 * cs.x + x0 * cs.y) * sc);
        }
    }
}

// ---------------------------------------------------------------------------
// Tensor-core causal flash attention (proven round-16 body): 64q x 64k tiles,
// 4 warps, in-warp softmax, register-resident P, split cp.async wait groups.
// ---------------------------------------------------------------------------
#define BTS_Q  0          // 4 panels x 4096 = 16384
#define BTS_K  16384      // 16384
#define BTS_V  32768      // 16384
#define ATT_SMEM 49152

__global__ __launch_bounds__(128, 4)
void attn_tc(const __half* __restrict__ Qh,
             const __half* __restrict__ Kh,
             const __half* __restrict__ Vh,
             __half* __restrict__ AXO)
{
    extern __shared__ __align__(1024) char sm[];
    const uint32_t sb = smem_u32(sm);

    const int tid  = threadIdx.x;
    const int lane = tid & 31;
    const int w    = tid >> 5;
    const int qt   = 31 - (int)blockIdx.x;
    const int bh   = blockIdx.y;
    const int qb   = qt * 64;
    const int nkt  = qt + 1;

    const __half* qh = Qh + ((size_t)bh * PS + qb) * 128;
    const __half* k2 = Kh + (size_t)bh * PS * 128;
    const __half* vh = Vh + (size_t)bh * PS * PHD;

    {
#pragma unroll
        for (int p = 0; p < 4; ++p)
#pragma unroll
            for (int ps = 0; ps < 2; ++ps) {
                int idx = tid + ps * 128;
                int r = idx >> 2, ch = idx & 3;
                uint32_t sw = swz64(r, ch);
                CP_ASYNC16(sb + BTS_Q + p * 4096 + sw,
                           qh + (size_t)r * 128 + p * 32 + ch * 8);
                CP_ASYNC16(sb + BTS_K + p * 4096 + sw,
                           k2 + (size_t)r * 128 + p * 32 + ch * 8);
            }
        CP_COMMIT();
#pragma unroll
        for (int ps = 0; ps < 8; ++ps) {
            int idx = tid + ps * 128;
            int rr = idx >> 4, cc = idx & 15;
            CP_ASYNC16(sb + BTS_V + swzV(rr, cc), vh + (size_t)rr * PHD + cc * 8);
        }
        CP_COMMIT();
    }

    float m0 = -INFINITY, m1 = -INFINITY, l0 = 0.0f, l1 = 0.0f;
    float oa[16][4];
#pragma unroll
    for (int j = 0; j < 16; ++j)
#pragma unroll
        for (int e = 0; e < 4; ++e) oa[j][e] = 0.0f;

    const int arow = w * 16 + (lane & 15);
    const int aswz = (arow >> 1) & 3;
    const int acp  = lane >> 4;
    const int r0   = w * 16 + (lane >> 2);
    const int vkb  = (lane & 7) + 8 * ((lane >> 3) & 1);

    for (int kt = 0; kt < nkt; ++kt) {
        CP_WAIT1();
        __syncthreads();

        float sa[8][4];
#pragma unroll
        for (int j = 0; j < 8; ++j)
#pragma unroll
            for (int e = 0; e < 4; ++e) sa[j][e] = 0.0f;

#pragma unroll
        for (int p = 0; p < 4; ++p) {
#pragma unroll
            for (int h = 0; h < 2; ++h) {
                uint32_t a0, a1, a2, a3;
                LDSM_X4(a0, a1, a2, a3,
                        sb + BTS_Q + p * 4096 + arow * 64
                           + (((2 * h + acp) ^ aswz) << 4));
#pragma unroll
                for (int jj = 0; jj < 4; ++jj) {
                    int brow = jj * 16 + (lane & 15);
                    uint32_t b0, b1, b2, b3;
                    LDSM_X4(b0, b1, b2, b3,
                            sb + BTS_K + p * 4096 + brow * 64
                               + (((2 * h + acp) ^ ((brow >> 1) & 3)) << 4));
                    MMA_16816_F16(sa[2 * jj][0], sa[2 * jj][1],
                                  sa[2 * jj][2], sa[2 * jj][3],
                                  a0, a1, a2, a3, b0, b2);
                    MMA_16816_F16(sa[2 * jj + 1][0], sa[2 * jj + 1][1],
                                  sa[2 * jj + 1][2], sa[2 * jj + 1][3],
                                  a0, a1, a2, a3, b1, b3);
                }
            }
        }
        __syncthreads();

        if (kt + 1 < nkt) {
            const __half* kp = k2 + (size_t)(kt + 1) * 64 * 128;
#pragma unroll
            for (int p = 0; p < 4; ++p)
#pragma unroll
                for (int ps = 0; ps < 2; ++ps) {
                    int idx = tid + ps * 128;
                    int r = idx >> 2, ch = idx & 3;
                    CP_ASYNC16(sb + BTS_K + p * 4096 + swz64(r, ch),
                               kp + (size_t)r * 128 + p * 32 + ch * 8);
                }
        }
        CP_COMMIT();

        if (kt == qt) {
            const int gr0 = qb + r0;
            const int gr1 = gr0 + 8;
            const int kb = kt * 64;
#pragma unroll
            for (int nb = 0; nb < 8; ++nb) {
                int c0 = kb + nb * 8 + 2 * (lane & 3);
                if (c0 > gr0)     sa[nb][0] = -INFINITY;
                if (c0 + 1 > gr0) sa[nb][1] = -INFINITY;
                if (c0 > gr1)     sa[nb][2] = -INFINITY;
                if (c0 + 1 > gr1) sa[nb][3] = -INFINITY;
            }
        }

        float rm0 = -INFINITY, rm1 = -INFINITY;
#pragma unroll
        for (int nb = 0; nb < 8; ++nb) {
            rm0 = fmaxf(rm0, fmaxf(sa[nb][0], sa[nb][1]));
            rm1 = fmaxf(rm1, fmaxf(sa[nb][2], sa[nb][3]));
        }
        rm0 = fmaxf(rm0, __shfl_xor_sync(0xffffffffu, rm0, 1));
        rm0 = fmaxf(rm0, __shfl_xor_sync(0xffffffffu, rm0, 2));
        rm1 = fmaxf(rm1, __shfl_xor_sync(0xffffffffu, rm1, 1));
        rm1 = fmaxf(rm1, __shfl_xor_sync(0xffffffffu, rm1, 2));

        float mn0 = fmaxf(m0, rm0);
        float mn1 = fmaxf(m1, rm1);
        float corr0 = __expf(m0 - mn0);
        float corr1 = __expf(m1 - mn1);
        m0 = mn0; m1 = mn1;
#pragma unroll
        for (int j = 0; j < 16; ++j) {
            oa[j][0] *= corr0; oa[j][1] *= corr0;
            oa[j][2] *= corr1; oa[j][3] *= corr1;
        }

        float rs0 = 0.0f, rs1 = 0.0f;
#pragma unroll
        for (int nb = 0; nb < 8; ++nb) {
            sa[nb][0] = __expf(sa[nb][0] - mn0);
            sa[nb][1] = __expf(sa[nb][1] - mn0);
            sa[nb][2] = __expf(sa[nb][2] - mn1);
            sa[nb][3] = __expf(sa[nb][3] - mn1);
            rs0 += sa[nb][0] + sa[nb][1];
            rs1 += sa[nb][2] + sa[nb][3];
        }
        rs0 += __shfl_xor_sync(0xffffffffu, rs0, 1);
        rs0 += __shfl_xor_sync(0xffffffffu, rs0, 2);
        rs1 += __shfl_xor_sync(0xffffffffu, rs1, 1);
        rs1 += __shfl_xor_sync(0xffffffffu, rs1, 2);
        l0 = l0 * corr0 + rs0;
        l1 = l1 * corr1 + rs1;

        uint32_t pa[4][4];
#pragma unroll
        for (int c = 0; c < 4; ++c) {
            pa[c][0] = h2u(__floats2half2_rn(sa[2 * c][0], sa[2 * c][1]));
            pa[c][1] = h2u(__floats2half2_rn(sa[2 * c][2], sa[2 * c][3]));
            pa[c][2] = h2u(__floats2half2_rn(sa[2 * c + 1][0], sa[2 * c + 1][1]));
            pa[c][3] = h2u(__floats2half2_rn(sa[2 * c + 1][2], sa[2 * c + 1][3]));
        }

        CP_WAIT1();
        __syncthreads();

#pragma unroll
        for (int c = 0; c < 4; ++c) {
            int vk = c * 16 + vkb;
#pragma unroll
            for (int gp = 0; gp < 8; ++gp) {
                uint32_t b0, b1, b2, b3;
                LDSM_X4T(b0, b1, b2, b3,
                         sb + BTS_V + vk * 256
                            + ((((2 * gp + (lane >> 4)) ^ (vk & 7))) << 4));
                MMA_16816_F16(oa[2 * gp][0], oa[2 * gp][1],
                              oa[2 * gp][2], oa[2 * gp][3],
                              pa[c][0], pa[c][1], pa[c][2], pa[c][3],
                              b0, b1);
                MMA_16816_F16(oa[2 * gp + 1][0], oa[2 * gp + 1][1],
                              oa[2 * gp + 1][2], oa[2 * gp + 1][3],
                              pa[c][0], pa[c][1], pa[c][2], pa[c][3],
                              b2, b3);
            }
        }
        __syncthreads();

        if (kt + 1 < nkt) {
            const __half* va = vh + (size_t)(kt + 1) * 64 * PHD;
#pragma unroll
            for (int ps = 0; ps < 8; ++ps) {
                int idx = tid + ps * 128;
                int rr = idx >> 4, cc = idx & 15;
                CP_ASYNC16(sb + BTS_V + swzV(rr, cc), va + (size_t)rr * PHD + cc * 8);
            }
        }
        CP_COMMIT();
    }

    const float inv0 = 1.0f / l0;
    const float inv1 = 1.0f / l1;
    const int b = bh >> 4, h = bh & 15;
    const size_t row0 = (size_t)b * PS + qb + r0;
    const size_t row1 = row0 + 8;
#pragma unroll
    for (int j = 0; j < 16; ++j) {
        int col = h * PHD + j * 8 + 2 * (lane & 3);
        __half2 h20 = __float22half2_rn(
            make_float2(oa[j][0] * inv0, oa[j][1] * inv0));
        __half2 h21 = __float22half2_rn(
            make_float2(oa[j][2] * inv1, oa[j][3] * inv1));
        *(__half2*)(AXO + row0 * KC + col) = h20;
        *(__half2*)(AXO + row1 * KC + col) = h21;
    }
}

// ---------------------------------------------------------------------------
// kernel_launch
// ---------------------------------------------------------------------------
extern "C" void kernel_launch(void* const* d_in, const int* in_sizes, int n_in,
                              void* d_out, int out_size)
{
    const float* x  = (const float*)d_in[0];
    const float* Wq = (const float*)d_in[1];
    const float* Wk = (const float*)d_in[2];
    const float* Wv = (const float*)d_in[3];
    const float* Wo = (const float*)d_in[4];
    float* out = (float*)d_out;

    __half *Axp, *Bqkvp, *Bop, *AxOp, *Qhp, *Khp, *Vhp;
    float2* tabp;
    cudaGetSymbolAddress((void**)&Axp,   g_Ax);
    cudaGetSymbolAddress((void**)&Bqkvp, g_Bqkv);
    cudaGetSymbolAddress((void**)&Bop,   g_Bo);
    cudaGetSymbolAddress((void**)&AxOp,  g_AxO);
    cudaGetSymbolAddress((void**)&Qhp,   g_Qh);
    cudaGetSymbolAddress((void**)&Khp,   g_Kh);
    cudaGetSymbolAddress((void**)&Vhp,   g_Vh);
    cudaGetSymbolAddress((void**)&tabp,  g_tab);

    cudaFuncSetAttribute((const void*)gemm_f16<0>,
                         cudaFuncAttributeMaxDynamicSharedMemorySize, HG_SMEM0);
    cudaFuncSetAttribute((const void*)gemm_f16<1>,
                         cudaFuncAttributeMaxDynamicSharedMemorySize, HG_SMEM1);
    cudaFuncSetAttribute((const void*)attn_tc,
                         cudaFuncAttributeMaxDynamicSharedMemorySize, ATT_SMEM);

    // RoPE tables + all fp16 converts
    rope_tables<<<512, 256>>>(tabp);
    convert_all<<<8192 + 4 * 4096, 256>>>(x, Wq, Wk, Wv, Wo, Axp, Bqkvp, Bop);

    // fused QKV projection (N = 6144) with RoPE epilogue
    gemm_f16<1><<<dim3(NQKV / 128, PM / 128), 128, HG_SMEM1>>>(
        Axp, Bqkvp, nullptr, Qhp, Khp, Vhp, tabp);

    // attention (64-query tiles, register-resident P, split wait groups)
    attn_tc<<<dim3(PS / 64, PB * PH), 128, ATT_SMEM>>>(Qhp, Khp, Vhp, AxOp);

    // Wo projection
    gemm_f16<0><<<dim3(PD / 128, PM / 128), 128, HG_SMEM0>>>(
        AxOp, Bop, out, nullptr, nullptr, nullptr, nullptr);
}